// round 1
// baseline (speedup 1.0000x reference)
#include <cuda_runtime.h>
#include <math.h>

#define B_   4
#define S_   1024
#define E_   1024
#define H_   16
#define HD_  64
#define NBH  64          /* B*H */
#define SLAB 16
#define SLDS 17

/* ---------------- scratch (device globals: no allocations allowed) -------- */
__device__ float  g_Q[(size_t)B_ * S_ * E_];
__device__ float  g_K[(size_t)B_ * S_ * E_];
__device__ float  g_V[(size_t)B_ * S_ * E_];
__device__ float  g_ctx[(size_t)B_ * S_ * E_];
__device__ float  g_scores[(size_t)NBH * S_ * S_];   /* 256 MB, reused for attn */
__device__ float2 g_freq[(size_t)NBH * S_ * S_];     /* 512 MB */

/* =================== GEMM: C = A * B^T + bias  (fp32 SIMT) ================ */
/* A: M x K row-major, B: N x K row-major. M%128==0, N%128==0, K%16==0.      */
__global__ void __launch_bounds__(256) gemm_nt_bias(
    const float* __restrict__ A, const float* __restrict__ Bm,
    const float* __restrict__ bias, float* __restrict__ C,
    int M, int N, int K)
{
    __shared__ float As[16][128];
    __shared__ float Bs[16][128];
    int tid = threadIdx.x;
    int tx = tid & 15, ty = tid >> 4;
    const float* Ab = A  + (size_t)blockIdx.y * 128 * K;
    const float* Bb = Bm + (size_t)blockIdx.x * 128 * K;
    int lr = tid >> 2;
    int lc = (tid & 3) << 2;
    float acc[8][8] = {};
    for (int k0 = 0; k0 < K; k0 += 16) {
#pragma unroll
        for (int i = 0; i < 2; i++) {
            int m = lr + i * 64;
            float4 va = *(const float4*)(Ab + (size_t)m * K + k0 + lc);
            As[lc + 0][m] = va.x; As[lc + 1][m] = va.y;
            As[lc + 2][m] = va.z; As[lc + 3][m] = va.w;
            float4 vb = *(const float4*)(Bb + (size_t)m * K + k0 + lc);
            Bs[lc + 0][m] = vb.x; Bs[lc + 1][m] = vb.y;
            Bs[lc + 2][m] = vb.z; Bs[lc + 3][m] = vb.w;
        }
        __syncthreads();
#pragma unroll
        for (int k = 0; k < 16; k++) {
            float a[8], b[8];
#pragma unroll
            for (int i = 0; i < 8; i++) a[i] = As[k][ty * 8 + i];
#pragma unroll
            for (int j = 0; j < 8; j++) b[j] = Bs[k][tx * 8 + j];
#pragma unroll
            for (int i = 0; i < 8; i++)
#pragma unroll
                for (int j = 0; j < 8; j++) acc[i][j] += a[i] * b[j];
        }
        __syncthreads();
    }
    int row0 = blockIdx.y * 128 + ty * 8;
    int col0 = blockIdx.x * 128 + tx * 8;
#pragma unroll
    for (int i = 0; i < 8; i++)
#pragma unroll
        for (int j = 0; j < 8; j++)
            C[(size_t)(row0 + i) * N + col0 + j] = acc[i][j] + bias[col0 + j];
}

/* =========== scores[z,q,k] = scale * sum_d Q[b,q,h,d] K[b,k,h,d] ========== */
__global__ void __launch_bounds__(256) gemm_scores(
    const float* __restrict__ Q, const float* __restrict__ Kmat,
    float* __restrict__ Sc)
{
    __shared__ float As[16][128];
    __shared__ float Bs[16][128];
    int z = blockIdx.z;
    int b = z >> 4, h = z & 15;
    size_t hoff = (size_t)b * S_ * E_ + (size_t)h * HD_;
    int tid = threadIdx.x;
    int tx = tid & 15, ty = tid >> 4;
    const float* Ab = Q    + hoff + (size_t)blockIdx.y * 128 * E_;
    const float* Bb = Kmat + hoff + (size_t)blockIdx.x * 128 * E_;
    int lr = tid >> 2;
    int lc = (tid & 3) << 2;
    float acc[8][8] = {};
    for (int k0 = 0; k0 < HD_; k0 += 16) {
#pragma unroll
        for (int i = 0; i < 2; i++) {
            int m = lr + i * 64;
            float4 va = *(const float4*)(Ab + (size_t)m * E_ + k0 + lc);
            As[lc + 0][m] = va.x; As[lc + 1][m] = va.y;
            As[lc + 2][m] = va.z; As[lc + 3][m] = va.w;
            float4 vb = *(const float4*)(Bb + (size_t)m * E_ + k0 + lc);
            Bs[lc + 0][m] = vb.x; Bs[lc + 1][m] = vb.y;
            Bs[lc + 2][m] = vb.z; Bs[lc + 3][m] = vb.w;
        }
        __syncthreads();
#pragma unroll
        for (int k = 0; k < 16; k++) {
            float a[8], b2[8];
#pragma unroll
            for (int i = 0; i < 8; i++) a[i] = As[k][ty * 8 + i];
#pragma unroll
            for (int j = 0; j < 8; j++) b2[j] = Bs[k][tx * 8 + j];
#pragma unroll
            for (int i = 0; i < 8; i++)
#pragma unroll
                for (int j = 0; j < 8; j++) acc[i][j] += a[i] * b2[j];
        }
        __syncthreads();
    }
    float* Cb = Sc + (size_t)z * S_ * S_;
    int row0 = blockIdx.y * 128 + ty * 8;
    int col0 = blockIdx.x * 128 + tx * 8;
    const float scale = 0.125f; /* 1/sqrt(64) */
#pragma unroll
    for (int i = 0; i < 8; i++)
#pragma unroll
        for (int j = 0; j < 8; j++)
            Cb[(size_t)(row0 + i) * S_ + col0 + j] = acc[i][j] * scale;
}

/* ============ ctx[b,q,h,d] = sum_k attn[z,q,k] * V[b,k,h,d] =============== */
__global__ void __launch_bounds__(256) gemm_av(
    const float* __restrict__ attn, const float* __restrict__ V,
    float* __restrict__ ctx)
{
    __shared__ float As[16][128];
    __shared__ float Bs[16][68];
    int z = blockIdx.z;
    int b = z >> 4, h = z & 15;
    int tid = threadIdx.x;
    int tx = tid & 15, ty = tid >> 4;   /* cols: tx*4 (64), rows: ty*8 (128) */
    const float* Ab    = attn + (size_t)z * S_ * S_ + (size_t)blockIdx.y * 128 * S_;
    const float* Bbase = V + (size_t)b * S_ * E_ + (size_t)h * HD_;
    int lrA = tid >> 2, lcA = (tid & 3) << 2;
    int krB = tid >> 4, ncB = (tid & 15) << 2;
    float acc[8][4] = {};
    for (int k0 = 0; k0 < S_; k0 += 16) {
#pragma unroll
        for (int i = 0; i < 2; i++) {
            int m = lrA + i * 64;
            float4 va = *(const float4*)(Ab + (size_t)m * S_ + k0 + lcA);
            As[lcA + 0][m] = va.x; As[lcA + 1][m] = va.y;
            As[lcA + 2][m] = va.z; As[lcA + 3][m] = va.w;
        }
        float4 vb = *(const float4*)(Bbase + (size_t)(k0 + krB) * E_ + ncB);
        Bs[krB][ncB + 0] = vb.x; Bs[krB][ncB + 1] = vb.y;
        Bs[krB][ncB + 2] = vb.z; Bs[krB][ncB + 3] = vb.w;
        __syncthreads();
#pragma unroll
        for (int k = 0; k < 16; k++) {
            float a[8], b2[4];
#pragma unroll
            for (int i = 0; i < 8; i++) a[i] = As[k][ty * 8 + i];
#pragma unroll
            for (int j = 0; j < 4; j++) b2[j] = Bs[k][tx * 4 + j];
#pragma unroll
            for (int i = 0; i < 8; i++)
#pragma unroll
                for (int j = 0; j < 4; j++) acc[i][j] += a[i] * b2[j];
        }
        __syncthreads();
    }
    int q0 = blockIdx.y * 128 + ty * 8;
#pragma unroll
    for (int i = 0; i < 8; i++)
#pragma unroll
        for (int j = 0; j < 4; j++)
            ctx[(size_t)(b * S_ + q0 + i) * E_ + h * HD_ + tx * 4 + j] = acc[i][j];
}

/* ======================== FFT helpers ===================================== */
__device__ __forceinline__ int swz(int i) { return i ^ (i >> 5); }

/* rowFFT forward: real scores row -> complex spectrum row (natural order)   */
__global__ void __launch_bounds__(512) fft_rows_fwd(
    const float* __restrict__ in, float2* __restrict__ out)
{
    __shared__ float2 s[1024];
    size_t rb = (size_t)blockIdx.x * 1024;
    int t = threadIdx.x;
    for (int i = t; i < 1024; i += 512) {
        int r = __brev(i) >> 22;
        s[swz(r)] = make_float2(in[rb + i], 0.f);
    }
    __syncthreads();
    for (int st = 1; st <= 10; st++) {
        int half = 1 << (st - 1);
        int j = t & (half - 1);
        int base = (t >> (st - 1)) << st;
        float ang = -6.2831853071795864f * (float)j / (float)(half << 1);
        float sn, cs; sincosf(ang, &sn, &cs);
        int i0 = swz(base + j), i1 = swz(base + j + half);
        float2 a = s[i0], bv = s[i1];
        float2 tb = make_float2(bv.x * cs - bv.y * sn, bv.x * sn + bv.y * cs);
        s[i0] = make_float2(a.x + tb.x, a.y + tb.y);
        s[i1] = make_float2(a.x - tb.x, a.y - tb.y);
        __syncthreads();
    }
    for (int i = t; i < 1024; i += 512) out[rb + i] = s[swz(i)];
}

/* column FFT (q axis) + spectral filter + column IFFT, on a 16-col slab.    */
__global__ void __launch_bounds__(512) fft_cols_filter(
    float2* __restrict__ data, const float* __restrict__ alpha_p)
{
    extern __shared__ float2 cs[];     /* [1024][SLDS] */
    int z = blockIdx.y;
    int k0 = blockIdx.x * SLAB;
    float2* base = data + (size_t)z * S_ * S_ + k0;
    int t = threadIdx.x;

    for (int idx = t; idx < 1024 * SLAB; idx += 512) {
        int q = idx >> 4, c = idx & 15;
        int r = __brev(q) >> 22;
        cs[r * SLDS + c] = base[(size_t)q * 1024 + c];
    }
    __syncthreads();
    /* forward DIT along q */
    for (int st = 1; st <= 10; st++) {
        int half = 1 << (st - 1);
        int j = t & (half - 1);
        int bb = (t >> (st - 1)) << st;
        float ang = -6.2831853071795864f * (float)j / (float)(half << 1);
        float sn, csn; sincosf(ang, &sn, &csn);
        int i0 = (bb + j) * SLDS, i1 = (bb + j + half) * SLDS;
#pragma unroll
        for (int c = 0; c < SLAB; c++) {
            float2 a = cs[i0 + c], bv = cs[i1 + c];
            float2 tb = make_float2(bv.x * csn - bv.y * sn, bv.x * sn + bv.y * csn);
            cs[i0 + c] = make_float2(a.x + tb.x, a.y + tb.y);
            cs[i1 + c] = make_float2(a.x - tb.x, a.y - tb.y);
        }
        __syncthreads();
    }
    /* pointwise spectral filter: F *= exp(i * alpha * atan(log(|F|+eps)))   */
    float alpha = *alpha_p;
    for (int idx = t; idx < 1024 * SLAB; idx += 512) {
        int q = idx >> 4, c = idx & 15;
        float2 v = cs[q * SLDS + c];
        float mag = sqrtf(v.x * v.x + v.y * v.y);
        float ph = alpha * atanf(logf(mag + 1e-10f));
        float sp, cp; sincosf(ph, &sp, &cp);
        cs[q * SLDS + c] = make_float2(v.x * cp - v.y * sp, v.x * sp + v.y * cp);
    }
    __syncthreads();
    /* inverse DIF along q (output bit-reversed) */
    for (int st = 10; st >= 1; st--) {
        int half = 1 << (st - 1);
        int j = t & (half - 1);
        int bb = (t >> (st - 1)) << st;
        float ang = 6.2831853071795864f * (float)j / (float)(half << 1);
        float sn, csn; sincosf(ang, &sn, &csn);
        int i0 = (bb + j) * SLDS, i1 = (bb + j + half) * SLDS;
#pragma unroll
        for (int c = 0; c < SLAB; c++) {
            float2 a = cs[i0 + c], bv = cs[i1 + c];
            cs[i0 + c] = make_float2(a.x + bv.x, a.y + bv.y);
            float dx = a.x - bv.x, dy = a.y - bv.y;
            cs[i1 + c] = make_float2(dx * csn - dy * sn, dx * sn + dy * csn);
        }
        __syncthreads();
    }
    const float scl = 1.0f / 1024.0f;
    for (int idx = t; idx < 1024 * SLAB; idx += 512) {
        int q = idx >> 4, c = idx & 15;
        int r = __brev(q) >> 22;
        float2 v = cs[r * SLDS + c];
        base[(size_t)q * 1024 + c] = make_float2(v.x * scl, v.y * scl);
    }
}

/* rowIFFT (k axis) -> real, fused softmax over keys                         */
__global__ void __launch_bounds__(512) fft_rows_inv_softmax(
    const float2* __restrict__ in, float* __restrict__ out)
{
    __shared__ float2 s[1024];
    __shared__ float red[512];
    size_t rb = (size_t)blockIdx.x * 1024;
    int t = threadIdx.x;
    for (int i = t; i < 1024; i += 512) s[swz(i)] = in[rb + i];
    __syncthreads();
    for (int st = 10; st >= 1; st--) {
        int half = 1 << (st - 1);
        int j = t & (half - 1);
        int base = (t >> (st - 1)) << st;
        float ang = 6.2831853071795864f * (float)j / (float)(half << 1);
        float sn, cs_; sincosf(ang, &sn, &cs_);
        int i0 = swz(base + j), i1 = swz(base + j + half);
        float2 a = s[i0], bv = s[i1];
        s[i0] = make_float2(a.x + bv.x, a.y + bv.y);
        float dx = a.x - bv.x, dy = a.y - bv.y;
        s[i1] = make_float2(dx * cs_ - dy * sn, dx * sn + dy * cs_);
        __syncthreads();
    }
    /* slot i holds X[rev(i)]; softmax reductions are order-invariant */
    const float scl = 1.0f / 1024.0f;
    int r0 = __brev(t) >> 22;
    int r1 = __brev(t + 512) >> 22;
    float e0 = s[swz(t)].x * scl;
    float e1 = s[swz(t + 512)].x * scl;
    red[t] = fmaxf(e0, e1);
    __syncthreads();
    for (int o = 256; o > 0; o >>= 1) {
        if (t < o) red[t] = fmaxf(red[t], red[t + o]);
        __syncthreads();
    }
    float m = red[0];
    __syncthreads();
    float p0 = expf(e0 - m), p1 = expf(e1 - m);
    red[t] = p0 + p1;
    __syncthreads();
    for (int o = 256; o > 0; o >>= 1) {
        if (t < o) red[t] += red[t + o];
        __syncthreads();
    }
    float inv = 1.0f / red[0];
    __syncthreads();
    float* vals = (float*)s;              /* reuse smem, natural order */
    vals[r0] = p0 * inv;
    vals[r1] = p1 * inv;
    __syncthreads();
    for (int i = t; i < 1024; i += 512) out[rb + i] = vals[i];
}

/* ============================== launcher =================================== */
extern "C" void kernel_launch(void* const* d_in, const int* in_sizes, int n_in,
                              void* d_out, int out_size)
{
    const float* query = (const float*)d_in[0];
    const float* Wq    = (const float*)d_in[1];
    const float* bq    = (const float*)d_in[2];
    const float* Wk    = (const float*)d_in[3];
    const float* bk    = (const float*)d_in[4];
    const float* Wv    = (const float*)d_in[5];
    const float* bv    = (const float*)d_in[6];
    const float* Wo    = (const float*)d_in[7];
    const float* bo    = (const float*)d_in[8];
    const float* alpha = (const float*)d_in[9];
    float* out = (float*)d_out;

    float  *pQ, *pK, *pV, *pCtx, *pSc;
    float2 *pFreq;
    cudaGetSymbolAddress((void**)&pQ,    g_Q);
    cudaGetSymbolAddress((void**)&pK,    g_K);
    cudaGetSymbolAddress((void**)&pV,    g_V);
    cudaGetSymbolAddress((void**)&pCtx,  g_ctx);
    cudaGetSymbolAddress((void**)&pSc,   g_scores);
    cudaGetSymbolAddress((void**)&pFreq, g_freq);

    size_t col_smem = (size_t)1024 * SLDS * sizeof(float2); /* 139264 B */
    cudaFuncSetAttribute(fft_cols_filter,
                         cudaFuncAttributeMaxDynamicSharedMemorySize,
                         (int)col_smem);

    dim3 gp(E_ / 128, (B_ * S_) / 128);           /* (8, 32) */
    gemm_nt_bias<<<gp, 256>>>(query, Wq, bq, pQ, B_ * S_, E_, E_);
    gemm_nt_bias<<<gp, 256>>>(query, Wk, bk, pK, B_ * S_, E_, E_);
    gemm_nt_bias<<<gp, 256>>>(query, Wv, bv, pV, B_ * S_, E_, E_);

    dim3 gs(S_ / 128, S_ / 128, NBH);             /* (8, 8, 64) */
    gemm_scores<<<gs, 256>>>(pQ, pK, pSc);

    fft_rows_fwd<<<NBH * S_, 512>>>(pSc, pFreq);

    dim3 gc(S_ / SLAB, NBH);                      /* (64, 64) */
    fft_cols_filter<<<gc, 512, col_smem>>>(pFreq, alpha);

    fft_rows_inv_softmax<<<NBH * S_, 512>>>(pFreq, pSc);

    dim3 ga(1, S_ / 128, NBH);                    /* (1, 8, 64) */
    gemm_av<<<ga, 256>>>(pSc, pV, pCtx);

    gemm_nt_bias<<<gp, 256>>>(pCtx, Wo, bo, out, B_ * S_, E_, E_);
}

// round 2
// speedup vs baseline: 1.6230x; 1.6230x over previous
#include <cuda_runtime.h>
#include <math.h>

#define B_   4
#define S_   1024
#define E_   1024
#define H_   16
#define HD_  64
#define NBH  64          /* B*H */
#define KP   528         /* padded half-spectrum width (>=513, 16-mult) */
#define SLAB 8
#define SLDS 9

/* ---------------- scratch (device globals: no allocations allowed) -------- */
__device__ float  g_Q[(size_t)B_ * S_ * E_];
__device__ float  g_K[(size_t)B_ * S_ * E_];
__device__ float  g_V[(size_t)B_ * S_ * E_];
__device__ float  g_ctx[(size_t)B_ * S_ * E_];
__device__ float  g_scores[(size_t)NBH * S_ * S_];   /* 256 MB, reused for attn */
__device__ float2 g_freq[(size_t)NBH * S_ * KP];     /* half-spectrum, ~277 MB */
__device__ float2 g_tw[1024];                        /* W_1024^j, forward sign */

/* ===================== twiddle init ======================================= */
__global__ void init_twiddles(float2* tw)
{
    int j = blockIdx.x * blockDim.x + threadIdx.x;
    if (j < 1024) {
        float ang = -6.28318530717958647692f * (float)j / 1024.0f;
        tw[j] = make_float2(cosf(ang), sinf(ang));
    }
}

/* ===================== complex helpers ==================================== */
__device__ __forceinline__ float2 cadd(float2 a, float2 b) { return make_float2(a.x + b.x, a.y + b.y); }
__device__ __forceinline__ float2 csub(float2 a, float2 b) { return make_float2(a.x - b.x, a.y - b.y); }
__device__ __forceinline__ float2 cmul(float2 a, float2 b) { return make_float2(a.x * b.x - a.y * b.y, a.x * b.y + a.y * b.x); }
__device__ __forceinline__ float2 cmulc(float2 a, float2 b) { return make_float2(a.x * b.x + a.y * b.y, a.y * b.x - a.x * b.y); }

__device__ __forceinline__ int padi(int i) { return i + (i >> 4); }   /* smem pad */
__device__ __forceinline__ int dr4(int k)                              /* base-4 digit reverse, N=1024 */
{
    return ((k & 3) << 8) | (((k >> 2) & 3) << 6) | (((k >> 4) & 3) << 4)
         | (((k >> 6) & 3) << 2) | ((k >> 8) & 3);
}

/* in-place radix-4 DIF forward: natural in -> digit-reversed out. 256 thr.  */
__device__ __forceinline__ void fft4_fwd(float2* s, const float2* tw, int t)
{
#pragma unroll
    for (int ln = 10; ln >= 2; ln -= 2) {
        int q4 = 1 << (ln - 2);
        int j = t & (q4 - 1);
        int i = ((t >> (ln - 2)) << ln) + j;
        int tj = j << (10 - ln);
        float2 w1 = tw[tj], w2 = tw[2 * tj], w3 = tw[3 * tj];
        float2 a = s[padi(i)], b = s[padi(i + q4)];
        float2 c = s[padi(i + 2 * q4)], d = s[padi(i + 3 * q4)];
        float2 t0 = cadd(a, c), t1 = csub(a, c), t2 = cadd(b, d);
        float2 bd = csub(b, d);
        float2 t3 = make_float2(bd.y, -bd.x);           /* -i*(b-d) */
        s[padi(i)]          = cadd(t0, t2);
        s[padi(i + q4)]     = cmul(cadd(t1, t3), w1);
        s[padi(i + 2 * q4)] = cmul(csub(t0, t2), w2);
        s[padi(i + 3 * q4)] = cmul(csub(t1, t3), w3);
        __syncthreads();
    }
}

/* in-place radix-4 DIT inverse: digit-reversed in -> natural out. 256 thr.  */
__device__ __forceinline__ void fft4_inv(float2* s, const float2* tw, int t)
{
#pragma unroll
    for (int ln = 2; ln <= 10; ln += 2) {
        int q4 = 1 << (ln - 2);
        int j = t & (q4 - 1);
        int i = ((t >> (ln - 2)) << ln) + j;
        int tj = j << (10 - ln);
        float2 w1 = tw[tj], w2 = tw[2 * tj], w3 = tw[3 * tj];
        float2 a = s[padi(i)];
        float2 b = cmulc(s[padi(i + q4)], w1);
        float2 c = cmulc(s[padi(i + 2 * q4)], w2);
        float2 d = cmulc(s[padi(i + 3 * q4)], w3);
        float2 t0 = cadd(a, c), t1 = csub(a, c), t2 = cadd(b, d);
        float2 bd = csub(b, d);
        float2 t3 = make_float2(-bd.y, bd.x);           /* +i*(b-d) */
        s[padi(i)]          = cadd(t0, t2);
        s[padi(i + q4)]     = cadd(t1, t3);
        s[padi(i + 2 * q4)] = csub(t0, t2);
        s[padi(i + 3 * q4)] = csub(t1, t3);
        __syncthreads();
    }
}

/* ======== pass 1: 2 packed real rows -> one FFT -> half spectra =========== */
__global__ void __launch_bounds__(256) fft_rows_fwd2(
    const float* __restrict__ in, float2* __restrict__ Y,
    const float2* __restrict__ twg)
{
    __shared__ float2 s[1088];
    __shared__ float2 tw[1024];
    int t = threadIdx.x;
    const float* r0 = in + (size_t)blockIdx.x * 2048;
    const float* r1 = r0 + 1024;
#pragma unroll
    for (int i = t; i < 1024; i += 256) tw[i] = twg[i];
#pragma unroll
    for (int i = t; i < 1024; i += 256)
        s[padi(i)] = make_float2(r0[i], r1[i]);
    __syncthreads();
    fft4_fwd(s, tw, t);
    float2* y0 = Y + (size_t)(2 * blockIdx.x) * KP;
    float2* y1 = y0 + KP;
    for (int k = t; k < 513; k += 256) {
        float2 Zk = s[padi(dr4(k))];
        float2 Zm = s[padi(dr4((1024 - k) & 1023))];
        y0[k] = make_float2(0.5f * (Zk.x + Zm.x), 0.5f * (Zk.y - Zm.y));
        y1[k] = make_float2(0.5f * (Zk.y + Zm.y), 0.5f * (Zm.x - Zk.x));
    }
}

/* ===== pass 2: col FFT (q) + real cos-filter + col IFFT, 8-col slabs ====== */
__global__ void __launch_bounds__(512) fft_cols_filter2(
    float2* __restrict__ Y, const float* __restrict__ alpha_p,
    const float2* __restrict__ twg)
{
    extern __shared__ float2 cs[];     /* [1024][SLDS] */
    int z = blockIdx.y;
    int k0 = blockIdx.x * SLAB;
    float2* base = Y + (size_t)z * S_ * KP + k0;
    int t = threadIdx.x;
    int c = t & 7, b0 = t >> 3;        /* column, butterfly base (0..63) */

    for (int idx = t; idx < 1024 * SLAB; idx += 512) {
        int q = idx >> 3, cc = idx & 7;
        cs[q * SLDS + cc] = base[(size_t)q * KP + cc];
    }
    __syncthreads();
    /* forward DIF along q */
#pragma unroll
    for (int ln = 10; ln >= 2; ln -= 2) {
        int q4 = 1 << (ln - 2);
#pragma unroll
        for (int m = 0; m < 4; m++) {
            int bf = b0 + (m << 6);
            int j = bf & (q4 - 1);
            int i = ((bf >> (ln - 2)) << ln) + j;
            int tj = j << (10 - ln);
            float2 w1 = twg[tj], w2 = twg[2 * tj], w3 = twg[3 * tj];
            int i0 = i * SLDS + c, i1 = (i + q4) * SLDS + c;
            int i2 = (i + 2 * q4) * SLDS + c, i3 = (i + 3 * q4) * SLDS + c;
            float2 a = cs[i0], b = cs[i1], cc2 = cs[i2], d = cs[i3];
            float2 t0 = cadd(a, cc2), t1 = csub(a, cc2), t2 = cadd(b, d);
            float2 bd = csub(b, d);
            float2 t3 = make_float2(bd.y, -bd.x);
            cs[i0] = cadd(t0, t2);
            cs[i1] = cmul(cadd(t1, t3), w1);
            cs[i2] = cmul(csub(t0, t2), w2);
            cs[i3] = cmul(csub(t1, t3), w3);
        }
        __syncthreads();
    }
    /* real spectral filter: F *= cos(alpha * atan(log(|F|+eps))) */
    float alpha = *alpha_p;
    for (int idx = t; idx < 1024 * SLAB; idx += 512) {
        int q = idx >> 3, cc = idx & 7;
        float2 v = cs[q * SLDS + cc];
        float mag = sqrtf(v.x * v.x + v.y * v.y);
        float g = cosf(alpha * atanf(__logf(mag + 1e-10f)));
        cs[q * SLDS + cc] = make_float2(v.x * g, v.y * g);
    }
    __syncthreads();
    /* inverse DIT along q */
#pragma unroll
    for (int ln = 2; ln <= 10; ln += 2) {
        int q4 = 1 << (ln - 2);
#pragma unroll
        for (int m = 0; m < 4; m++) {
            int bf = b0 + (m << 6);
            int j = bf & (q4 - 1);
            int i = ((bf >> (ln - 2)) << ln) + j;
            int tj = j << (10 - ln);
            float2 w1 = twg[tj], w2 = twg[2 * tj], w3 = twg[3 * tj];
            int i0 = i * SLDS + c, i1 = (i + q4) * SLDS + c;
            int i2 = (i + 2 * q4) * SLDS + c, i3 = (i + 3 * q4) * SLDS + c;
            float2 a = cs[i0];
            float2 b = cmulc(cs[i1], w1);
            float2 cc2 = cmulc(cs[i2], w2);
            float2 d = cmulc(cs[i3], w3);
            float2 t0 = cadd(a, cc2), t1 = csub(a, cc2), t2 = cadd(b, d);
            float2 bd = csub(b, d);
            float2 t3 = make_float2(-bd.y, bd.x);
            cs[i0] = cadd(t0, t2);
            cs[i1] = cadd(t1, t3);
            cs[i2] = csub(t0, t2);
            cs[i3] = csub(t1, t3);
        }
        __syncthreads();
    }
    const float scl = 1.0f / 1024.0f;
    for (int idx = t; idx < 1024 * SLAB; idx += 512) {
        int q = idx >> 3, cc = idx & 7;
        float2 v = cs[q * SLDS + cc];
        base[(size_t)q * KP + cc] = make_float2(v.x * scl, v.y * scl);
    }
}

/* ==== pass 3: c2r inverse of 2 packed Hermitian rows + fused softmax ====== */
__global__ void __launch_bounds__(256) fft_rows_inv_softmax2(
    const float2* __restrict__ Y, float* __restrict__ out,
    const float2* __restrict__ twg)
{
    __shared__ float2 s[1088];
    __shared__ float2 tw[1024];
    __shared__ float2 wred[8];
    int t = threadIdx.x;
    const float2* y0 = Y + (size_t)(2 * blockIdx.x) * KP;
    const float2* y1 = y0 + KP;
#pragma unroll
    for (int i = t; i < 1024; i += 256) tw[i] = twg[i];
    for (int k = t; k < 513; k += 256) {
        float2 h0 = y0[k], h1 = y1[k];
        s[padi(dr4(k))] = make_float2(h0.x - h1.y, h0.y + h1.x);   /* H0+iH1  */
        if (k >= 1 && k <= 511)                                    /* mirror  */
            s[padi(dr4(1024 - k))] = make_float2(h0.x + h1.y, h1.x - h0.y);
    }
    __syncthreads();
    fft4_inv(s, tw, t);
    /* Re -> row0, Im -> row1; softmax each over 1024 keys */
    const float scl = 1.0f / 1024.0f;
    float v0[4], v1[4];
    float m0 = -1e30f, m1 = -1e30f;
#pragma unroll
    for (int u = 0; u < 4; u++) {
        float2 x = s[padi(t + 256 * u)];
        v0[u] = x.x * scl; v1[u] = x.y * scl;
        m0 = fmaxf(m0, v0[u]); m1 = fmaxf(m1, v1[u]);
    }
#pragma unroll
    for (int o = 16; o; o >>= 1) {
        m0 = fmaxf(m0, __shfl_xor_sync(0xffffffffu, m0, o));
        m1 = fmaxf(m1, __shfl_xor_sync(0xffffffffu, m1, o));
    }
    if ((t & 31) == 0) wred[t >> 5] = make_float2(m0, m1);
    __syncthreads();
    float2 mm = wred[0];
#pragma unroll
    for (int w = 1; w < 8; w++) { mm.x = fmaxf(mm.x, wred[w].x); mm.y = fmaxf(mm.y, wred[w].y); }
    float p0[4], p1[4], s0 = 0.f, s1 = 0.f;
#pragma unroll
    for (int u = 0; u < 4; u++) {
        p0[u] = __expf(v0[u] - mm.x); p1[u] = __expf(v1[u] - mm.y);
        s0 += p0[u]; s1 += p1[u];
    }
#pragma unroll
    for (int o = 16; o; o >>= 1) {
        s0 += __shfl_xor_sync(0xffffffffu, s0, o);
        s1 += __shfl_xor_sync(0xffffffffu, s1, o);
    }
    __syncthreads();
    if ((t & 31) == 0) wred[t >> 5] = make_float2(s0, s1);
    __syncthreads();
    float2 ss = wred[0];
#pragma unroll
    for (int w = 1; w < 8; w++) { ss.x += wred[w].x; ss.y += wred[w].y; }
    float inv0 = 1.0f / ss.x, inv1 = 1.0f / ss.y;
    float* o0 = out + (size_t)(2 * blockIdx.x) * 1024;
    float* o1 = o0 + 1024;
#pragma unroll
    for (int u = 0; u < 4; u++) {
        o0[t + 256 * u] = p0[u] * inv0;
        o1[t + 256 * u] = p1[u] * inv1;
    }
}

/* ======== GEMM: C = A*B^T + bias, register-pipelined fp32 SIMT =========== */
__global__ void __launch_bounds__(256, 2) gemm_nt_bias(
    const float* __restrict__ A, const float* __restrict__ Bm,
    const float* __restrict__ bias, float* __restrict__ C,
    int M, int N, int K)
{
    __shared__ float As[16][128];
    __shared__ float Bs[16][128];
    int tid = threadIdx.x;
    int tx = tid & 15, ty = tid >> 4;
    const float* Ab = A  + (size_t)blockIdx.y * 128 * K;
    const float* Bb = Bm + (size_t)blockIdx.x * 128 * K;
    int lr = tid >> 2;
    int lc = (tid & 3) << 2;
    float acc[8][8] = {};
    float4 pa0 = *(const float4*)(Ab + (size_t)lr * K + lc);
    float4 pa1 = *(const float4*)(Ab + (size_t)(lr + 64) * K + lc);
    float4 pb0 = *(const float4*)(Bb + (size_t)lr * K + lc);
    float4 pb1 = *(const float4*)(Bb + (size_t)(lr + 64) * K + lc);
    for (int k0 = 0; k0 < K; k0 += 16) {
        As[lc + 0][lr] = pa0.x; As[lc + 1][lr] = pa0.y; As[lc + 2][lr] = pa0.z; As[lc + 3][lr] = pa0.w;
        As[lc + 0][lr + 64] = pa1.x; As[lc + 1][lr + 64] = pa1.y; As[lc + 2][lr + 64] = pa1.z; As[lc + 3][lr + 64] = pa1.w;
        Bs[lc + 0][lr] = pb0.x; Bs[lc + 1][lr] = pb0.y; Bs[lc + 2][lr] = pb0.z; Bs[lc + 3][lr] = pb0.w;
        Bs[lc + 0][lr + 64] = pb1.x; Bs[lc + 1][lr + 64] = pb1.y; Bs[lc + 2][lr + 64] = pb1.z; Bs[lc + 3][lr + 64] = pb1.w;
        __syncthreads();
        if (k0 + 16 < K) {
            pa0 = *(const float4*)(Ab + (size_t)lr * K + k0 + 16 + lc);
            pa1 = *(const float4*)(Ab + (size_t)(lr + 64) * K + k0 + 16 + lc);
            pb0 = *(const float4*)(Bb + (size_t)lr * K + k0 + 16 + lc);
            pb1 = *(const float4*)(Bb + (size_t)(lr + 64) * K + k0 + 16 + lc);
        }
#pragma unroll
        for (int k = 0; k < 16; k++) {
            float a[8], b[8];
#pragma unroll
            for (int i = 0; i < 8; i++) a[i] = As[k][ty * 8 + i];
#pragma unroll
            for (int j = 0; j < 8; j++) b[j] = Bs[k][tx * 8 + j];
#pragma unroll
            for (int i = 0; i < 8; i++)
#pragma unroll
                for (int j = 0; j < 8; j++) acc[i][j] += a[i] * b[j];
        }
        __syncthreads();
    }
    int row0 = blockIdx.y * 128 + ty * 8;
    int col0 = blockIdx.x * 128 + tx * 8;
#pragma unroll
    for (int i = 0; i < 8; i++)
#pragma unroll
        for (int j = 0; j < 8; j++)
            C[(size_t)(row0 + i) * N + col0 + j] = acc[i][j] + bias[col0 + j];
}

/* =========== scores[z,q,k] = scale * sum_d Q[b,q,h,d] K[b,k,h,d] ========== */
__global__ void __launch_bounds__(256, 2) gemm_scores(
    const float* __restrict__ Q, const float* __restrict__ Kmat,
    float* __restrict__ Sc)
{
    __shared__ float As[16][128];
    __shared__ float Bs[16][128];
    int z = blockIdx.z;
    int b = z >> 4, h = z & 15;
    size_t hoff = (size_t)b * S_ * E_ + (size_t)h * HD_;
    int tid = threadIdx.x;
    int tx = tid & 15, ty = tid >> 4;
    const float* Ab = Q    + hoff + (size_t)blockIdx.y * 128 * E_;
    const float* Bb = Kmat + hoff + (size_t)blockIdx.x * 128 * E_;
    int lr = tid >> 2;
    int lc = (tid & 3) << 2;
    float acc[8][8] = {};
    float4 pa0 = *(const float4*)(Ab + (size_t)lr * E_ + lc);
    float4 pa1 = *(const float4*)(Ab + (size_t)(lr + 64) * E_ + lc);
    float4 pb0 = *(const float4*)(Bb + (size_t)lr * E_ + lc);
    float4 pb1 = *(const float4*)(Bb + (size_t)(lr + 64) * E_ + lc);
    for (int k0 = 0; k0 < HD_; k0 += 16) {
        As[lc + 0][lr] = pa0.x; As[lc + 1][lr] = pa0.y; As[lc + 2][lr] = pa0.z; As[lc + 3][lr] = pa0.w;
        As[lc + 0][lr + 64] = pa1.x; As[lc + 1][lr + 64] = pa1.y; As[lc + 2][lr + 64] = pa1.z; As[lc + 3][lr + 64] = pa1.w;
        Bs[lc + 0][lr] = pb0.x; Bs[lc + 1][lr] = pb0.y; Bs[lc + 2][lr] = pb0.z; Bs[lc + 3][lr] = pb0.w;
        Bs[lc + 0][lr + 64] = pb1.x; Bs[lc + 1][lr + 64] = pb1.y; Bs[lc + 2][lr + 64] = pb1.z; Bs[lc + 3][lr + 64] = pb1.w;
        __syncthreads();
        if (k0 + 16 < HD_) {
            pa0 = *(const float4*)(Ab + (size_t)lr * E_ + k0 + 16 + lc);
            pa1 = *(const float4*)(Ab + (size_t)(lr + 64) * E_ + k0 + 16 + lc);
            pb0 = *(const float4*)(Bb + (size_t)lr * E_ + k0 + 16 + lc);
            pb1 = *(const float4*)(Bb + (size_t)(lr + 64) * E_ + k0 + 16 + lc);
        }
#pragma unroll
        for (int k = 0; k < 16; k++) {
            float a[8], b2[8];
#pragma unroll
            for (int i = 0; i < 8; i++) a[i] = As[k][ty * 8 + i];
#pragma unroll
            for (int j = 0; j < 8; j++) b2[j] = Bs[k][tx * 8 + j];
#pragma unroll
            for (int i = 0; i < 8; i++)
#pragma unroll
                for (int j = 0; j < 8; j++) acc[i][j] += a[i] * b2[j];
        }
        __syncthreads();
    }
    float* Cb = Sc + (size_t)z * S_ * S_;
    int row0 = blockIdx.y * 128 + ty * 8;
    int col0 = blockIdx.x * 128 + tx * 8;
    const float scale = 0.125f;
#pragma unroll
    for (int i = 0; i < 8; i++)
#pragma unroll
        for (int j = 0; j < 8; j++)
            Cb[(size_t)(row0 + i) * S_ + col0 + j] = acc[i][j] * scale;
}

/* ============ ctx[b,q,h,d] = sum_k attn[z,q,k] * V[b,k,h,d] =============== */
__global__ void __launch_bounds__(256, 2) gemm_av(
    const float* __restrict__ attn, const float* __restrict__ V,
    float* __restrict__ ctx)
{
    __shared__ float As[16][128];
    __shared__ float Bs[16][68];
    int z = blockIdx.z;
    int b = z >> 4, h = z & 15;
    int tid = threadIdx.x;
    int tx = tid & 15, ty = tid >> 4;
    const float* Ab    = attn + (size_t)z * S_ * S_ + (size_t)blockIdx.y * 128 * S_;
    const float* Bbase = V + (size_t)b * S_ * E_ + (size_t)h * HD_;
    int lrA = tid >> 2, lcA = (tid & 3) << 2;
    int krB = tid >> 4, ncB = (tid & 15) << 2;
    float acc[8][4] = {};
    float4 pa0 = *(const float4*)(Ab + (size_t)lrA * S_ + lcA);
    float4 pa1 = *(const float4*)(Ab + (size_t)(lrA + 64) * S_ + lcA);
    float4 pb  = *(const float4*)(Bbase + (size_t)krB * E_ + ncB);
    for (int k0 = 0; k0 < S_; k0 += 16) {
        As[lcA + 0][lrA] = pa0.x; As[lcA + 1][lrA] = pa0.y; As[lcA + 2][lrA] = pa0.z; As[lcA + 3][lrA] = pa0.w;
        As[lcA + 0][lrA + 64] = pa1.x; As[lcA + 1][lrA + 64] = pa1.y; As[lcA + 2][lrA + 64] = pa1.z; As[lcA + 3][lrA + 64] = pa1.w;
        Bs[krB][ncB + 0] = pb.x; Bs[krB][ncB + 1] = pb.y;
        Bs[krB][ncB + 2] = pb.z; Bs[krB][ncB + 3] = pb.w;
        __syncthreads();
        if (k0 + 16 < S_) {
            pa0 = *(const float4*)(Ab + (size_t)lrA * S_ + k0 + 16 + lcA);
            pa1 = *(const float4*)(Ab + (size_t)(lrA + 64) * S_ + k0 + 16 + lcA);
            pb  = *(const float4*)(Bbase + (size_t)(k0 + 16 + krB) * E_ + ncB);
        }
#pragma unroll
        for (int k = 0; k < 16; k++) {
            float a[8], b2[4];
#pragma unroll
            for (int i = 0; i < 8; i++) a[i] = As[k][ty * 8 + i];
#pragma unroll
            for (int j = 0; j < 4; j++) b2[j] = Bs[k][tx * 4 + j];
#pragma unroll
            for (int i = 0; i < 8; i++)
#pragma unroll
                for (int j = 0; j < 4; j++) acc[i][j] += a[i] * b2[j];
        }
        __syncthreads();
    }
    int q0 = blockIdx.y * 128 + ty * 8;
#pragma unroll
    for (int i = 0; i < 8; i++)
#pragma unroll
        for (int j = 0; j < 4; j++)
            ctx[(size_t)(b * S_ + q0 + i) * E_ + h * HD_ + tx * 4 + j] = acc[i][j];
}

/* ============================== launcher =================================== */
extern "C" void kernel_launch(void* const* d_in, const int* in_sizes, int n_in,
                              void* d_out, int out_size)
{
    const float* query = (const float*)d_in[0];
    const float* Wq    = (const float*)d_in[1];
    const float* bq    = (const float*)d_in[2];
    const float* Wk    = (const float*)d_in[3];
    const float* bk    = (const float*)d_in[4];
    const float* Wv    = (const float*)d_in[5];
    const float* bv    = (const float*)d_in[6];
    const float* Wo    = (const float*)d_in[7];
    const float* bo    = (const float*)d_in[8];
    const float* alpha = (const float*)d_in[9];
    float* out = (float*)d_out;

    float  *pQ, *pK, *pV, *pCtx, *pSc;
    float2 *pFreq, *pTw;
    cudaGetSymbolAddress((void**)&pQ,    g_Q);
    cudaGetSymbolAddress((void**)&pK,    g_K);
    cudaGetSymbolAddress((void**)&pV,    g_V);
    cudaGetSymbolAddress((void**)&pCtx,  g_ctx);
    cudaGetSymbolAddress((void**)&pSc,   g_scores);
    cudaGetSymbolAddress((void**)&pFreq, g_freq);
    cudaGetSymbolAddress((void**)&pTw,   g_tw);

    size_t col_smem = (size_t)1024 * SLDS * sizeof(float2);   /* 73728 B */
    cudaFuncSetAttribute(fft_cols_filter2,
                         cudaFuncAttributeMaxDynamicSharedMemorySize,
                         (int)col_smem);

    init_twiddles<<<4, 256>>>(pTw);

    dim3 gp(E_ / 128, (B_ * S_) / 128);           /* (8, 32) */
    gemm_nt_bias<<<gp, 256>>>(query, Wq, bq, pQ, B_ * S_, E_, E_);
    gemm_nt_bias<<<gp, 256>>>(query, Wk, bk, pK, B_ * S_, E_, E_);
    gemm_nt_bias<<<gp, 256>>>(query, Wv, bv, pV, B_ * S_, E_, E_);

    dim3 gs(S_ / 128, S_ / 128, NBH);             /* (8, 8, 64) */
    gemm_scores<<<gs, 256>>>(pQ, pK, pSc);

    fft_rows_fwd2<<<NBH * S_ / 2, 256>>>(pSc, pFreq, pTw);

    dim3 gc(65, NBH);                             /* 65 slabs x 64 heads */
    fft_cols_filter2<<<gc, 512, col_smem>>>(pFreq, alpha, pTw);

    fft_rows_inv_softmax2<<<NBH * S_ / 2, 256>>>(pFreq, pSc, pTw);

    dim3 ga(1, S_ / 128, NBH);                    /* (1, 8, 64) */
    gemm_av<<<ga, 256>>>(pSc, pV, pCtx);

    gemm_nt_bias<<<gp, 256>>>(pCtx, Wo, bo, out, B_ * S_, E_, E_);
}

// round 4
// speedup vs baseline: 2.0382x; 1.2558x over previous
#include <cuda_runtime.h>
#include <cuda_bf16.h>
#include <math.h>
#include <stdint.h>

#define B_   4
#define S_   1024
#define E_   1024
#define H_   16
#define HD_  64
#define NBH  64          /* B*H */
#define KP   528         /* padded half-spectrum width (>=513, 16-mult) */
#define SLAB 8
#define SLDS 9

/* ---------------- scratch (device globals: no allocations allowed) -------- */
__device__ float  g_Q[(size_t)B_ * S_ * E_];
__device__ float  g_K[(size_t)B_ * S_ * E_];
__device__ float  g_V[(size_t)B_ * S_ * E_];
__device__ float  g_Vt[(size_t)NBH * HD_ * S_];      /* V transposed per head  */
__device__ float  g_ctx[(size_t)B_ * S_ * E_];
__device__ float  g_scores[(size_t)NBH * S_ * S_];   /* reused for attn */
__device__ float2 g_freq[(size_t)NBH * S_ * KP];     /* half-spectrum */
__device__ float2 g_tw[1024];                        /* W_1024^j, forward sign */

/* =============== mma.sync m16n8k16 bf16 helper (sm_80+, no 'a') =========== */
__device__ __forceinline__ void mma16816(float* d, const uint32_t* a, const uint32_t* b)
{
    asm volatile(
        "mma.sync.aligned.m16n8k16.row.col.f32.bf16.bf16.f32 "
        "{%0,%1,%2,%3}, {%4,%5,%6,%7}, {%8,%9}, {%0,%1,%2,%3};"
        : "+f"(d[0]), "+f"(d[1]), "+f"(d[2]), "+f"(d[3])
        : "r"(a[0]), "r"(a[1]), "r"(a[2]), "r"(a[3]), "r"(b[0]), "r"(b[1]));
}

__device__ __forceinline__ void split2(float x, float y, uint32_t& h, uint32_t& l)
{
    __nv_bfloat16 hx = __float2bfloat16(x), hy = __float2bfloat16(y);
    __nv_bfloat16 lx = __float2bfloat16(x - __bfloat162float(hx));
    __nv_bfloat16 ly = __float2bfloat16(y - __bfloat162float(hy));
    h = (uint32_t)__bfloat16_as_ushort(hx) | ((uint32_t)__bfloat16_as_ushort(hy) << 16);
    l = (uint32_t)__bfloat16_as_ushort(lx) | ((uint32_t)__bfloat16_as_ushort(ly) << 16);
}

/* ====== split-bf16 tensor-core GEMM: C = (A * B^T) * oscale (+ bias) ====== */
/* MODE 0: projections (bias). MODE 1: per-head scores. MODE 2: attn*Vt.     */
/* All global strides are 1024 floats. A tiles 128 rows; B tiles BN rows.    */
template<int MODE, int BN, int WROWS, int WCOLS, int KTOT>
__global__ void __launch_bounds__(256, 1) mma_gemm(
    const float* __restrict__ A, const float* __restrict__ Bm,
    const float* __restrict__ bias, float* __restrict__ C, float oscale)
{
    constexpr int BM = 128, BK = 32, LDT = BK + 4;       /* pad: 36 elems */
    constexpr int WTM = BM / WROWS, WTN = BN / WCOLS;
    constexpr int FM = WTM / 16, FN = WTN / 8;
    constexpr int TPRA = 256 / BM, FA = 8 / TPRA;        /* 2, 4 */
    constexpr int TPRB = 256 / BN, FB = 8 / TPRB;

    __shared__ uint16_t Ah[BM * LDT], Al[BM * LDT];
    __shared__ uint16_t Bh[BN * LDT], Bl[BN * LDT];

    int tid = threadIdx.x;
    int lane = tid & 31, wid = tid >> 5;
    int wrow = wid / WCOLS, wcol = wid % WCOLS;
    int m0 = wrow * WTM, n0 = wcol * WTN;
    int gid = lane >> 2, tig = lane & 3;

    size_t offA = 0, offB = 0, offC = 0;
    if (MODE == 1) {
        int z = blockIdx.z;
        size_t ho = (size_t)(z >> 4) * S_ * E_ + (size_t)(z & 15) * HD_;
        offA = ho; offB = ho; offC = (size_t)z * S_ * S_;
    } else if (MODE == 2) {
        int z = blockIdx.z;
        offA = (size_t)z * S_ * S_;
        offB = (size_t)z * HD_ * S_;
        offC = (size_t)(z >> 4) * S_ * E_ + (size_t)(z & 15) * HD_;
    }
    const float* Abase = A + offA + (size_t)blockIdx.y * BM * 1024;
    const float* Bbase = Bm + offB + (size_t)blockIdx.x * BN * 1024;

    int arow = tid / TPRA, aj0 = (tid % TPRA) * FA;
    int brow = tid / TPRB, bj0 = (tid % TPRB) * FB;

    float acc[FM][FN][4];
#pragma unroll
    for (int i = 0; i < FM; i++)
#pragma unroll
        for (int j = 0; j < FN; j++)
#pragma unroll
            for (int u = 0; u < 4; u++) acc[i][j][u] = 0.f;

    float4 pa[FA], pb[FB];
#pragma unroll
    for (int i = 0; i < FA; i++)
        pa[i] = *(const float4*)(Abase + (size_t)arow * 1024 + (aj0 + i) * 4);
#pragma unroll
    for (int i = 0; i < FB; i++)
        pb[i] = *(const float4*)(Bbase + (size_t)brow * 1024 + (bj0 + i) * 4);

    for (int k0 = 0; k0 < KTOT; k0 += BK) {
        /* stage: split-convert prefetched regs into hi/lo smem tiles */
#pragma unroll
        for (int i = 0; i < FA; i++) {
            uint2 hv, lv;
            split2(pa[i].x, pa[i].y, hv.x, lv.x);
            split2(pa[i].z, pa[i].w, hv.y, lv.y);
            int so = arow * LDT + (aj0 + i) * 4;
            *(uint2*)&Ah[so] = hv;
            *(uint2*)&Al[so] = lv;
        }
#pragma unroll
        for (int i = 0; i < FB; i++) {
            uint2 hv, lv;
            split2(pb[i].x, pb[i].y, hv.x, lv.x);
            split2(pb[i].z, pb[i].w, hv.y, lv.y);
            int so = brow * LDT + (bj0 + i) * 4;
            *(uint2*)&Bh[so] = hv;
            *(uint2*)&Bl[so] = lv;
        }
        __syncthreads();
        if (k0 + BK < KTOT) {
#pragma unroll
            for (int i = 0; i < FA; i++)
                pa[i] = *(const float4*)(Abase + (size_t)arow * 1024 + k0 + BK + (aj0 + i) * 4);
#pragma unroll
            for (int i = 0; i < FB; i++)
                pb[i] = *(const float4*)(Bbase + (size_t)brow * 1024 + k0 + BK + (bj0 + i) * 4);
        }
        /* compute: 2 x k16 steps, 3 products (AhBh + AhBl + AlBh) */
#pragma unroll
        for (int ks = 0; ks < 2; ks++) {
            int c0 = ks * 16 + tig * 2;
            uint32_t bhf[FN][2], blf[FN][2];
#pragma unroll
            for (int fn = 0; fn < FN; fn++) {
                int rb = (n0 + fn * 8 + gid) * LDT + c0;
                bhf[fn][0] = *(const uint32_t*)&Bh[rb];
                bhf[fn][1] = *(const uint32_t*)&Bh[rb + 8];
                blf[fn][0] = *(const uint32_t*)&Bl[rb];
                blf[fn][1] = *(const uint32_t*)&Bl[rb + 8];
            }
#pragma unroll
            for (int fm = 0; fm < FM; fm++) {
                int ra = (m0 + fm * 16 + gid) * LDT + c0;
                int ra8 = ra + 8 * LDT;
                uint32_t ahf[4], alf[4];
                ahf[0] = *(const uint32_t*)&Ah[ra];
                ahf[1] = *(const uint32_t*)&Ah[ra8];
                ahf[2] = *(const uint32_t*)&Ah[ra + 8];
                ahf[3] = *(const uint32_t*)&Ah[ra8 + 8];
                alf[0] = *(const uint32_t*)&Al[ra];
                alf[1] = *(const uint32_t*)&Al[ra8];
                alf[2] = *(const uint32_t*)&Al[ra + 8];
                alf[3] = *(const uint32_t*)&Al[ra8 + 8];
#pragma unroll
                for (int fn = 0; fn < FN; fn++) {
                    mma16816(acc[fm][fn], ahf, bhf[fn]);
                    mma16816(acc[fm][fn], ahf, blf[fn]);
                    mma16816(acc[fm][fn], alf, bhf[fn]);
                }
            }
        }
        __syncthreads();
    }
    /* epilogue */
#pragma unroll
    for (int fm = 0; fm < FM; fm++) {
        size_t r0 = (size_t)blockIdx.y * BM + m0 + fm * 16 + gid;
#pragma unroll
        for (int fn = 0; fn < FN; fn++) {
            int cgl = blockIdx.x * BN + n0 + fn * 8 + tig * 2;
            float b0 = 0.f, b1 = 0.f;
            if (MODE == 0) { b0 = bias[cgl]; b1 = bias[cgl + 1]; }
            float2 v0 = make_float2(acc[fm][fn][0] * oscale + b0,
                                    acc[fm][fn][1] * oscale + b1);
            float2 v1 = make_float2(acc[fm][fn][2] * oscale + b0,
                                    acc[fm][fn][3] * oscale + b1);
            *(float2*)&C[offC + r0 * 1024 + cgl] = v0;
            *(float2*)&C[offC + (r0 + 8) * 1024 + cgl] = v1;
        }
    }
}

/* ========= Vt[z][d][k] = V[b][k][h*64+d]  (per-head transpose) ============ */
__global__ void transpose_v(const float* __restrict__ V, float* __restrict__ Vt)
{
    __shared__ float tile[32][33];
    int z = blockIdx.z;
    int b = z >> 4, h = z & 15;
    int k0 = blockIdx.x * 32, d0 = blockIdx.y * 32;
    int tx = threadIdx.x, ty = threadIdx.y;
#pragma unroll
    for (int i = 0; i < 4; i++)
        tile[ty + i * 8][tx] =
            V[((size_t)b * S_ + k0 + ty + i * 8) * E_ + h * HD_ + d0 + tx];
    __syncthreads();
#pragma unroll
    for (int i = 0; i < 4; i++)
        Vt[((size_t)z * HD_ + d0 + ty + i * 8) * S_ + k0 + tx] = tile[tx][ty + i * 8];
}

/* ===================== twiddle init ======================================= */
__global__ void init_twiddles(float2* tw)
{
    int j = blockIdx.x * blockDim.x + threadIdx.x;
    if (j < 1024) {
        float ang = -6.28318530717958647692f * (float)j / 1024.0f;
        tw[j] = make_float2(cosf(ang), sinf(ang));
    }
}

/* ===================== complex helpers ==================================== */
__device__ __forceinline__ float2 cadd(float2 a, float2 b) { return make_float2(a.x + b.x, a.y + b.y); }
__device__ __forceinline__ float2 csub(float2 a, float2 b) { return make_float2(a.x - b.x, a.y - b.y); }
__device__ __forceinline__ float2 cmul(float2 a, float2 b) { return make_float2(a.x * b.x - a.y * b.y, a.x * b.y + a.y * b.x); }
__device__ __forceinline__ float2 cmulc(float2 a, float2 b) { return make_float2(a.x * b.x + a.y * b.y, a.y * b.x - a.x * b.y); }

__device__ __forceinline__ int padi(int i) { return i + (i >> 4); }
__device__ __forceinline__ int dr4(int k)
{
    return ((k & 3) << 8) | (((k >> 2) & 3) << 6) | (((k >> 4) & 3) << 4)
         | (((k >> 6) & 3) << 2) | ((k >> 8) & 3);
}

__device__ __forceinline__ void fft4_fwd(float2* s, const float2* tw, int t)
{
#pragma unroll
    for (int ln = 10; ln >= 2; ln -= 2) {
        int q4 = 1 << (ln - 2);
        int j = t & (q4 - 1);
        int i = ((t >> (ln - 2)) << ln) + j;
        int tj = j << (10 - ln);
        float2 w1 = tw[tj], w2 = tw[2 * tj], w3 = tw[3 * tj];
        float2 a = s[padi(i)], b = s[padi(i + q4)];
        float2 c = s[padi(i + 2 * q4)], d = s[padi(i + 3 * q4)];
        float2 t0 = cadd(a, c), t1 = csub(a, c), t2 = cadd(b, d);
        float2 bd = csub(b, d);
        float2 t3 = make_float2(bd.y, -bd.x);
        s[padi(i)]          = cadd(t0, t2);
        s[padi(i + q4)]     = cmul(cadd(t1, t3), w1);
        s[padi(i + 2 * q4)] = cmul(csub(t0, t2), w2);
        s[padi(i + 3 * q4)] = cmul(csub(t1, t3), w3);
        __syncthreads();
    }
}

__device__ __forceinline__ void fft4_inv(float2* s, const float2* tw, int t)
{
#pragma unroll
    for (int ln = 2; ln <= 10; ln += 2) {
        int q4 = 1 << (ln - 2);
        int j = t & (q4 - 1);
        int i = ((t >> (ln - 2)) << ln) + j;
        int tj = j << (10 - ln);
        float2 w1 = tw[tj], w2 = tw[2 * tj], w3 = tw[3 * tj];
        float2 a = s[padi(i)];
        float2 b = cmulc(s[padi(i + q4)], w1);
        float2 c = cmulc(s[padi(i + 2 * q4)], w2);
        float2 d = cmulc(s[padi(i + 3 * q4)], w3);
        float2 t0 = cadd(a, c), t1 = csub(a, c), t2 = cadd(b, d);
        float2 bd = csub(b, d);
        float2 t3 = make_float2(-bd.y, bd.x);
        s[padi(i)]          = cadd(t0, t2);
        s[padi(i + q4)]     = cadd(t1, t3);
        s[padi(i + 2 * q4)] = csub(t0, t2);
        s[padi(i + 3 * q4)] = csub(t1, t3);
        __syncthreads();
    }
}

/* ======== pass 1: 2 packed real rows -> one FFT -> half spectra =========== */
__global__ void __launch_bounds__(256) fft_rows_fwd2(
    const float* __restrict__ in, float2* __restrict__ Y,
    const float2* __restrict__ twg)
{
    __shared__ float2 s[1088];
    __shared__ float2 tw[1024];
    int t = threadIdx.x;
    const float* r0 = in + (size_t)blockIdx.x * 2048;
    const float* r1 = r0 + 1024;
#pragma unroll
    for (int i = t; i < 1024; i += 256) tw[i] = twg[i];
#pragma unroll
    for (int i = t; i < 1024; i += 256)
        s[padi(i)] = make_float2(r0[i], r1[i]);
    __syncthreads();
    fft4_fwd(s, tw, t);
    float2* y0 = Y + (size_t)(2 * blockIdx.x) * KP;
    float2* y1 = y0 + KP;
    for (int k = t; k < 513; k += 256) {
        float2 Zk = s[padi(dr4(k))];
        float2 Zm = s[padi(dr4((1024 - k) & 1023))];
        y0[k] = make_float2(0.5f * (Zk.x + Zm.x), 0.5f * (Zk.y - Zm.y));
        y1[k] = make_float2(0.5f * (Zk.y + Zm.y), 0.5f * (Zm.x - Zk.x));
    }
}

/* ===== pass 2: col FFT (q) + real cos-filter + col IFFT, 8-col slabs ====== */
__global__ void __launch_bounds__(512) fft_cols_filter2(
    float2* __restrict__ Y, const float* __restrict__ alpha_p,
    const float2* __restrict__ twg)
{
    extern __shared__ float2 cs[];
    int z = blockIdx.y;
    int k0 = blockIdx.x * SLAB;
    float2* base = Y + (size_t)z * S_ * KP + k0;
    int t = threadIdx.x;
    int c = t & 7, b0 = t >> 3;

    for (int idx = t; idx < 1024 * SLAB; idx += 512) {
        int q = idx >> 3, cc = idx & 7;
        cs[q * SLDS + cc] = base[(size_t)q * KP + cc];
    }
    __syncthreads();
#pragma unroll
    for (int ln = 10; ln >= 2; ln -= 2) {
        int q4 = 1 << (ln - 2);
#pragma unroll
        for (int m = 0; m < 4; m++) {
            int bf = b0 + (m << 6);
            int j = bf & (q4 - 1);
            int i = ((bf >> (ln - 2)) << ln) + j;
            int tj = j << (10 - ln);
            float2 w1 = twg[tj], w2 = twg[2 * tj], w3 = twg[3 * tj];
            int i0 = i * SLDS + c, i1 = (i + q4) * SLDS + c;
            int i2 = (i + 2 * q4) * SLDS + c, i3 = (i + 3 * q4) * SLDS + c;
            float2 a = cs[i0], b = cs[i1], cc2 = cs[i2], d = cs[i3];
            float2 t0 = cadd(a, cc2), t1 = csub(a, cc2), t2 = cadd(b, d);
            float2 bd = csub(b, d);
            float2 t3 = make_float2(bd.y, -bd.x);
            cs[i0] = cadd(t0, t2);
            cs[i1] = cmul(cadd(t1, t3), w1);
            cs[i2] = cmul(csub(t0, t2), w2);
            cs[i3] = cmul(csub(t1, t3), w3);
        }
        __syncthreads();
    }
    float alpha = *alpha_p;
    for (int idx = t; idx < 1024 * SLAB; idx += 512) {
        int q = idx >> 3, cc = idx & 7;
        float2 v = cs[q * SLDS + cc];
        float mag = sqrtf(v.x * v.x + v.y * v.y);
        float g = cosf(alpha * atanf(__logf(mag + 1e-10f)));
        cs[q * SLDS + cc] = make_float2(v.x * g, v.y * g);
    }
    __syncthreads();
#pragma unroll
    for (int ln = 2; ln <= 10; ln += 2) {
        int q4 = 1 << (ln - 2);
#pragma unroll
        for (int m = 0; m < 4; m++) {
            int bf = b0 + (m << 6);
            int j = bf & (q4 - 1);
            int i = ((bf >> (ln - 2)) << ln) + j;
            int tj = j << (10 - ln);
            float2 w1 = twg[tj], w2 = twg[2 * tj], w3 = twg[3 * tj];
            int i0 = i * SLDS + c, i1 = (i + q4) * SLDS + c;
            int i2 = (i + 2 * q4) * SLDS + c, i3 = (i + 3 * q4) * SLDS + c;
            float2 a = cs[i0];
            float2 b = cmulc(cs[i1], w1);
            float2 cc2 = cmulc(cs[i2], w2);
            float2 d = cmulc(cs[i3], w3);
            float2 t0 = cadd(a, cc2), t1 = csub(a, cc2), t2 = cadd(b, d);
            float2 bd = csub(b, d);
            float2 t3 = make_float2(-bd.y, bd.x);
            cs[i0] = cadd(t0, t2);
            cs[i1] = cadd(t1, t3);
            cs[i2] = csub(t0, t2);
            cs[i3] = csub(t1, t3);
        }
        __syncthreads();
    }
    const float scl = 1.0f / 1024.0f;
    for (int idx = t; idx < 1024 * SLAB; idx += 512) {
        int q = idx >> 3, cc = idx & 7;
        float2 v = cs[q * SLDS + cc];
        base[(size_t)q * KP + cc] = make_float2(v.x * scl, v.y * scl);
    }
}

/* ==== pass 3: c2r inverse of 2 packed Hermitian rows + fused softmax ====== */
__global__ void __launch_bounds__(256) fft_rows_inv_softmax2(
    const float2* __restrict__ Y, float* __restrict__ out,
    const float2* __restrict__ twg)
{
    __shared__ float2 s[1088];
    __shared__ float2 tw[1024];
    __shared__ float2 wred[8];
    int t = threadIdx.x;
    const float2* y0 = Y + (size_t)(2 * blockIdx.x) * KP;
    const float2* y1 = y0 + KP;
#pragma unroll
    for (int i = t; i < 1024; i += 256) tw[i] = twg[i];
    for (int k = t; k < 513; k += 256) {
        float2 h0 = y0[k], h1 = y1[k];
        s[padi(dr4(k))] = make_float2(h0.x - h1.y, h0.y + h1.x);
        if (k >= 1 && k <= 511)
            s[padi(dr4(1024 - k))] = make_float2(h0.x + h1.y, h1.x - h0.y);
    }
    __syncthreads();
    fft4_inv(s, tw, t);
    const float scl = 1.0f / 1024.0f;
    float v0[4], v1[4];
    float m0 = -1e30f, m1 = -1e30f;
#pragma unroll
    for (int u = 0; u < 4; u++) {
        float2 x = s[padi(t + 256 * u)];
        v0[u] = x.x * scl; v1[u] = x.y * scl;
        m0 = fmaxf(m0, v0[u]); m1 = fmaxf(m1, v1[u]);
    }
#pragma unroll
    for (int o = 16; o; o >>= 1) {
        m0 = fmaxf(m0, __shfl_xor_sync(0xffffffffu, m0, o));
        m1 = fmaxf(m1, __shfl_xor_sync(0xffffffffu, m1, o));
    }
    if ((t & 31) == 0) wred[t >> 5] = make_float2(m0, m1);
    __syncthreads();
    float2 mm = wred[0];
#pragma unroll
    for (int w = 1; w < 8; w++) { mm.x = fmaxf(mm.x, wred[w].x); mm.y = fmaxf(mm.y, wred[w].y); }
    float p0[4], p1[4], s0 = 0.f, s1 = 0.f;
#pragma unroll
    for (int u = 0; u < 4; u++) {
        p0[u] = __expf(v0[u] - mm.x); p1[u] = __expf(v1[u] - mm.y);
        s0 += p0[u]; s1 += p1[u];
    }
#pragma unroll
    for (int o = 16; o; o >>= 1) {
        s0 += __shfl_xor_sync(0xffffffffu, s0, o);
        s1 += __shfl_xor_sync(0xffffffffu, s1, o);
    }
    __syncthreads();
    if ((t & 31) == 0) wred[t >> 5] = make_float2(s0, s1);
    __syncthreads();
    float2 ss = wred[0];
#pragma unroll
    for (int w = 1; w < 8; w++) { ss.x += wred[w].x; ss.y += wred[w].y; }
    float inv0 = 1.0f / ss.x, inv1 = 1.0f / ss.y;
    float* o0 = out + (size_t)(2 * blockIdx.x) * 1024;
    float* o1 = o0 + 1024;
#pragma unroll
    for (int u = 0; u < 4; u++) {
        o0[t + 256 * u] = p0[u] * inv0;
        o1[t + 256 * u] = p1[u] * inv1;
    }
}

/* ============================== launcher =================================== */
extern "C" void kernel_launch(void* const* d_in, const int* in_sizes, int n_in,
                              void* d_out, int out_size)
{
    const float* query = (const float*)d_in[0];
    const float* Wq    = (const float*)d_in[1];
    const float* bq    = (const float*)d_in[2];
    const float* Wk    = (const float*)d_in[3];
    const float* bk    = (const float*)d_in[4];
    const float* Wv    = (const float*)d_in[5];
    const float* bv    = (const float*)d_in[6];
    const float* Wo    = (const float*)d_in[7];
    const float* bo    = (const float*)d_in[8];
    const float* alpha = (const float*)d_in[9];
    float* out = (float*)d_out;

    float  *pQ, *pK, *pV, *pVt, *pCtx, *pSc;
    float2 *pFreq, *pTw;
    cudaGetSymbolAddress((void**)&pQ,    g_Q);
    cudaGetSymbolAddress((void**)&pK,    g_K);
    cudaGetSymbolAddress((void**)&pV,    g_V);
    cudaGetSymbolAddress((void**)&pVt,   g_Vt);
    cudaGetSymbolAddress((void**)&pCtx,  g_ctx);
    cudaGetSymbolAddress((void**)&pSc,   g_scores);
    cudaGetSymbolAddress((void**)&pFreq, g_freq);
    cudaGetSymbolAddress((void**)&pTw,   g_tw);

    size_t col_smem = (size_t)1024 * SLDS * sizeof(float2);
    cudaFuncSetAttribute(fft_cols_filter2,
                         cudaFuncAttributeMaxDynamicSharedMemorySize,
                         (int)col_smem);

    init_twiddles<<<4, 256>>>(pTw);

    dim3 gp(E_ / 128, (B_ * S_) / 128, 1);        /* (8, 32) */
    mma_gemm<0, 128, 2, 4, 1024><<<gp, 256>>>(query, Wq, bq, pQ, 1.0f);
    mma_gemm<0, 128, 2, 4, 1024><<<gp, 256>>>(query, Wk, bk, pK, 1.0f);
    mma_gemm<0, 128, 2, 4, 1024><<<gp, 256>>>(query, Wv, bv, pV, 1.0f);

    transpose_v<<<dim3(32, 2, NBH), dim3(32, 8)>>>(pV, pVt);

    dim3 gs(S_ / 128, S_ / 128, NBH);             /* (8, 8, 64) */
    mma_gemm<1, 128, 2, 4, 64><<<gs, 256>>>(pQ, pK, (const float*)0, pSc, 0.125f);

    fft_rows_fwd2<<<NBH * S_ / 2, 256>>>(pSc, pFreq, pTw);

    dim3 gc(65, NBH);
    fft_cols_filter2<<<gc, 512, col_smem>>>(pFreq, alpha, pTw);

    fft_rows_inv_softmax2<<<NBH * S_ / 2, 256>>>(pFreq, pSc, pTw);

    dim3 ga(1, S_ / 128, NBH);                    /* (1, 8, 64) */
    mma_gemm<2, 64, 4, 2, 1024><<<ga, 256>>>(pSc, pVt, (const float*)0, pCtx, 1.0f);

    mma_gemm<0, 128, 2, 4, 1024><<<gp, 256>>>(pCtx, Wo, bo, out, 1.0f);
}

// round 5
// speedup vs baseline: 2.6318x; 1.2913x over previous
#include <cuda_runtime.h>
#include <cuda_bf16.h>
#include <math.h>
#include <stdint.h>

#define B_   4
#define S_   1024
#define E_   1024
#define H_   16
#define HD_  64
#define NBH  64          /* B*H */
#define KP   528         /* padded half-spectrum width (>=513, 16-mult) */
#define SLAB 8
#define SLDS 9
#define NELEM ((size_t)B_ * S_ * E_)   /* 4M */

/* ---------------- scratch (device globals: no allocations allowed) -------- */
__device__ __nv_bfloat16 g_qh[NELEM],  g_ql[NELEM];    /* query split        */
__device__ __nv_bfloat16 g_Wqh[E_*E_], g_Wql[E_*E_];
__device__ __nv_bfloat16 g_Wkh[E_*E_], g_Wkl[E_*E_];
__device__ __nv_bfloat16 g_Wvh[E_*E_], g_Wvl[E_*E_];
__device__ __nv_bfloat16 g_Woh[E_*E_], g_Wol[E_*E_];
__device__ __nv_bfloat16 g_Qh[NELEM],  g_Ql[NELEM];
__device__ __nv_bfloat16 g_Kh[NELEM],  g_Kl[NELEM];
__device__ float         g_V[NELEM];
__device__ __nv_bfloat16 g_Vth[NELEM], g_Vtl[NELEM];   /* [z][d][k]          */
__device__ float         g_scores[(size_t)NBH * S_ * S_];
__device__ __nv_bfloat16 g_ah[(size_t)NBH * S_ * S_];  /* attn split         */
__device__ __nv_bfloat16 g_al[(size_t)NBH * S_ * S_];
__device__ __nv_bfloat16 g_ch[NELEM],  g_cl[NELEM];    /* ctx split          */
__device__ float2 g_freq[(size_t)NBH * S_ * KP];
__device__ float2 g_tw[1024];

/* ======================= small helpers ==================================== */
__device__ __forceinline__ uint32_t smem_u32(const void* p) {
    uint32_t a;
    asm("{ .reg .u64 t; cvta.to.shared.u64 t, %1; cvt.u32.u64 %0, t; }"
        : "=r"(a) : "l"(p));
    return a;
}
#define CP16(dst, src) \
    asm volatile("cp.async.cg.shared.global [%0], [%1], 16;" \
                 :: "r"(dst), "l"(src))
#define CP_COMMIT() asm volatile("cp.async.commit_group;" ::: "memory")
#define CP_WAIT1()  asm volatile("cp.async.wait_group 1;" ::: "memory")
#define CP_WAIT0()  asm volatile("cp.async.wait_group 0;" ::: "memory")

__device__ __forceinline__ void mma16816(float* d, const uint32_t* a, const uint32_t* b)
{
    asm volatile(
        "mma.sync.aligned.m16n8k16.row.col.f32.bf16.bf16.f32 "
        "{%0,%1,%2,%3}, {%4,%5,%6,%7}, {%8,%9}, {%0,%1,%2,%3};"
        : "+f"(d[0]), "+f"(d[1]), "+f"(d[2]), "+f"(d[3])
        : "r"(a[0]), "r"(a[1]), "r"(a[2]), "r"(a[3]), "r"(b[0]), "r"(b[1]));
}

/* swizzled byte offset inside a 128(BN)x32-bf16 tile: 64B rows, 16B chunks */
__device__ __forceinline__ int swzt(int row, int ch) {
    return (row << 6) + ((ch ^ ((row >> 1) & 3)) << 4);
}

__device__ __forceinline__ void splitw(float v, __nv_bfloat16& h, __nv_bfloat16& l) {
    h = __float2bfloat16(v);
    l = __float2bfloat16(v - __bfloat162float(h));
}

/* ============ split convert: fp32 -> bf16 hi + bf16 lo (vectorized) ======= */
__global__ void split_convert(const float* __restrict__ src,
                              __nv_bfloat16* __restrict__ h,
                              __nv_bfloat16* __restrict__ l, int n4)
{
    int i = blockIdx.x * blockDim.x + threadIdx.x;
    if (i >= n4) return;
    float4 v = ((const float4*)src)[i];
    __nv_bfloat16 h0, h1, h2, h3, l0, l1, l2, l3;
    splitw(v.x, h0, l0); splitw(v.y, h1, l1);
    splitw(v.z, h2, l2); splitw(v.w, h3, l3);
    uint2 hv, lv;
    hv.x = (uint32_t)__bfloat16_as_ushort(h0) | ((uint32_t)__bfloat16_as_ushort(h1) << 16);
    hv.y = (uint32_t)__bfloat16_as_ushort(h2) | ((uint32_t)__bfloat16_as_ushort(h3) << 16);
    lv.x = (uint32_t)__bfloat16_as_ushort(l0) | ((uint32_t)__bfloat16_as_ushort(l1) << 16);
    lv.y = (uint32_t)__bfloat16_as_ushort(l2) | ((uint32_t)__bfloat16_as_ushort(l3) << 16);
    ((uint2*)h)[i] = hv;
    ((uint2*)l)[i] = lv;
}

/* ====== split-bf16 tensor-core GEMM with cp.async double buffering ======== */
/* C = (A * B^T) * oscale (+ bias).  All global lds = 1024 elements.         */
/* MODE 0: proj; 1: per-head scores; 2: attn*Vt.                              */
/* EPI 0: fp32 + bias; 1: fp32 * oscale; 2: split-bf16 + bias; 3: split-bf16 */
template<int MODE, int EPI, int BN, int WROWS, int WCOLS, int KTOT>
__global__ void __launch_bounds__(256, 2) mma_gemm(
    const __nv_bfloat16* __restrict__ Ahg, const __nv_bfloat16* __restrict__ Alg,
    const __nv_bfloat16* __restrict__ Bhg, const __nv_bfloat16* __restrict__ Blg,
    const float* __restrict__ bias, void* __restrict__ Cp, void* __restrict__ C2p,
    float oscale)
{
    constexpr int BM = 128;
    constexpr int ATB = BM * 64;          /* tile bytes per array (8KB)      */
    constexpr int BTB = BN * 64;
    constexpr int BUFS = 2 * ATB + 2 * BTB;
    constexpr int WTM = BM / WROWS, WTN = BN / WCOLS;
    constexpr int FM = WTM / 16, FN = WTN / 8;
    constexpr int NIT = KTOT / 32;

    extern __shared__ char sm[];
    uint32_t smb = smem_u32(sm);

    int tid = threadIdx.x;
    int lane = tid & 31, wid = tid >> 5;
    int wrow = wid / WCOLS, wcol = wid % WCOLS;
    int m0 = wrow * WTM, n0 = wcol * WTN;
    int gid = lane >> 2, tig = lane & 3;

    size_t offA = 0, offB = 0, offC = 0;
    if (MODE == 1) {
        int z = blockIdx.z;
        size_t ho = (size_t)(z >> 4) * S_ * E_ + (size_t)(z & 15) * HD_;
        offA = ho; offB = ho; offC = (size_t)z * S_ * S_;
    } else if (MODE == 2) {
        int z = blockIdx.z;
        offA = (size_t)z * S_ * S_;
        offB = (size_t)z * HD_ * S_;
        offC = (size_t)(z >> 4) * S_ * E_ + (size_t)(z & 15) * HD_;
    }
    const char* A8h = (const char*)(Ahg + offA + (size_t)blockIdx.y * BM * 1024);
    const char* A8l = (const char*)(Alg + offA + (size_t)blockIdx.y * BM * 1024);
    const char* B8h = (const char*)(Bhg + offB + (size_t)blockIdx.x * BN * 1024);
    const char* B8l = (const char*)(Blg + offB + (size_t)blockIdx.x * BN * 1024);

    auto fill = [&](int bf, int k0) {
        size_t kb = (size_t)k0 * 2;
        uint32_t base = smb + bf * BUFS;
#pragma unroll
        for (int i = tid; i < BM * 4; i += 256) {
            int r = i >> 2, ch = i & 3;
            size_t so = (size_t)r * 2048 + kb + ch * 16;
            CP16(base + swzt(r, ch), A8h + so);
            CP16(base + ATB + swzt(r, ch), A8l + so);
        }
#pragma unroll
        for (int i = tid; i < BN * 4; i += 256) {
            int r = i >> 2, ch = i & 3;
            size_t so = (size_t)r * 2048 + kb + ch * 16;
            CP16(base + 2 * ATB + swzt(r, ch), B8h + so);
            CP16(base + 2 * ATB + BTB + swzt(r, ch), B8l + so);
        }
    };

    float acc[FM][FN][4];
#pragma unroll
    for (int i = 0; i < FM; i++)
#pragma unroll
        for (int j = 0; j < FN; j++)
#pragma unroll
            for (int u = 0; u < 4; u++) acc[i][j][u] = 0.f;

    fill(0, 0);
    CP_COMMIT();
    int buf = 0;
    for (int it = 0; it < NIT; ++it) {
        if (it + 1 < NIT) {
            fill(buf ^ 1, (it + 1) * 32);
            CP_COMMIT();
            CP_WAIT1();
        } else {
            CP_WAIT0();
        }
        __syncthreads();
        const char* pAh = sm + buf * BUFS;
        const char* pAl = pAh + ATB;
        const char* pBh = pAh + 2 * ATB;
        const char* pBl = pBh + BTB;
#pragma unroll
        for (int ks = 0; ks < 2; ks++) {
            uint32_t bhf[FN][2], blf[FN][2];
#pragma unroll
            for (int fn = 0; fn < FN; fn++) {
                int br = n0 + fn * 8 + gid;
                int o0 = swzt(br, ks * 2) + tig * 4;
                int o1 = swzt(br, ks * 2 + 1) + tig * 4;
                bhf[fn][0] = *(const uint32_t*)(pBh + o0);
                bhf[fn][1] = *(const uint32_t*)(pBh + o1);
                blf[fn][0] = *(const uint32_t*)(pBl + o0);
                blf[fn][1] = *(const uint32_t*)(pBl + o1);
            }
#pragma unroll
            for (int fm = 0; fm < FM; fm++) {
                int ar0 = m0 + fm * 16 + gid, ar8 = ar0 + 8;
                int o00 = swzt(ar0, ks * 2) + tig * 4;
                int o80 = swzt(ar8, ks * 2) + tig * 4;
                int o01 = swzt(ar0, ks * 2 + 1) + tig * 4;
                int o81 = swzt(ar8, ks * 2 + 1) + tig * 4;
                uint32_t ahf[4], alf[4];
                ahf[0] = *(const uint32_t*)(pAh + o00);
                ahf[1] = *(const uint32_t*)(pAh + o80);
                ahf[2] = *(const uint32_t*)(pAh + o01);
                ahf[3] = *(const uint32_t*)(pAh + o81);
                alf[0] = *(const uint32_t*)(pAl + o00);
                alf[1] = *(const uint32_t*)(pAl + o80);
                alf[2] = *(const uint32_t*)(pAl + o01);
                alf[3] = *(const uint32_t*)(pAl + o81);
#pragma unroll
                for (int fn = 0; fn < FN; fn++) {
                    mma16816(acc[fm][fn], ahf, bhf[fn]);
                    mma16816(acc[fm][fn], ahf, blf[fn]);
                    mma16816(acc[fm][fn], alf, bhf[fn]);
                }
            }
        }
        __syncthreads();
        buf ^= 1;
    }

    /* epilogue */
#pragma unroll
    for (int fm = 0; fm < FM; fm++) {
        size_t r0 = (size_t)blockIdx.y * BM + m0 + fm * 16 + gid;
#pragma unroll
        for (int fn = 0; fn < FN; fn++) {
            int cgl = blockIdx.x * BN + n0 + fn * 8 + tig * 2;
            float b0 = 0.f, b1 = 0.f;
            if (EPI == 0 || EPI == 2) { b0 = bias[cgl]; b1 = bias[cgl + 1]; }
            float v00 = acc[fm][fn][0] * oscale + b0;
            float v01 = acc[fm][fn][1] * oscale + b1;
            float v10 = acc[fm][fn][2] * oscale + b0;
            float v11 = acc[fm][fn][3] * oscale + b1;
            if (EPI <= 1) {
                float* C = (float*)Cp;
                *(float2*)&C[offC + r0 * 1024 + cgl] = make_float2(v00, v01);
                *(float2*)&C[offC + (r0 + 8) * 1024 + cgl] = make_float2(v10, v11);
            } else {
                __nv_bfloat16* Ch = (__nv_bfloat16*)Cp;
                __nv_bfloat16* Cl = (__nv_bfloat16*)C2p;
                __nv_bfloat16 h00, h01, h10, h11, l00, l01, l10, l11;
                splitw(v00, h00, l00); splitw(v01, h01, l01);
                splitw(v10, h10, l10); splitw(v11, h11, l11);
                uint32_t hv0 = (uint32_t)__bfloat16_as_ushort(h00) | ((uint32_t)__bfloat16_as_ushort(h01) << 16);
                uint32_t lv0 = (uint32_t)__bfloat16_as_ushort(l00) | ((uint32_t)__bfloat16_as_ushort(l01) << 16);
                uint32_t hv1 = (uint32_t)__bfloat16_as_ushort(h10) | ((uint32_t)__bfloat16_as_ushort(h11) << 16);
                uint32_t lv1 = (uint32_t)__bfloat16_as_ushort(l10) | ((uint32_t)__bfloat16_as_ushort(l11) << 16);
                *(uint32_t*)&Ch[offC + r0 * 1024 + cgl] = hv0;
                *(uint32_t*)&Cl[offC + r0 * 1024 + cgl] = lv0;
                *(uint32_t*)&Ch[offC + (r0 + 8) * 1024 + cgl] = hv1;
                *(uint32_t*)&Cl[offC + (r0 + 8) * 1024 + cgl] = lv1;
            }
        }
    }
}

/* ===== Vt[z][d][k] = V[b][k][h*64+d], written split-bf16 ================== */
__global__ void transpose_v(const float* __restrict__ V,
                            __nv_bfloat16* __restrict__ Vth,
                            __nv_bfloat16* __restrict__ Vtl)
{
    __shared__ float tile[32][33];
    int z = blockIdx.z;
    int b = z >> 4, h = z & 15;
    int k0 = blockIdx.x * 32, d0 = blockIdx.y * 32;
    int tx = threadIdx.x, ty = threadIdx.y;
#pragma unroll
    for (int i = 0; i < 4; i++)
        tile[ty + i * 8][tx] =
            V[((size_t)b * S_ + k0 + ty + i * 8) * E_ + h * HD_ + d0 + tx];
    __syncthreads();
#pragma unroll
    for (int i = 0; i < 4; i++) {
        float v = tile[tx][ty + i * 8];
        __nv_bfloat16 hh, ll;
        splitw(v, hh, ll);
        size_t o = ((size_t)z * HD_ + d0 + ty + i * 8) * S_ + k0 + tx;
        Vth[o] = hh;
        Vtl[o] = ll;
    }
}

/* ===================== twiddle init ======================================= */
__global__ void init_twiddles(float2* tw)
{
    int j = blockIdx.x * blockDim.x + threadIdx.x;
    if (j < 1024) {
        float ang = -6.28318530717958647692f * (float)j / 1024.0f;
        tw[j] = make_float2(cosf(ang), sinf(ang));
    }
}

/* ===================== complex helpers ==================================== */
__device__ __forceinline__ float2 cadd(float2 a, float2 b) { return make_float2(a.x + b.x, a.y + b.y); }
__device__ __forceinline__ float2 csub(float2 a, float2 b) { return make_float2(a.x - b.x, a.y - b.y); }
__device__ __forceinline__ float2 cmul(float2 a, float2 b) { return make_float2(a.x * b.x - a.y * b.y, a.x * b.y + a.y * b.x); }
__device__ __forceinline__ float2 cmulc(float2 a, float2 b) { return make_float2(a.x * b.x + a.y * b.y, a.y * b.x - a.x * b.y); }

__device__ __forceinline__ int padi(int i) { return i + (i >> 4); }
__device__ __forceinline__ int dr4(int k)
{
    return ((k & 3) << 8) | (((k >> 2) & 3) << 6) | (((k >> 4) & 3) << 4)
         | (((k >> 6) & 3) << 2) | ((k >> 8) & 3);
}

__device__ __forceinline__ void fft4_fwd(float2* s, const float2* tw, int t)
{
#pragma unroll
    for (int ln = 10; ln >= 2; ln -= 2) {
        int q4 = 1 << (ln - 2);
        int j = t & (q4 - 1);
        int i = ((t >> (ln - 2)) << ln) + j;
        int tj = j << (10 - ln);
        float2 w1 = tw[tj], w2 = tw[2 * tj], w3 = tw[3 * tj];
        float2 a = s[padi(i)], b = s[padi(i + q4)];
        float2 c = s[padi(i + 2 * q4)], d = s[padi(i + 3 * q4)];
        float2 t0 = cadd(a, c), t1 = csub(a, c), t2 = cadd(b, d);
        float2 bd = csub(b, d);
        float2 t3 = make_float2(bd.y, -bd.x);
        s[padi(i)]          = cadd(t0, t2);
        s[padi(i + q4)]     = cmul(cadd(t1, t3), w1);
        s[padi(i + 2 * q4)] = cmul(csub(t0, t2), w2);
        s[padi(i + 3 * q4)] = cmul(csub(t1, t3), w3);
        __syncthreads();
    }
}

__device__ __forceinline__ void fft4_inv(float2* s, const float2* tw, int t)
{
#pragma unroll
    for (int ln = 2; ln <= 10; ln += 2) {
        int q4 = 1 << (ln - 2);
        int j = t & (q4 - 1);
        int i = ((t >> (ln - 2)) << ln) + j;
        int tj = j << (10 - ln);
        float2 w1 = tw[tj], w2 = tw[2 * tj], w3 = tw[3 * tj];
        float2 a = s[padi(i)];
        float2 b = cmulc(s[padi(i + q4)], w1);
        float2 c = cmulc(s[padi(i + 2 * q4)], w2);
        float2 d = cmulc(s[padi(i + 3 * q4)], w3);
        float2 t0 = cadd(a, c), t1 = csub(a, c), t2 = cadd(b, d);
        float2 bd = csub(b, d);
        float2 t3 = make_float2(-bd.y, bd.x);
        s[padi(i)]          = cadd(t0, t2);
        s[padi(i + q4)]     = cadd(t1, t3);
        s[padi(i + 2 * q4)] = csub(t0, t2);
        s[padi(i + 3 * q4)] = csub(t1, t3);
        __syncthreads();
    }
}

/* ======== pass 1: 2 packed real rows -> one FFT -> half spectra =========== */
__global__ void __launch_bounds__(256) fft_rows_fwd2(
    const float* __restrict__ in, float2* __restrict__ Y,
    const float2* __restrict__ twg)
{
    __shared__ float2 s[1088];
    __shared__ float2 tw[1024];
    int t = threadIdx.x;
    const float* r0 = in + (size_t)blockIdx.x * 2048;
    const float* r1 = r0 + 1024;
#pragma unroll
    for (int i = t; i < 1024; i += 256) tw[i] = twg[i];
#pragma unroll
    for (int i = t; i < 1024; i += 256)
        s[padi(i)] = make_float2(r0[i], r1[i]);
    __syncthreads();
    fft4_fwd(s, tw, t);
    float2* y0 = Y + (size_t)(2 * blockIdx.x) * KP;
    float2* y1 = y0 + KP;
    for (int k = t; k < 513; k += 256) {
        float2 Zk = s[padi(dr4(k))];
        float2 Zm = s[padi(dr4((1024 - k) & 1023))];
        y0[k] = make_float2(0.5f * (Zk.x + Zm.x), 0.5f * (Zk.y - Zm.y));
        y1[k] = make_float2(0.5f * (Zk.y + Zm.y), 0.5f * (Zm.x - Zk.x));
    }
}

/* ===== pass 2: col FFT (q) + real cos-filter + col IFFT, 8-col slabs ====== */
__global__ void __launch_bounds__(512) fft_cols_filter2(
    float2* __restrict__ Y, const float* __restrict__ alpha_p,
    const float2* __restrict__ twg)
{
    extern __shared__ float2 cs[];
    int z = blockIdx.y;
    int k0 = blockIdx.x * SLAB;
    float2* base = Y + (size_t)z * S_ * KP + k0;
    int t = threadIdx.x;
    int c = t & 7, b0 = t >> 3;

    for (int idx = t; idx < 1024 * SLAB; idx += 512) {
        int q = idx >> 3, cc = idx & 7;
        cs[q * SLDS + cc] = base[(size_t)q * KP + cc];
    }
    __syncthreads();
#pragma unroll
    for (int ln = 10; ln >= 2; ln -= 2) {
        int q4 = 1 << (ln - 2);
#pragma unroll
        for (int m = 0; m < 4; m++) {
            int bf = b0 + (m << 6);
            int j = bf & (q4 - 1);
            int i = ((bf >> (ln - 2)) << ln) + j;
            int tj = j << (10 - ln);
            float2 w1 = twg[tj], w2 = twg[2 * tj], w3 = twg[3 * tj];
            int i0 = i * SLDS + c, i1 = (i + q4) * SLDS + c;
            int i2 = (i + 2 * q4) * SLDS + c, i3 = (i + 3 * q4) * SLDS + c;
            float2 a = cs[i0], b = cs[i1], cc2 = cs[i2], d = cs[i3];
            float2 t0 = cadd(a, cc2), t1 = csub(a, cc2), t2 = cadd(b, d);
            float2 bd = csub(b, d);
            float2 t3 = make_float2(bd.y, -bd.x);
            cs[i0] = cadd(t0, t2);
            cs[i1] = cmul(cadd(t1, t3), w1);
            cs[i2] = cmul(csub(t0, t2), w2);
            cs[i3] = cmul(csub(t1, t3), w3);
        }
        __syncthreads();
    }
    float alpha = *alpha_p;
    for (int idx = t; idx < 1024 * SLAB; idx += 512) {
        int q = idx >> 3, cc = idx & 7;
        float2 v = cs[q * SLDS + cc];
        float mag = sqrtf(v.x * v.x + v.y * v.y);
        float g = cosf(alpha * atanf(__logf(mag + 1e-10f)));
        cs[q * SLDS + cc] = make_float2(v.x * g, v.y * g);
    }
    __syncthreads();
#pragma unroll
    for (int ln = 2; ln <= 10; ln += 2) {
        int q4 = 1 << (ln - 2);
#pragma unroll
        for (int m = 0; m < 4; m++) {
            int bf = b0 + (m << 6);
            int j = bf & (q4 - 1);
            int i = ((bf >> (ln - 2)) << ln) + j;
            int tj = j << (10 - ln);
            float2 w1 = twg[tj], w2 = twg[2 * tj], w3 = twg[3 * tj];
            int i0 = i * SLDS + c, i1 = (i + q4) * SLDS + c;
            int i2 = (i + 2 * q4) * SLDS + c, i3 = (i + 3 * q4) * SLDS + c;
            float2 a = cs[i0];
            float2 b = cmulc(cs[i1], w1);
            float2 cc2 = cmulc(cs[i2], w2);
            float2 d = cmulc(cs[i3], w3);
            float2 t0 = cadd(a, cc2), t1 = csub(a, cc2), t2 = cadd(b, d);
            float2 bd = csub(b, d);
            float2 t3 = make_float2(-bd.y, bd.x);
            cs[i0] = cadd(t0, t2);
            cs[i1] = cadd(t1, t3);
            cs[i2] = csub(t0, t2);
            cs[i3] = csub(t1, t3);
        }
        __syncthreads();
    }
    const float scl = 1.0f / 1024.0f;
    for (int idx = t; idx < 1024 * SLAB; idx += 512) {
        int q = idx >> 3, cc = idx & 7;
        float2 v = cs[q * SLDS + cc];
        base[(size_t)q * KP + cc] = make_float2(v.x * scl, v.y * scl);
    }
}

/* = pass 3: c2r inverse + fused softmax, attn written split-bf16 =========== */
__global__ void __launch_bounds__(256) fft_rows_inv_softmax2(
    const float2* __restrict__ Y,
    __nv_bfloat16* __restrict__ outh, __nv_bfloat16* __restrict__ outl,
    const float2* __restrict__ twg)
{
    __shared__ float2 s[1088];
    __shared__ float2 tw[1024];
    __shared__ float2 wred[8];
    int t = threadIdx.x;
    const float2* y0 = Y + (size_t)(2 * blockIdx.x) * KP;
    const float2* y1 = y0 + KP;
#pragma unroll
    for (int i = t; i < 1024; i += 256) tw[i] = twg[i];
    for (int k = t; k < 513; k += 256) {
        float2 h0 = y0[k], h1 = y1[k];
        s[padi(dr4(k))] = make_float2(h0.x - h1.y, h0.y + h1.x);
        if (k >= 1 && k <= 511)
            s[padi(dr4(1024 - k))] = make_float2(h0.x + h1.y, h1.x - h0.y);
    }
    __syncthreads();
    fft4_inv(s, tw, t);
    const float scl = 1.0f / 1024.0f;
    float v0[4], v1[4];
    float m0 = -1e30f, m1 = -1e30f;
#pragma unroll
    for (int u = 0; u < 4; u++) {
        float2 x = s[padi(t + 256 * u)];
        v0[u] = x.x * scl; v1[u] = x.y * scl;
        m0 = fmaxf(m0, v0[u]); m1 = fmaxf(m1, v1[u]);
    }
#pragma unroll
    for (int o = 16; o; o >>= 1) {
        m0 = fmaxf(m0, __shfl_xor_sync(0xffffffffu, m0, o));
        m1 = fmaxf(m1, __shfl_xor_sync(0xffffffffu, m1, o));
    }
    if ((t & 31) == 0) wred[t >> 5] = make_float2(m0, m1);
    __syncthreads();
    float2 mm = wred[0];
#pragma unroll
    for (int w = 1; w < 8; w++) { mm.x = fmaxf(mm.x, wred[w].x); mm.y = fmaxf(mm.y, wred[w].y); }
    float p0[4], p1[4], s0 = 0.f, s1 = 0.f;
#pragma unroll
    for (int u = 0; u < 4; u++) {
        p0[u] = __expf(v0[u] - mm.x); p1[u] = __expf(v1[u] - mm.y);
        s0 += p0[u]; s1 += p1[u];
    }
#pragma unroll
    for (int o = 16; o; o >>= 1) {
        s0 += __shfl_xor_sync(0xffffffffu, s0, o);
        s1 += __shfl_xor_sync(0xffffffffu, s1, o);
    }
    __syncthreads();
    if ((t & 31) == 0) wred[t >> 5] = make_float2(s0, s1);
    __syncthreads();
    float2 ss = wred[0];
#pragma unroll
    for (int w = 1; w < 8; w++) { ss.x += wred[w].x; ss.y += wred[w].y; }
    float inv0 = 1.0f / ss.x, inv1 = 1.0f / ss.y;
    size_t rb = (size_t)(2 * blockIdx.x) * 1024;
#pragma unroll
    for (int u = 0; u < 4; u++) {
        float a0 = p0[u] * inv0, a1 = p1[u] * inv1;
        __nv_bfloat16 h, l;
        splitw(a0, h, l);
        outh[rb + t + 256 * u] = h;
        outl[rb + t + 256 * u] = l;
        splitw(a1, h, l);
        outh[rb + 1024 + t + 256 * u] = h;
        outl[rb + 1024 + t + 256 * u] = l;
    }
}

/* ============================== launcher =================================== */
extern "C" void kernel_launch(void* const* d_in, const int* in_sizes, int n_in,
                              void* d_out, int out_size)
{
    const float* query = (const float*)d_in[0];
    const float* Wq    = (const float*)d_in[1];
    const float* bq    = (const float*)d_in[2];
    const float* Wk    = (const float*)d_in[3];
    const float* bk    = (const float*)d_in[4];
    const float* Wv    = (const float*)d_in[5];
    const float* bv    = (const float*)d_in[6];
    const float* Wo    = (const float*)d_in[7];
    const float* bo    = (const float*)d_in[8];
    const float* alpha = (const float*)d_in[9];
    float* out = (float*)d_out;

    __nv_bfloat16 *pqh, *pql, *pWqh, *pWql, *pWkh, *pWkl, *pWvh, *pWvl, *pWoh, *pWol;
    __nv_bfloat16 *pQh, *pQl, *pKh, *pKl, *pVth, *pVtl, *pah, *pal, *pch, *pcl;
    float *pV, *pSc;
    float2 *pFreq, *pTw;
    cudaGetSymbolAddress((void**)&pqh, g_qh);   cudaGetSymbolAddress((void**)&pql, g_ql);
    cudaGetSymbolAddress((void**)&pWqh, g_Wqh); cudaGetSymbolAddress((void**)&pWql, g_Wql);
    cudaGetSymbolAddress((void**)&pWkh, g_Wkh); cudaGetSymbolAddress((void**)&pWkl, g_Wkl);
    cudaGetSymbolAddress((void**)&pWvh, g_Wvh); cudaGetSymbolAddress((void**)&pWvl, g_Wvl);
    cudaGetSymbolAddress((void**)&pWoh, g_Woh); cudaGetSymbolAddress((void**)&pWol, g_Wol);
    cudaGetSymbolAddress((void**)&pQh, g_Qh);   cudaGetSymbolAddress((void**)&pQl, g_Ql);
    cudaGetSymbolAddress((void**)&pKh, g_Kh);   cudaGetSymbolAddress((void**)&pKl, g_Kl);
    cudaGetSymbolAddress((void**)&pVth, g_Vth); cudaGetSymbolAddress((void**)&pVtl, g_Vtl);
    cudaGetSymbolAddress((void**)&pah, g_ah);   cudaGetSymbolAddress((void**)&pal, g_al);
    cudaGetSymbolAddress((void**)&pch, g_ch);   cudaGetSymbolAddress((void**)&pcl, g_cl);
    cudaGetSymbolAddress((void**)&pV, g_V);
    cudaGetSymbolAddress((void**)&pSc, g_scores);
    cudaGetSymbolAddress((void**)&pFreq, g_freq);
    cudaGetSymbolAddress((void**)&pTw, g_tw);

    const int SM_P = 2 * (2 * 8192 + 2 * 8192);   /* BN=128: 65536 */
    const int SM_A = 2 * (2 * 8192 + 2 * 4096);   /* BN=64:  49152 */
    cudaFuncSetAttribute((const void*)mma_gemm<0, 2, 128, 2, 4, 1024>,
                         cudaFuncAttributeMaxDynamicSharedMemorySize, SM_P);
    cudaFuncSetAttribute((const void*)mma_gemm<0, 0, 128, 2, 4, 1024>,
                         cudaFuncAttributeMaxDynamicSharedMemorySize, SM_P);
    cudaFuncSetAttribute((const void*)mma_gemm<1, 1, 128, 2, 4, 64>,
                         cudaFuncAttributeMaxDynamicSharedMemorySize, SM_P);
    cudaFuncSetAttribute((const void*)mma_gemm<2, 3, 64, 4, 2, 1024>,
                         cudaFuncAttributeMaxDynamicSharedMemorySize, SM_A);
    size_t col_smem = (size_t)1024 * SLDS * sizeof(float2);
    cudaFuncSetAttribute(fft_cols_filter2,
                         cudaFuncAttributeMaxDynamicSharedMemorySize,
                         (int)col_smem);

    init_twiddles<<<4, 256>>>(pTw);

    split_convert<<<(int)(NELEM / 4 / 256), 256>>>(query, pqh, pql, (int)(NELEM / 4));
    split_convert<<<E_ * E_ / 4 / 256, 256>>>(Wq, pWqh, pWql, E_ * E_ / 4);
    split_convert<<<E_ * E_ / 4 / 256, 256>>>(Wk, pWkh, pWkl, E_ * E_ / 4);
    split_convert<<<E_ * E_ / 4 / 256, 256>>>(Wv, pWvh, pWvl, E_ * E_ / 4);
    split_convert<<<E_ * E_ / 4 / 256, 256>>>(Wo, pWoh, pWol, E_ * E_ / 4);

    dim3 gp(E_ / 128, (B_ * S_) / 128, 1);        /* (8, 32) */
    mma_gemm<0, 2, 128, 2, 4, 1024><<<gp, 256, SM_P>>>(pqh, pql, pWqh, pWql, bq, pQh, pQl, 1.0f);
    mma_gemm<0, 2, 128, 2, 4, 1024><<<gp, 256, SM_P>>>(pqh, pql, pWkh, pWkl, bk, pKh, pKl, 1.0f);
    mma_gemm<0, 0, 128, 2, 4, 1024><<<gp, 256, SM_P>>>(pqh, pql, pWvh, pWvl, bv, pV, 0, 1.0f);

    transpose_v<<<dim3(32, 2, NBH), dim3(32, 8)>>>(pV, pVth, pVtl);

    dim3 gs(S_ / 128, S_ / 128, NBH);             /* (8, 8, 64) */
    mma_gemm<1, 1, 128, 2, 4, 64><<<gs, 256, SM_P>>>(pQh, pQl, pKh, pKl, 0, pSc, 0, 0.125f);

    fft_rows_fwd2<<<NBH * S_ / 2, 256>>>(pSc, pFreq, pTw);

    dim3 gc(65, NBH);
    fft_cols_filter2<<<gc, 512, col_smem>>>(pFreq, alpha, pTw);

    fft_rows_inv_softmax2<<<NBH * S_ / 2, 256>>>(pFreq, pah, pal, pTw);

    dim3 ga(1, S_ / 128, NBH);                    /* (1, 8, 64) */
    mma_gemm<2, 3, 64, 4, 2, 1024><<<ga, 256, SM_A>>>(pah, pal, pVth, pVtl, 0, pch, pcl, 1.0f);

    mma_gemm<0, 0, 128, 2, 4, 1024><<<gp, 256, SM_P>>>(pch, pcl, pWoh, pWol, bo, out, 0, 1.0f);
}

// round 6
// speedup vs baseline: 3.8824x; 1.4751x over previous
#include <cuda_runtime.h>
#include <cuda_bf16.h>
#include <math.h>
#include <stdint.h>

#define B_   4
#define S_   1024
#define E_   1024
#define H_   16
#define HD_  64
#define NBH  64          /* B*H */
#define KP   528         /* padded half-spectrum width (>=513, 16-mult) */
#define NELEM ((size_t)B_ * S_ * E_)   /* 4M */

/* ---------------- scratch (device globals: no allocations allowed) -------- */
__device__ __nv_bfloat16 g_qh[NELEM],  g_ql[NELEM];
__device__ __nv_bfloat16 g_Wqh[E_*E_], g_Wql[E_*E_];
__device__ __nv_bfloat16 g_Wkh[E_*E_], g_Wkl[E_*E_];
__device__ __nv_bfloat16 g_Wvh[E_*E_], g_Wvl[E_*E_];
__device__ __nv_bfloat16 g_Woh[E_*E_], g_Wol[E_*E_];
__device__ __nv_bfloat16 g_Qh[NELEM],  g_Ql[NELEM];
__device__ __nv_bfloat16 g_Kh[NELEM],  g_Kl[NELEM];
__device__ float         g_V[NELEM];
__device__ __nv_bfloat16 g_Vth[NELEM], g_Vtl[NELEM];
__device__ float         g_scores[(size_t)NBH * S_ * S_];
__device__ __nv_bfloat16 g_ah[(size_t)NBH * S_ * S_];
__device__ __nv_bfloat16 g_al[(size_t)NBH * S_ * S_];
__device__ __nv_bfloat16 g_ch[NELEM],  g_cl[NELEM];
__device__ float2 g_freq[(size_t)NBH * S_ * KP];
__device__ float2 g_tw[1024];

/* ======================= small helpers ==================================== */
__device__ __forceinline__ uint32_t smem_u32(const void* p) {
    uint32_t a;
    asm("{ .reg .u64 t; cvta.to.shared.u64 t, %1; cvt.u32.u64 %0, t; }"
        : "=r"(a) : "l"(p));
    return a;
}
#define CP16(dst, src) \
    asm volatile("cp.async.cg.shared.global [%0], [%1], 16;" \
                 :: "r"(dst), "l"(src))
#define CP_COMMIT() asm volatile("cp.async.commit_group;" ::: "memory")
#define CP_WAIT1()  asm volatile("cp.async.wait_group 1;" ::: "memory")
#define CP_WAIT0()  asm volatile("cp.async.wait_group 0;" ::: "memory")

__device__ __forceinline__ void mma16816(float* d, const uint32_t* a, const uint32_t* b)
{
    asm volatile(
        "mma.sync.aligned.m16n8k16.row.col.f32.bf16.bf16.f32 "
        "{%0,%1,%2,%3}, {%4,%5,%6,%7}, {%8,%9}, {%0,%1,%2,%3};"
        : "+f"(d[0]), "+f"(d[1]), "+f"(d[2]), "+f"(d[3])
        : "r"(a[0]), "r"(a[1]), "r"(a[2]), "r"(a[3]), "r"(b[0]), "r"(b[1]));
}

__device__ __forceinline__ int swzt(int row, int ch) {
    return (row << 6) + ((ch ^ ((row >> 1) & 3)) << 4);
}

__device__ __forceinline__ void splitw(float v, __nv_bfloat16& h, __nv_bfloat16& l) {
    h = __float2bfloat16(v);
    l = __float2bfloat16(v - __bfloat162float(h));
}

__device__ __forceinline__ float2 cmul(float2 a, float2 b) {
    return make_float2(a.x * b.x - a.y * b.y, a.x * b.y + a.y * b.x);
}
__device__ __forceinline__ float2 cmulc(float2 a, float2 b) {
    return make_float2(a.x * b.x + a.y * b.y, a.y * b.x - a.x * b.y);
}

/* ============ split convert: fp32 -> bf16 hi + bf16 lo (vectorized) ======= */
__global__ void split_convert(const float* __restrict__ src,
                              __nv_bfloat16* __restrict__ h,
                              __nv_bfloat16* __restrict__ l, int n4)
{
    int i = blockIdx.x * blockDim.x + threadIdx.x;
    if (i >= n4) return;
    float4 v = ((const float4*)src)[i];
    __nv_bfloat16 h0, h1, h2, h3, l0, l1, l2, l3;
    splitw(v.x, h0, l0); splitw(v.y, h1, l1);
    splitw(v.z, h2, l2); splitw(v.w, h3, l3);
    uint2 hv, lv;
    hv.x = (uint32_t)__bfloat16_as_ushort(h0) | ((uint32_t)__bfloat16_as_ushort(h1) << 16);
    hv.y = (uint32_t)__bfloat16_as_ushort(h2) | ((uint32_t)__bfloat16_as_ushort(h3) << 16);
    lv.x = (uint32_t)__bfloat16_as_ushort(l0) | ((uint32_t)__bfloat16_as_ushort(l1) << 16);
    lv.y = (uint32_t)__bfloat16_as_ushort(l2) | ((uint32_t)__bfloat16_as_ushort(l3) << 16);
    ((uint2*)h)[i] = hv;
    ((uint2*)l)[i] = lv;
}

/* ====== split-bf16 tensor-core GEMM with cp.async double buffering ======== */
template<int MODE, int EPI, int BN, int WROWS, int WCOLS, int KTOT>
__global__ void __launch_bounds__(256, 2) mma_gemm(
    const __nv_bfloat16* __restrict__ Ahg, const __nv_bfloat16* __restrict__ Alg,
    const __nv_bfloat16* __restrict__ Bhg, const __nv_bfloat16* __restrict__ Blg,
    const float* __restrict__ bias, void* __restrict__ Cp, void* __restrict__ C2p,
    float oscale)
{
    constexpr int BM = 128;
    constexpr int ATB = BM * 64;
    constexpr int BTB = BN * 64;
    constexpr int BUFS = 2 * ATB + 2 * BTB;
    constexpr int WTM = BM / WROWS, WTN = BN / WCOLS;
    constexpr int FM = WTM / 16, FN = WTN / 8;
    constexpr int NIT = KTOT / 32;

    extern __shared__ char sm[];
    uint32_t smb = smem_u32(sm);

    int tid = threadIdx.x;
    int lane = tid & 31, wid = tid >> 5;
    int wrow = wid / WCOLS, wcol = wid % WCOLS;
    int m0 = wrow * WTM, n0 = wcol * WTN;
    int gid = lane >> 2, tig = lane & 3;

    size_t offA = 0, offB = 0, offC = 0;
    if (MODE == 1) {
        int z = blockIdx.z;
        size_t ho = (size_t)(z >> 4) * S_ * E_ + (size_t)(z & 15) * HD_;
        offA = ho; offB = ho; offC = (size_t)z * S_ * S_;
    } else if (MODE == 2) {
        int z = blockIdx.z;
        offA = (size_t)z * S_ * S_;
        offB = (size_t)z * HD_ * S_;
        offC = (size_t)(z >> 4) * S_ * E_ + (size_t)(z & 15) * HD_;
    }
    const char* A8h = (const char*)(Ahg + offA + (size_t)blockIdx.y * BM * 1024);
    const char* A8l = (const char*)(Alg + offA + (size_t)blockIdx.y * BM * 1024);
    const char* B8h = (const char*)(Bhg + offB + (size_t)blockIdx.x * BN * 1024);
    const char* B8l = (const char*)(Blg + offB + (size_t)blockIdx.x * BN * 1024);

    auto fill = [&](int bf, int k0) {
        size_t kb = (size_t)k0 * 2;
        uint32_t base = smb + bf * BUFS;
#pragma unroll
        for (int i = tid; i < BM * 4; i += 256) {
            int r = i >> 2, ch = i & 3;
            size_t so = (size_t)r * 2048 + kb + ch * 16;
            CP16(base + swzt(r, ch), A8h + so);
            CP16(base + ATB + swzt(r, ch), A8l + so);
        }
#pragma unroll
        for (int i = tid; i < BN * 4; i += 256) {
            int r = i >> 2, ch = i & 3;
            size_t so = (size_t)r * 2048 + kb + ch * 16;
            CP16(base + 2 * ATB + swzt(r, ch), B8h + so);
            CP16(base + 2 * ATB + BTB + swzt(r, ch), B8l + so);
        }
    };

    float acc[FM][FN][4];
#pragma unroll
    for (int i = 0; i < FM; i++)
#pragma unroll
        for (int j = 0; j < FN; j++)
#pragma unroll
            for (int u = 0; u < 4; u++) acc[i][j][u] = 0.f;

    fill(0, 0);
    CP_COMMIT();
    int buf = 0;
    for (int it = 0; it < NIT; ++it) {
        if (it + 1 < NIT) {
            fill(buf ^ 1, (it + 1) * 32);
            CP_COMMIT();
            CP_WAIT1();
        } else {
            CP_WAIT0();
        }
        __syncthreads();
        const char* pAh = sm + buf * BUFS;
        const char* pAl = pAh + ATB;
        const char* pBh = pAh + 2 * ATB;
        const char* pBl = pBh + BTB;
#pragma unroll
        for (int ks = 0; ks < 2; ks++) {
            uint32_t bhf[FN][2], blf[FN][2];
#pragma unroll
            for (int fn = 0; fn < FN; fn++) {
                int br = n0 + fn * 8 + gid;
                int o0 = swzt(br, ks * 2) + tig * 4;
                int o1 = swzt(br, ks * 2 + 1) + tig * 4;
                bhf[fn][0] = *(const uint32_t*)(pBh + o0);
                bhf[fn][1] = *(const uint32_t*)(pBh + o1);
                blf[fn][0] = *(const uint32_t*)(pBl + o0);
                blf[fn][1] = *(const uint32_t*)(pBl + o1);
            }
#pragma unroll
            for (int fm = 0; fm < FM; fm++) {
                int ar0 = m0 + fm * 16 + gid, ar8 = ar0 + 8;
                int o00 = swzt(ar0, ks * 2) + tig * 4;
                int o80 = swzt(ar8, ks * 2) + tig * 4;
                int o01 = swzt(ar0, ks * 2 + 1) + tig * 4;
                int o81 = swzt(ar8, ks * 2 + 1) + tig * 4;
                uint32_t ahf[4], alf[4];
                ahf[0] = *(const uint32_t*)(pAh + o00);
                ahf[1] = *(const uint32_t*)(pAh + o80);
                ahf[2] = *(const uint32_t*)(pAh + o01);
                ahf[3] = *(const uint32_t*)(pAh + o81);
                alf[0] = *(const uint32_t*)(pAl + o00);
                alf[1] = *(const uint32_t*)(pAl + o80);
                alf[2] = *(const uint32_t*)(pAl + o01);
                alf[3] = *(const uint32_t*)(pAl + o81);
#pragma unroll
                for (int fn = 0; fn < FN; fn++) {
                    mma16816(acc[fm][fn], ahf, bhf[fn]);
                    mma16816(acc[fm][fn], ahf, blf[fn]);
                    mma16816(acc[fm][fn], alf, bhf[fn]);
                }
            }
        }
        __syncthreads();
        buf ^= 1;
    }

#pragma unroll
    for (int fm = 0; fm < FM; fm++) {
        size_t r0 = (size_t)blockIdx.y * BM + m0 + fm * 16 + gid;
#pragma unroll
        for (int fn = 0; fn < FN; fn++) {
            int cgl = blockIdx.x * BN + n0 + fn * 8 + tig * 2;
            float b0 = 0.f, b1 = 0.f;
            if (EPI == 0 || EPI == 2) { b0 = bias[cgl]; b1 = bias[cgl + 1]; }
            float v00 = acc[fm][fn][0] * oscale + b0;
            float v01 = acc[fm][fn][1] * oscale + b1;
            float v10 = acc[fm][fn][2] * oscale + b0;
            float v11 = acc[fm][fn][3] * oscale + b1;
            if (EPI <= 1) {
                float* C = (float*)Cp;
                *(float2*)&C[offC + r0 * 1024 + cgl] = make_float2(v00, v01);
                *(float2*)&C[offC + (r0 + 8) * 1024 + cgl] = make_float2(v10, v11);
            } else {
                __nv_bfloat16* Ch = (__nv_bfloat16*)Cp;
                __nv_bfloat16* Cl = (__nv_bfloat16*)C2p;
                __nv_bfloat16 h00, h01, h10, h11, l00, l01, l10, l11;
                splitw(v00, h00, l00); splitw(v01, h01, l01);
                splitw(v10, h10, l10); splitw(v11, h11, l11);
                uint32_t hv0 = (uint32_t)__bfloat16_as_ushort(h00) | ((uint32_t)__bfloat16_as_ushort(h01) << 16);
                uint32_t lv0 = (uint32_t)__bfloat16_as_ushort(l00) | ((uint32_t)__bfloat16_as_ushort(l01) << 16);
                uint32_t hv1 = (uint32_t)__bfloat16_as_ushort(h10) | ((uint32_t)__bfloat16_as_ushort(h11) << 16);
                uint32_t lv1 = (uint32_t)__bfloat16_as_ushort(l10) | ((uint32_t)__bfloat16_as_ushort(l11) << 16);
                *(uint32_t*)&Ch[offC + r0 * 1024 + cgl] = hv0;
                *(uint32_t*)&Cl[offC + r0 * 1024 + cgl] = lv0;
                *(uint32_t*)&Ch[offC + (r0 + 8) * 1024 + cgl] = hv1;
                *(uint32_t*)&Cl[offC + (r0 + 8) * 1024 + cgl] = lv1;
            }
        }
    }
}

/* ===== Vt[z][d][k] = V[b][k][h*64+d], written split-bf16 ================== */
__global__ void transpose_v(const float* __restrict__ V,
                            __nv_bfloat16* __restrict__ Vth,
                            __nv_bfloat16* __restrict__ Vtl)
{
    __shared__ float tile[32][33];
    int z = blockIdx.z;
    int b = z >> 4, h = z & 15;
    int k0 = blockIdx.x * 32, d0 = blockIdx.y * 32;
    int tx = threadIdx.x, ty = threadIdx.y;
#pragma unroll
    for (int i = 0; i < 4; i++)
        tile[ty + i * 8][tx] =
            V[((size_t)b * S_ + k0 + ty + i * 8) * E_ + h * HD_ + d0 + tx];
    __syncthreads();
#pragma unroll
    for (int i = 0; i < 4; i++) {
        float v = tile[tx][ty + i * 8];
        __nv_bfloat16 hh, ll;
        splitw(v, hh, ll);
        size_t o = ((size_t)z * HD_ + d0 + ty + i * 8) * S_ + k0 + tx;
        Vth[o] = hh;
        Vtl[o] = ll;
    }
}

/* ===================== twiddle init ======================================= */
__global__ void init_twiddles(float2* tw)
{
    int j = blockIdx.x * blockDim.x + threadIdx.x;
    if (j < 1024) {
        float ang = -6.28318530717958647692f * (float)j / 1024.0f;
        tw[j] = make_float2(cosf(ang), sinf(ang));
    }
}

/* ============== in-register 32-pt FFT (DIF, natural order out) ============ */
template<bool INV>
__device__ __forceinline__ void fft32r(float2* v)
{
    const float C[16] = {
        1.f, 0.980785280403230f, 0.923879532511287f, 0.831469612302545f,
        0.707106781186548f, 0.555570233019602f, 0.382683432365090f, 0.195090322016128f,
        0.f, -0.195090322016128f, -0.382683432365090f, -0.555570233019602f,
        -0.707106781186548f, -0.831469612302545f, -0.923879532511287f, -0.980785280403230f };
    const float Sn[16] = {
        0.f, 0.195090322016128f, 0.382683432365090f, 0.555570233019602f,
        0.707106781186548f, 0.831469612302545f, 0.923879532511287f, 0.980785280403230f,
        1.f, 0.980785280403230f, 0.923879532511287f, 0.831469612302545f,
        0.707106781186548f, 0.555570233019602f, 0.382683432365090f, 0.195090322016128f };
#pragma unroll
    for (int h = 16; h >= 1; h >>= 1) {
#pragma unroll
        for (int b = 0; b < 32; b += 2 * h) {
#pragma unroll
            for (int j = 0; j < h; j++) {
                int e = j * (16 / h);
                float tc = C[e];
                float ts = INV ? Sn[e] : -Sn[e];
                float2 a = v[b + j], bb = v[b + j + h];
                v[b + j] = make_float2(a.x + bb.x, a.y + bb.y);
                float dx = a.x - bb.x, dy = a.y - bb.y;
                v[b + j + h] = make_float2(dx * tc - dy * ts, dx * ts + dy * tc);
            }
        }
    }
#pragma unroll
    for (int i = 0; i < 32; i++) {
        int r = ((i & 1) << 4) | ((i & 2) << 2) | (i & 4) | ((i & 8) >> 2) | ((i & 16) >> 4);
        if (r > i) { float2 tmp = v[i]; v[i] = v[r]; v[r] = tmp; }
    }
}

/* ====== pass 1: warp-level fwd FFT of 2 packed real rows -> half spectra == */
/* 128 threads = 4 warps = 4 packed row-pairs per CTA.                        */
__global__ void __launch_bounds__(128) fft_rows_fwd_w(
    const float* __restrict__ in, float2* __restrict__ Y,
    const float2* __restrict__ twg)
{
    __shared__ float pat[4 * 2112];
    int t = threadIdx.x & 31, w = threadIdx.x >> 5;
    float* pre = pat + w * 2112;
    float* pim = pre + 1056;
    size_t p = (size_t)blockIdx.x * 4 + w;
    const float* r0 = in + p * 2048;
    const float* r1 = r0 + 1024;

    float2 v[32];
#pragma unroll
    for (int i2 = 0; i2 < 32; i2++)
        v[i2] = make_float2(r0[t + 32 * i2], r1[t + 32 * i2]);
    fft32r<false>(v);                       /* y[k2], thread = i1 */
#pragma unroll
    for (int k2 = 1; k2 < 32; k2++)
        v[k2] = cmul(v[k2], twg[(t * k2) & 1023]);
#pragma unroll
    for (int k2 = 0; k2 < 32; k2++) {       /* transpose: pat[i1][k2] */
        pre[t * 33 + k2] = v[k2].x;
        pim[t * 33 + k2] = v[k2].y;
    }
    __syncwarp();
#pragma unroll
    for (int i1 = 0; i1 < 32; i1++)
        v[i1] = make_float2(pre[i1 * 33 + t], pim[i1 * 33 + t]);
    __syncwarp();
    fft32r<false>(v);                       /* X[t + 32*k1], thread = k2 = t */
#pragma unroll
    for (int k1 = 0; k1 < 32; k1++) {       /* natural store: pat[k1][k2] = X[k2+32k1] */
        pre[k1 * 33 + t] = v[k1].x;
        pim[k1 * 33 + t] = v[k1].y;
    }
    __syncwarp();

    float2* y0 = Y + (size_t)(2 * p) * KP;
    float2* y1 = y0 + KP;
#pragma unroll
    for (int u = 0; u <= 16; u++) {
        int k = t + 32 * u;
        if (u < 16 || t == 0) {
            int idx = u * 33 + t;
            float2 Xk = make_float2(pre[idx], pim[idx]);
            int m = (1024 - k) & 1023;
            int midx = (m >> 5) * 33 + (m & 31);
            float2 Xm = make_float2(pre[midx], pim[midx]);
            y0[k] = make_float2(0.5f * (Xk.x + Xm.x), 0.5f * (Xk.y - Xm.y));
            y1[k] = make_float2(0.5f * (Xk.y + Xm.y), 0.5f * (Xm.x - Xk.x));
        }
    }
}

/* ===== pass 2: warp-level col FFT + real cos-filter + col IFFT =========== */
/* 128 threads = 4 warps = 4 columns per CTA. smem reused slab<->patches.    */
__global__ void __launch_bounds__(128) fft_cols_w(
    float2* __restrict__ Y, const float* __restrict__ alpha_p,
    const float2* __restrict__ twg)
{
    __shared__ float sm[10240];             /* 40KB: slab 2x5120 / patches 4x2112 */
    float* slab_re = sm;
    float* slab_im = sm + 5120;
    int tid = threadIdx.x;
    int t = tid & 31, w = tid >> 5;
    int z = blockIdx.y;
    int kbase = blockIdx.x * 4;
    float2* base = Y + (size_t)z * S_ * KP + kbase;

    /* cooperative load slab (cols kbase..kbase+3; pads <528 are in-bounds) */
#pragma unroll 8
    for (int idx = tid; idx < 4096; idx += 128) {
        int q = idx >> 2, c = idx & 3;
        float2 val = base[(size_t)q * KP + c];
        slab_re[q * 5 + c] = val.x;
        slab_im[q * 5 + c] = val.y;
    }
    __syncthreads();

    float2 v[32];
#pragma unroll
    for (int i2 = 0; i2 < 32; i2++) {
        int q = t + 32 * i2;
        v[i2] = make_float2(slab_re[q * 5 + w], slab_im[q * 5 + w]);
    }
    __syncthreads();                         /* slab dead -> patches */
    float* pre = sm + w * 2112;
    float* pim = pre + 1056;

    /* forward FFT along q */
    fft32r<false>(v);
#pragma unroll
    for (int k2 = 1; k2 < 32; k2++)
        v[k2] = cmul(v[k2], twg[(t * k2) & 1023]);
#pragma unroll
    for (int k2 = 0; k2 < 32; k2++) {
        pre[t * 33 + k2] = v[k2].x;
        pim[t * 33 + k2] = v[k2].y;
    }
    __syncwarp();
#pragma unroll
    for (int i1 = 0; i1 < 32; i1++)
        v[i1] = make_float2(pre[i1 * 33 + t], pim[i1 * 33 + t]);
    __syncwarp();
    fft32r<false>(v);                        /* spectrum F[t + 32*k1] */

    /* real spectral filter */
    float alpha = *alpha_p;
#pragma unroll
    for (int k1 = 0; k1 < 32; k1++) {
        float mag = sqrtf(v[k1].x * v[k1].x + v[k1].y * v[k1].y);
        float g = cosf(alpha * atanf(__logf(mag + 1e-10f)));
        v[k1].x *= g; v[k1].y *= g;
    }

    /* inverse FFT along q */
    fft32r<true>(v);                         /* u[i1], thread = k2 = t */
#pragma unroll
    for (int i1 = 1; i1 < 32; i1++)
        v[i1] = cmulc(v[i1], twg[(t * i1) & 1023]);
#pragma unroll
    for (int i1 = 0; i1 < 32; i1++) {        /* transpose: pat[k2][i1] */
        pre[t * 33 + i1] = v[i1].x;
        pim[t * 33 + i1] = v[i1].y;
    }
    __syncwarp();
#pragma unroll
    for (int k2 = 0; k2 < 32; k2++)
        v[k2] = make_float2(pre[k2 * 33 + t], pim[k2 * 33 + t]);
    __syncwarp();
    fft32r<true>(v);                         /* g[t + 32*i2] (x 1024) */

    __syncthreads();                         /* patches dead -> slab */
    const float scl = 1.0f / 1024.0f;
#pragma unroll
    for (int i2 = 0; i2 < 32; i2++) {
        int q = t + 32 * i2;
        slab_re[q * 5 + w] = v[i2].x * scl;
        slab_im[q * 5 + w] = v[i2].y * scl;
    }
    __syncthreads();
#pragma unroll 8
    for (int idx = tid; idx < 4096; idx += 128) {
        int q = idx >> 2, c = idx & 3;
        if (kbase + c < 513)
            base[(size_t)q * KP + c] = make_float2(slab_re[q * 5 + c], slab_im[q * 5 + c]);
    }
}

/* == pass 3: warp-level c2r inverse + warp softmax, attn split-bf16 out ==== */
__global__ void __launch_bounds__(128) fft_rows_inv_softmax_w(
    const float2* __restrict__ Y,
    __nv_bfloat16* __restrict__ outh, __nv_bfloat16* __restrict__ outl,
    const float2* __restrict__ twg)
{
    __shared__ float pat[4 * 2112];
    int t = threadIdx.x & 31, w = threadIdx.x >> 5;
    float* pre = pat + w * 2112;
    float* pim = pre + 1056;
    size_t p = (size_t)blockIdx.x * 4 + w;
    const float2* y0 = Y + (size_t)(2 * p) * KP;
    const float2* y1 = y0 + KP;

    /* build packed spectrum Z into natural-order patch */
#pragma unroll
    for (int u = 0; u <= 16; u++) {
        int k = t + 32 * u;
        if (u < 16 || t == 0) {
            float2 h0 = y0[k], h1 = y1[k];
            int idx = u * 33 + t;
            pre[idx] = h0.x - h1.y;
            pim[idx] = h0.y + h1.x;
            if (k >= 1 && k < 512) {
                int m = 1024 - k;
                int midx = (m >> 5) * 33 + (m & 31);
                pre[midx] = h0.x + h1.y;
                pim[midx] = h1.x - h0.y;
            }
        }
    }
    __syncwarp();
    float2 v[32];
#pragma unroll
    for (int k1 = 0; k1 < 32; k1++)          /* Z[t + 32*k1] */
        v[k1] = make_float2(pre[k1 * 33 + t], pim[k1 * 33 + t]);
    __syncwarp();
    fft32r<true>(v);                          /* u[i1], thread = k2 = t */
#pragma unroll
    for (int i1 = 1; i1 < 32; i1++)
        v[i1] = cmulc(v[i1], twg[(t * i1) & 1023]);
#pragma unroll
    for (int i1 = 0; i1 < 32; i1++) {
        pre[t * 33 + i1] = v[i1].x;
        pim[t * 33 + i1] = v[i1].y;
    }
    __syncwarp();
#pragma unroll
    for (int k2 = 0; k2 < 32; k2++)
        v[k2] = make_float2(pre[k2 * 33 + t], pim[k2 * 33 + t]);
    __syncwarp();
    fft32r<true>(v);                          /* x[t + 32*i2]: re=row0, im=row1 */

    /* warp softmax over 1024 cols for both rows */
    const float scl = 1.0f / 1024.0f;
    float m0 = -1e30f, m1 = -1e30f;
#pragma unroll
    for (int i2 = 0; i2 < 32; i2++) {
        v[i2].x *= scl; v[i2].y *= scl;
        m0 = fmaxf(m0, v[i2].x); m1 = fmaxf(m1, v[i2].y);
    }
#pragma unroll
    for (int o = 16; o; o >>= 1) {
        m0 = fmaxf(m0, __shfl_xor_sync(0xffffffffu, m0, o));
        m1 = fmaxf(m1, __shfl_xor_sync(0xffffffffu, m1, o));
    }
    float s0 = 0.f, s1 = 0.f;
    float p0[32], p1[32];
#pragma unroll
    for (int i2 = 0; i2 < 32; i2++) {
        p0[i2] = __expf(v[i2].x - m0);
        p1[i2] = __expf(v[i2].y - m1);
        s0 += p0[i2]; s1 += p1[i2];
    }
#pragma unroll
    for (int o = 16; o; o >>= 1) {
        s0 += __shfl_xor_sync(0xffffffffu, s0, o);
        s1 += __shfl_xor_sync(0xffffffffu, s1, o);
    }
    float inv0 = 1.0f / s0, inv1 = 1.0f / s1;
    size_t rb = (size_t)(2 * p) * 1024;
#pragma unroll
    for (int i2 = 0; i2 < 32; i2++) {
        int col = t + 32 * i2;
        __nv_bfloat16 h, l;
        splitw(p0[i2] * inv0, h, l);
        outh[rb + col] = h; outl[rb + col] = l;
        splitw(p1[i2] * inv1, h, l);
        outh[rb + 1024 + col] = h; outl[rb + 1024 + col] = l;
    }
}

/* ============================== launcher =================================== */
extern "C" void kernel_launch(void* const* d_in, const int* in_sizes, int n_in,
                              void* d_out, int out_size)
{
    const float* query = (const float*)d_in[0];
    const float* Wq    = (const float*)d_in[1];
    const float* bq    = (const float*)d_in[2];
    const float* Wk    = (const float*)d_in[3];
    const float* bk    = (const float*)d_in[4];
    const float* Wv    = (const float*)d_in[5];
    const float* bv    = (const float*)d_in[6];
    const float* Wo    = (const float*)d_in[7];
    const float* bo    = (const float*)d_in[8];
    const float* alpha = (const float*)d_in[9];
    float* out = (float*)d_out;

    __nv_bfloat16 *pqh, *pql, *pWqh, *pWql, *pWkh, *pWkl, *pWvh, *pWvl, *pWoh, *pWol;
    __nv_bfloat16 *pQh, *pQl, *pKh, *pKl, *pVth, *pVtl, *pah, *pal, *pch, *pcl;
    float *pV, *pSc;
    float2 *pFreq, *pTw;
    cudaGetSymbolAddress((void**)&pqh, g_qh);   cudaGetSymbolAddress((void**)&pql, g_ql);
    cudaGetSymbolAddress((void**)&pWqh, g_Wqh); cudaGetSymbolAddress((void**)&pWql, g_Wql);
    cudaGetSymbolAddress((void**)&pWkh, g_Wkh); cudaGetSymbolAddress((void**)&pWkl, g_Wkl);
    cudaGetSymbolAddress((void**)&pWvh, g_Wvh); cudaGetSymbolAddress((void**)&pWvl, g_Wvl);
    cudaGetSymbolAddress((void**)&pWoh, g_Woh); cudaGetSymbolAddress((void**)&pWol, g_Wol);
    cudaGetSymbolAddress((void**)&pQh, g_Qh);   cudaGetSymbolAddress((void**)&pQl, g_Ql);
    cudaGetSymbolAddress((void**)&pKh, g_Kh);   cudaGetSymbolAddress((void**)&pKl, g_Kl);
    cudaGetSymbolAddress((void**)&pVth, g_Vth); cudaGetSymbolAddress((void**)&pVtl, g_Vtl);
    cudaGetSymbolAddress((void**)&pah, g_ah);   cudaGetSymbolAddress((void**)&pal, g_al);
    cudaGetSymbolAddress((void**)&pch, g_ch);   cudaGetSymbolAddress((void**)&pcl, g_cl);
    cudaGetSymbolAddress((void**)&pV, g_V);
    cudaGetSymbolAddress((void**)&pSc, g_scores);
    cudaGetSymbolAddress((void**)&pFreq, g_freq);
    cudaGetSymbolAddress((void**)&pTw, g_tw);

    const int SM_P = 2 * (2 * 8192 + 2 * 8192);
    const int SM_A = 2 * (2 * 8192 + 2 * 4096);
    cudaFuncSetAttribute((const void*)mma_gemm<0, 2, 128, 2, 4, 1024>,
                         cudaFuncAttributeMaxDynamicSharedMemorySize, SM_P);
    cudaFuncSetAttribute((const void*)mma_gemm<0, 0, 128, 2, 4, 1024>,
                         cudaFuncAttributeMaxDynamicSharedMemorySize, SM_P);
    cudaFuncSetAttribute((const void*)mma_gemm<1, 1, 128, 2, 4, 64>,
                         cudaFuncAttributeMaxDynamicSharedMemorySize, SM_P);
    cudaFuncSetAttribute((const void*)mma_gemm<2, 3, 64, 4, 2, 1024>,
                         cudaFuncAttributeMaxDynamicSharedMemorySize, SM_A);

    init_twiddles<<<4, 256>>>(pTw);

    split_convert<<<(int)(NELEM / 4 / 256), 256>>>(query, pqh, pql, (int)(NELEM / 4));
    split_convert<<<E_ * E_ / 4 / 256, 256>>>(Wq, pWqh, pWql, E_ * E_ / 4);
    split_convert<<<E_ * E_ / 4 / 256, 256>>>(Wk, pWkh, pWkl, E_ * E_ / 4);
    split_convert<<<E_ * E_ / 4 / 256, 256>>>(Wv, pWvh, pWvl, E_ * E_ / 4);
    split_convert<<<E_ * E_ / 4 / 256, 256>>>(Wo, pWoh, pWol, E_ * E_ / 4);

    dim3 gp(E_ / 128, (B_ * S_) / 128, 1);
    mma_gemm<0, 2, 128, 2, 4, 1024><<<gp, 256, SM_P>>>(pqh, pql, pWqh, pWql, bq, pQh, pQl, 1.0f);
    mma_gemm<0, 2, 128, 2, 4, 1024><<<gp, 256, SM_P>>>(pqh, pql, pWkh, pWkl, bk, pKh, pKl, 1.0f);
    mma_gemm<0, 0, 128, 2, 4, 1024><<<gp, 256, SM_P>>>(pqh, pql, pWvh, pWvl, bv, pV, 0, 1.0f);

    transpose_v<<<dim3(32, 2, NBH), dim3(32, 8)>>>(pV, pVth, pVtl);

    dim3 gs(S_ / 128, S_ / 128, NBH);
    mma_gemm<1, 1, 128, 2, 4, 64><<<gs, 256, SM_P>>>(pQh, pQl, pKh, pKl, 0, pSc, 0, 0.125f);

    fft_rows_fwd_w<<<NBH * S_ / 2 / 4, 128>>>(pSc, pFreq, pTw);

    fft_cols_w<<<dim3(129, NBH), 128>>>(pFreq, alpha, pTw);

    fft_rows_inv_softmax_w<<<NBH * S_ / 2 / 4, 128>>>(pFreq, pah, pal, pTw);

    dim3 ga(1, S_ / 128, NBH);
    mma_gemm<2, 3, 64, 4, 2, 1024><<<ga, 256, SM_A>>>(pah, pal, pVth, pVtl, 0, pch, pcl, 1.0f);

    mma_gemm<0, 0, 128, 2, 4, 1024><<<gp, 256, SM_P>>>(pch, pcl, pWoh, pWol, bo, out, 0, 1.0f);
}

// round 7
// speedup vs baseline: 4.5309x; 1.1670x over previous
#include <cuda_runtime.h>
#include <cuda_bf16.h>
#include <cuda_fp16.h>
#include <math.h>
#include <stdint.h>

#define B_   4
#define S_   1024
#define E_   1024
#define H_   16
#define HD_  64
#define NBH  64          /* B*H */
#define KP   528         /* padded half-spectrum width (>=513, 16-mult) */
#define NELEM ((size_t)B_ * S_ * E_)   /* 4M */

/* ---------------- scratch (device globals: no allocations allowed) -------- */
__device__ __nv_bfloat16 g_qh[NELEM],  g_ql[NELEM];
__device__ __nv_bfloat16 g_Wqh[E_*E_], g_Wql[E_*E_];
__device__ __nv_bfloat16 g_Wkh[E_*E_], g_Wkl[E_*E_];
__device__ __nv_bfloat16 g_Wvh[E_*E_], g_Wvl[E_*E_];
__device__ __nv_bfloat16 g_Woh[E_*E_], g_Wol[E_*E_];
__device__ __nv_bfloat16 g_Qh[NELEM],  g_Ql[NELEM];
__device__ __nv_bfloat16 g_Kh[NELEM],  g_Kl[NELEM];
__device__ float         g_V[NELEM];
__device__ __nv_bfloat16 g_Vth[NELEM], g_Vtl[NELEM];
__device__ float         g_scores[(size_t)NBH * S_ * S_];
__device__ __nv_bfloat16 g_ah[(size_t)NBH * S_ * S_];
__device__ __nv_bfloat16 g_al[(size_t)NBH * S_ * S_];
__device__ __nv_bfloat16 g_ch[NELEM],  g_cl[NELEM];
__device__ __half2 g_freq[(size_t)NBH * S_ * KP];     /* fp16 half-spectrum */
__device__ float2 g_tw[1024];

/* ======================= small helpers ==================================== */
__device__ __forceinline__ uint32_t smem_u32(const void* p) {
    uint32_t a;
    asm("{ .reg .u64 t; cvta.to.shared.u64 t, %1; cvt.u32.u64 %0, t; }"
        : "=r"(a) : "l"(p));
    return a;
}
#define CP16(dst, src) \
    asm volatile("cp.async.cg.shared.global [%0], [%1], 16;" \
                 :: "r"(dst), "l"(src))
#define CP_COMMIT() asm volatile("cp.async.commit_group;" ::: "memory")
#define CP_WAIT1()  asm volatile("cp.async.wait_group 1;" ::: "memory")
#define CP_WAIT0()  asm volatile("cp.async.wait_group 0;" ::: "memory")

__device__ __forceinline__ void mma16816(float* d, const uint32_t* a, const uint32_t* b)
{
    asm volatile(
        "mma.sync.aligned.m16n8k16.row.col.f32.bf16.bf16.f32 "
        "{%0,%1,%2,%3}, {%4,%5,%6,%7}, {%8,%9}, {%0,%1,%2,%3};"
        : "+f"(d[0]), "+f"(d[1]), "+f"(d[2]), "+f"(d[3])
        : "r"(a[0]), "r"(a[1]), "r"(a[2]), "r"(a[3]), "r"(b[0]), "r"(b[1]));
}

__device__ __forceinline__ int swzt(int row, int ch) {
    return (row << 6) + ((ch ^ ((row >> 1) & 3)) << 4);
}

__device__ __forceinline__ void splitw(float v, __nv_bfloat16& h, __nv_bfloat16& l) {
    h = __float2bfloat16(v);
    l = __float2bfloat16(v - __bfloat162float(h));
}

__device__ __forceinline__ float2 cmul(float2 a, float2 b) {
    return make_float2(a.x * b.x - a.y * b.y, a.x * b.y + a.y * b.x);
}
__device__ __forceinline__ float2 cmulc(float2 a, float2 b) {
    return make_float2(a.x * b.x + a.y * b.y, a.y * b.x - a.x * b.y);
}

/* ============ split convert: fp32 -> bf16 hi + bf16 lo (vectorized) ======= */
__global__ void split_convert(const float* __restrict__ src,
                              __nv_bfloat16* __restrict__ h,
                              __nv_bfloat16* __restrict__ l, int n4)
{
    int i = blockIdx.x * blockDim.x + threadIdx.x;
    if (i >= n4) return;
    float4 v = ((const float4*)src)[i];
    __nv_bfloat16 h0, h1, h2, h3, l0, l1, l2, l3;
    splitw(v.x, h0, l0); splitw(v.y, h1, l1);
    splitw(v.z, h2, l2); splitw(v.w, h3, l3);
    uint2 hv, lv;
    hv.x = (uint32_t)__bfloat16_as_ushort(h0) | ((uint32_t)__bfloat16_as_ushort(h1) << 16);
    hv.y = (uint32_t)__bfloat16_as_ushort(h2) | ((uint32_t)__bfloat16_as_ushort(h3) << 16);
    lv.x = (uint32_t)__bfloat16_as_ushort(l0) | ((uint32_t)__bfloat16_as_ushort(l1) << 16);
    lv.y = (uint32_t)__bfloat16_as_ushort(l2) | ((uint32_t)__bfloat16_as_ushort(l3) << 16);
    ((uint2*)h)[i] = hv;
    ((uint2*)l)[i] = lv;
}

/* == split-bf16 tensor-core GEMM, 3-stage cp.async pipeline, 1 sync/iter === */
template<int MODE, int EPI, int BN, int WROWS, int WCOLS, int KTOT>
__global__ void __launch_bounds__(256, 2) mma_gemm(
    const __nv_bfloat16* __restrict__ Ahg, const __nv_bfloat16* __restrict__ Alg,
    const __nv_bfloat16* __restrict__ Bhg, const __nv_bfloat16* __restrict__ Blg,
    const float* __restrict__ bias, void* __restrict__ Cp, void* __restrict__ C2p,
    float oscale)
{
    constexpr int BM = 128;
    constexpr int ATB = BM * 64;
    constexpr int BTB = BN * 64;
    constexpr int BUFS = 2 * ATB + 2 * BTB;
    constexpr int WTM = BM / WROWS, WTN = BN / WCOLS;
    constexpr int FM = WTM / 16, FN = WTN / 8;
    constexpr int NIT = KTOT / 32;

    extern __shared__ char sm[];
    uint32_t smb = smem_u32(sm);

    int tid = threadIdx.x;
    int lane = tid & 31, wid = tid >> 5;
    int wrow = wid / WCOLS, wcol = wid % WCOLS;
    int m0 = wrow * WTM, n0 = wcol * WTN;
    int gid = lane >> 2, tig = lane & 3;

    size_t offA = 0, offB = 0, offC = 0;
    if (MODE == 1) {
        int z = blockIdx.z;
        size_t ho = (size_t)(z >> 4) * S_ * E_ + (size_t)(z & 15) * HD_;
        offA = ho; offB = ho; offC = (size_t)z * S_ * S_;
    } else if (MODE == 2) {
        int z = blockIdx.z;
        offA = (size_t)z * S_ * S_;
        offB = (size_t)z * HD_ * S_;
        offC = (size_t)(z >> 4) * S_ * E_ + (size_t)(z & 15) * HD_;
    }
    const char* A8h = (const char*)(Ahg + offA + (size_t)blockIdx.y * BM * 1024);
    const char* A8l = (const char*)(Alg + offA + (size_t)blockIdx.y * BM * 1024);
    const char* B8h = (const char*)(Bhg + offB + (size_t)blockIdx.x * BN * 1024);
    const char* B8l = (const char*)(Blg + offB + (size_t)blockIdx.x * BN * 1024);

    auto fill = [&](int bf, int k0) {
        size_t kb = (size_t)k0 * 2;
        uint32_t base = smb + bf * BUFS;
#pragma unroll
        for (int i = tid; i < BM * 4; i += 256) {
            int r = i >> 2, ch = i & 3;
            size_t so = (size_t)r * 2048 + kb + ch * 16;
            CP16(base + swzt(r, ch), A8h + so);
            CP16(base + ATB + swzt(r, ch), A8l + so);
        }
#pragma unroll
        for (int i = tid; i < BN * 4; i += 256) {
            int r = i >> 2, ch = i & 3;
            size_t so = (size_t)r * 2048 + kb + ch * 16;
            CP16(base + 2 * ATB + swzt(r, ch), B8h + so);
            CP16(base + 2 * ATB + BTB + swzt(r, ch), B8l + so);
        }
    };

    float acc[FM][FN][4];
#pragma unroll
    for (int i = 0; i < FM; i++)
#pragma unroll
        for (int j = 0; j < FN; j++)
#pragma unroll
            for (int u = 0; u < 4; u++) acc[i][j][u] = 0.f;

    fill(0, 0);
    CP_COMMIT();
    if (NIT > 1) fill(1, 32);
    CP_COMMIT();

    for (int it = 0; it < NIT; ++it) {
        if (it + 1 < NIT) { CP_WAIT1(); } else { CP_WAIT0(); }
        __syncthreads();
        int buf = it % 3;
        const char* pAh = sm + buf * BUFS;
        const char* pAl = pAh + ATB;
        const char* pBh = pAh + 2 * ATB;
        const char* pBl = pBh + BTB;
#pragma unroll
        for (int ks = 0; ks < 2; ks++) {
            uint32_t bhf[FN][2], blf[FN][2];
#pragma unroll
            for (int fn = 0; fn < FN; fn++) {
                int br = n0 + fn * 8 + gid;
                int o0 = swzt(br, ks * 2) + tig * 4;
                int o1 = swzt(br, ks * 2 + 1) + tig * 4;
                bhf[fn][0] = *(const uint32_t*)(pBh + o0);
                bhf[fn][1] = *(const uint32_t*)(pBh + o1);
                blf[fn][0] = *(const uint32_t*)(pBl + o0);
                blf[fn][1] = *(const uint32_t*)(pBl + o1);
            }
#pragma unroll
            for (int fm = 0; fm < FM; fm++) {
                int ar0 = m0 + fm * 16 + gid, ar8 = ar0 + 8;
                int o00 = swzt(ar0, ks * 2) + tig * 4;
                int o80 = swzt(ar8, ks * 2) + tig * 4;
                int o01 = swzt(ar0, ks * 2 + 1) + tig * 4;
                int o81 = swzt(ar8, ks * 2 + 1) + tig * 4;
                uint32_t ahf[4], alf[4];
                ahf[0] = *(const uint32_t*)(pAh + o00);
                ahf[1] = *(const uint32_t*)(pAh + o80);
                ahf[2] = *(const uint32_t*)(pAh + o01);
                ahf[3] = *(const uint32_t*)(pAh + o81);
                alf[0] = *(const uint32_t*)(pAl + o00);
                alf[1] = *(const uint32_t*)(pAl + o80);
                alf[2] = *(const uint32_t*)(pAl + o01);
                alf[3] = *(const uint32_t*)(pAl + o81);
#pragma unroll
                for (int fn = 0; fn < FN; fn++) {
                    mma16816(acc[fm][fn], ahf, bhf[fn]);
                    mma16816(acc[fm][fn], ahf, blf[fn]);
                    mma16816(acc[fm][fn], alf, bhf[fn]);
                }
            }
        }
        if (it + 2 < NIT) {
            fill((it + 2) % 3, (it + 2) * 32);
            CP_COMMIT();
        }
    }

#pragma unroll
    for (int fm = 0; fm < FM; fm++) {
        size_t r0 = (size_t)blockIdx.y * BM + m0 + fm * 16 + gid;
#pragma unroll
        for (int fn = 0; fn < FN; fn++) {
            int cgl = blockIdx.x * BN + n0 + fn * 8 + tig * 2;
            float b0 = 0.f, b1 = 0.f;
            if (EPI == 0 || EPI == 2) { b0 = bias[cgl]; b1 = bias[cgl + 1]; }
            float v00 = acc[fm][fn][0] * oscale + b0;
            float v01 = acc[fm][fn][1] * oscale + b1;
            float v10 = acc[fm][fn][2] * oscale + b0;
            float v11 = acc[fm][fn][3] * oscale + b1;
            if (EPI <= 1) {
                float* C = (float*)Cp;
                *(float2*)&C[offC + r0 * 1024 + cgl] = make_float2(v00, v01);
                *(float2*)&C[offC + (r0 + 8) * 1024 + cgl] = make_float2(v10, v11);
            } else {
                __nv_bfloat16* Ch = (__nv_bfloat16*)Cp;
                __nv_bfloat16* Cl = (__nv_bfloat16*)C2p;
                __nv_bfloat16 h00, h01, h10, h11, l00, l01, l10, l11;
                splitw(v00, h00, l00); splitw(v01, h01, l01);
                splitw(v10, h10, l10); splitw(v11, h11, l11);
                uint32_t hv0 = (uint32_t)__bfloat16_as_ushort(h00) | ((uint32_t)__bfloat16_as_ushort(h01) << 16);
                uint32_t lv0 = (uint32_t)__bfloat16_as_ushort(l00) | ((uint32_t)__bfloat16_as_ushort(l01) << 16);
                uint32_t hv1 = (uint32_t)__bfloat16_as_ushort(h10) | ((uint32_t)__bfloat16_as_ushort(h11) << 16);
                uint32_t lv1 = (uint32_t)__bfloat16_as_ushort(l10) | ((uint32_t)__bfloat16_as_ushort(l11) << 16);
                *(uint32_t*)&Ch[offC + r0 * 1024 + cgl] = hv0;
                *(uint32_t*)&Cl[offC + r0 * 1024 + cgl] = lv0;
                *(uint32_t*)&Ch[offC + (r0 + 8) * 1024 + cgl] = hv1;
                *(uint32_t*)&Cl[offC + (r0 + 8) * 1024 + cgl] = lv1;
            }
        }
    }
}

/* ===== Vt[z][d][k] = V[b][k][h*64+d], written split-bf16 ================== */
__global__ void transpose_v(const float* __restrict__ V,
                            __nv_bfloat16* __restrict__ Vth,
                            __nv_bfloat16* __restrict__ Vtl)
{
    __shared__ float tile[32][33];
    int z = blockIdx.z;
    int b = z >> 4, h = z & 15;
    int k0 = blockIdx.x * 32, d0 = blockIdx.y * 32;
    int tx = threadIdx.x, ty = threadIdx.y;
#pragma unroll
    for (int i = 0; i < 4; i++)
        tile[ty + i * 8][tx] =
            V[((size_t)b * S_ + k0 + ty + i * 8) * E_ + h * HD_ + d0 + tx];
    __syncthreads();
#pragma unroll
    for (int i = 0; i < 4; i++) {
        float v = tile[tx][ty + i * 8];
        __nv_bfloat16 hh, ll;
        splitw(v, hh, ll);
        size_t o = ((size_t)z * HD_ + d0 + ty + i * 8) * S_ + k0 + tx;
        Vth[o] = hh;
        Vtl[o] = ll;
    }
}

/* ===================== twiddle init ======================================= */
__global__ void init_twiddles(float2* tw)
{
    int j = blockIdx.x * blockDim.x + threadIdx.x;
    if (j < 1024) {
        float ang = -6.28318530717958647692f * (float)j / 1024.0f;
        tw[j] = make_float2(cosf(ang), sinf(ang));
    }
}

/* ============== in-register 32-pt FFT (DIF, natural order out) ============ */
template<bool INV>
__device__ __forceinline__ void fft32r(float2* v)
{
    const float C[16] = {
        1.f, 0.980785280403230f, 0.923879532511287f, 0.831469612302545f,
        0.707106781186548f, 0.555570233019602f, 0.382683432365090f, 0.195090322016128f,
        0.f, -0.195090322016128f, -0.382683432365090f, -0.555570233019602f,
        -0.707106781186548f, -0.831469612302545f, -0.923879532511287f, -0.980785280403230f };
    const float Sn[16] = {
        0.f, 0.195090322016128f, 0.382683432365090f, 0.555570233019602f,
        0.707106781186548f, 0.831469612302545f, 0.923879532511287f, 0.980785280403230f,
        1.f, 0.980785280403230f, 0.923879532511287f, 0.831469612302545f,
        0.707106781186548f, 0.555570233019602f, 0.382683432365090f, 0.195090322016128f };
#pragma unroll
    for (int h = 16; h >= 1; h >>= 1) {
#pragma unroll
        for (int b = 0; b < 32; b += 2 * h) {
#pragma unroll
            for (int j = 0; j < h; j++) {
                int e = j * (16 / h);
                float tc = C[e];
                float ts = INV ? Sn[e] : -Sn[e];
                float2 a = v[b + j], bb = v[b + j + h];
                v[b + j] = make_float2(a.x + bb.x, a.y + bb.y);
                float dx = a.x - bb.x, dy = a.y - bb.y;
                v[b + j + h] = make_float2(dx * tc - dy * ts, dx * ts + dy * tc);
            }
        }
    }
#pragma unroll
    for (int i = 0; i < 32; i++) {
        int r = ((i & 1) << 4) | ((i & 2) << 2) | (i & 4) | ((i & 8) >> 2) | ((i & 16) >> 4);
        if (r > i) { float2 tmp = v[i]; v[i] = v[r]; v[r] = tmp; }
    }
}

/* ====== pass 1: warp-level fwd FFT of 2 packed real rows -> half spectra == */
__global__ void __launch_bounds__(128) fft_rows_fwd_w(
    const float* __restrict__ in, __half2* __restrict__ Y,
    const float2* __restrict__ twg)
{
    __shared__ float pat[4 * 2112];
    int t = threadIdx.x & 31, w = threadIdx.x >> 5;
    float* pre = pat + w * 2112;
    float* pim = pre + 1056;
    size_t p = (size_t)blockIdx.x * 4 + w;
    const float* r0 = in + p * 2048;
    const float* r1 = r0 + 1024;

    float2 v[32];
#pragma unroll
    for (int i2 = 0; i2 < 32; i2++)
        v[i2] = make_float2(r0[t + 32 * i2], r1[t + 32 * i2]);
    fft32r<false>(v);
#pragma unroll
    for (int k2 = 1; k2 < 32; k2++)
        v[k2] = cmul(v[k2], twg[(t * k2) & 1023]);
#pragma unroll
    for (int k2 = 0; k2 < 32; k2++) {
        pre[t * 33 + k2] = v[k2].x;
        pim[t * 33 + k2] = v[k2].y;
    }
    __syncwarp();
#pragma unroll
    for (int i1 = 0; i1 < 32; i1++)
        v[i1] = make_float2(pre[i1 * 33 + t], pim[i1 * 33 + t]);
    __syncwarp();
    fft32r<false>(v);
#pragma unroll
    for (int k1 = 0; k1 < 32; k1++) {
        pre[k1 * 33 + t] = v[k1].x;
        pim[k1 * 33 + t] = v[k1].y;
    }
    __syncwarp();

    __half2* y0 = Y + (size_t)(2 * p) * KP;
    __half2* y1 = y0 + KP;
#pragma unroll
    for (int u = 0; u <= 16; u++) {
        int k = t + 32 * u;
        if (u < 16 || t == 0) {
            int idx = u * 33 + t;
            float2 Xk = make_float2(pre[idx], pim[idx]);
            int m = (1024 - k) & 1023;
            int midx = (m >> 5) * 33 + (m & 31);
            float2 Xm = make_float2(pre[midx], pim[midx]);
            y0[k] = __floats2half2_rn(0.5f * (Xk.x + Xm.x), 0.5f * (Xk.y - Xm.y));
            y1[k] = __floats2half2_rn(0.5f * (Xk.y + Xm.y), 0.5f * (Xm.x - Xk.x));
        }
    }
}

/* ===== pass 2: warp-level col FFT + real cos-filter + col IFFT =========== */
__global__ void __launch_bounds__(128) fft_cols_w(
    __half2* __restrict__ Y, const float* __restrict__ alpha_p,
    const float2* __restrict__ twg)
{
    __shared__ float sm[10240];             /* slab 2x5120 / patches 4x2112 */
    float* slab_re = sm;
    float* slab_im = sm + 5120;
    int tid = threadIdx.x;
    int t = tid & 31, w = tid >> 5;
    int z = blockIdx.y;
    int kbase = blockIdx.x * 4;
    __half2* base = Y + (size_t)z * S_ * KP + kbase;

#pragma unroll 8
    for (int idx = tid; idx < 4096; idx += 128) {
        int q = idx >> 2, c = idx & 3;
        float2 val = __half22float2(base[(size_t)q * KP + c]);
        slab_re[q * 5 + c] = val.x;
        slab_im[q * 5 + c] = val.y;
    }
    __syncthreads();

    float2 v[32];
#pragma unroll
    for (int i2 = 0; i2 < 32; i2++) {
        int q = t + 32 * i2;
        v[i2] = make_float2(slab_re[q * 5 + w], slab_im[q * 5 + w]);
    }
    __syncthreads();
    float* pre = sm + w * 2112;
    float* pim = pre + 1056;

    fft32r<false>(v);
#pragma unroll
    for (int k2 = 1; k2 < 32; k2++)
        v[k2] = cmul(v[k2], twg[(t * k2) & 1023]);
#pragma unroll
    for (int k2 = 0; k2 < 32; k2++) {
        pre[t * 33 + k2] = v[k2].x;
        pim[t * 33 + k2] = v[k2].y;
    }
    __syncwarp();
#pragma unroll
    for (int i1 = 0; i1 < 32; i1++)
        v[i1] = make_float2(pre[i1 * 33 + t], pim[i1 * 33 + t]);
    __syncwarp();
    fft32r<false>(v);

    float alpha = *alpha_p;
#pragma unroll
    for (int k1 = 0; k1 < 32; k1++) {
        float mag = sqrtf(v[k1].x * v[k1].x + v[k1].y * v[k1].y);
        float g = __cosf(alpha * atanf(__logf(mag + 1e-10f)));
        v[k1].x *= g; v[k1].y *= g;
    }

    fft32r<true>(v);
#pragma unroll
    for (int i1 = 1; i1 < 32; i1++)
        v[i1] = cmulc(v[i1], twg[(t * i1) & 1023]);
#pragma unroll
    for (int i1 = 0; i1 < 32; i1++) {
        pre[t * 33 + i1] = v[i1].x;
        pim[t * 33 + i1] = v[i1].y;
    }
    __syncwarp();
#pragma unroll
    for (int k2 = 0; k2 < 32; k2++)
        v[k2] = make_float2(pre[k2 * 33 + t], pim[k2 * 33 + t]);
    __syncwarp();
    fft32r<true>(v);

    __syncthreads();
    const float scl = 1.0f / 1024.0f;
#pragma unroll
    for (int i2 = 0; i2 < 32; i2++) {
        int q = t + 32 * i2;
        slab_re[q * 5 + w] = v[i2].x * scl;
        slab_im[q * 5 + w] = v[i2].y * scl;
    }
    __syncthreads();
#pragma unroll 8
    for (int idx = tid; idx < 4096; idx += 128) {
        int q = idx >> 2, c = idx & 3;
        if (kbase + c < 513)
            base[(size_t)q * KP + c] =
                __floats2half2_rn(slab_re[q * 5 + c], slab_im[q * 5 + c]);
    }
}

/* == pass 3: warp-level c2r inverse + warp softmax, attn split-bf16 out ==== */
__global__ void __launch_bounds__(128) fft_rows_inv_softmax_w(
    const __half2* __restrict__ Y,
    __nv_bfloat16* __restrict__ outh, __nv_bfloat16* __restrict__ outl,
    const float2* __restrict__ twg)
{
    __shared__ float pat[4 * 2112];
    int t = threadIdx.x & 31, w = threadIdx.x >> 5;
    float* pre = pat + w * 2112;
    float* pim = pre + 1056;
    size_t p = (size_t)blockIdx.x * 4 + w;
    const __half2* y0 = Y + (size_t)(2 * p) * KP;
    const __half2* y1 = y0 + KP;

#pragma unroll
    for (int u = 0; u <= 16; u++) {
        int k = t + 32 * u;
        if (u < 16 || t == 0) {
            float2 h0 = __half22float2(y0[k]);
            float2 h1 = __half22float2(y1[k]);
            int idx = u * 33 + t;
            pre[idx] = h0.x - h1.y;
            pim[idx] = h0.y + h1.x;
            if (k >= 1 && k < 512) {
                int m = 1024 - k;
                int midx = (m >> 5) * 33 + (m & 31);
                pre[midx] = h0.x + h1.y;
                pim[midx] = h1.x - h0.y;
            }
        }
    }
    __syncwarp();
    float2 v[32];
#pragma unroll
    for (int k1 = 0; k1 < 32; k1++)
        v[k1] = make_float2(pre[k1 * 33 + t], pim[k1 * 33 + t]);
    __syncwarp();
    fft32r<true>(v);
#pragma unroll
    for (int i1 = 1; i1 < 32; i1++)
        v[i1] = cmulc(v[i1], twg[(t * i1) & 1023]);
#pragma unroll
    for (int i1 = 0; i1 < 32; i1++) {
        pre[t * 33 + i1] = v[i1].x;
        pim[t * 33 + i1] = v[i1].y;
    }
    __syncwarp();
#pragma unroll
    for (int k2 = 0; k2 < 32; k2++)
        v[k2] = make_float2(pre[k2 * 33 + t], pim[k2 * 33 + t]);
    __syncwarp();
    fft32r<true>(v);

    const float scl = 1.0f / 1024.0f;
    float m0 = -1e30f, m1 = -1e30f;
#pragma unroll
    for (int i2 = 0; i2 < 32; i2++) {
        v[i2].x *= scl; v[i2].y *= scl;
        m0 = fmaxf(m0, v[i2].x); m1 = fmaxf(m1, v[i2].y);
    }
#pragma unroll
    for (int o = 16; o; o >>= 1) {
        m0 = fmaxf(m0, __shfl_xor_sync(0xffffffffu, m0, o));
        m1 = fmaxf(m1, __shfl_xor_sync(0xffffffffu, m1, o));
    }
    float s0 = 0.f, s1 = 0.f;
    float p0[32], p1[32];
#pragma unroll
    for (int i2 = 0; i2 < 32; i2++) {
        p0[i2] = __expf(v[i2].x - m0);
        p1[i2] = __expf(v[i2].y - m1);
        s0 += p0[i2]; s1 += p1[i2];
    }
#pragma unroll
    for (int o = 16; o; o >>= 1) {
        s0 += __shfl_xor_sync(0xffffffffu, s0, o);
        s1 += __shfl_xor_sync(0xffffffffu, s1, o);
    }
    float inv0 = 1.0f / s0, inv1 = 1.0f / s1;
    size_t rb = (size_t)(2 * p) * 1024;
#pragma unroll
    for (int i2 = 0; i2 < 32; i2++) {
        int col = t + 32 * i2;
        __nv_bfloat16 h, l;
        splitw(p0[i2] * inv0, h, l);
        outh[rb + col] = h; outl[rb + col] = l;
        splitw(p1[i2] * inv1, h, l);
        outh[rb + 1024 + col] = h; outl[rb + 1024 + col] = l;
    }
}

/* ============================== launcher =================================== */
extern "C" void kernel_launch(void* const* d_in, const int* in_sizes, int n_in,
                              void* d_out, int out_size)
{
    const float* query = (const float*)d_in[0];
    const float* Wq    = (const float*)d_in[1];
    const float* bq    = (const float*)d_in[2];
    const float* Wk    = (const float*)d_in[3];
    const float* bk    = (const float*)d_in[4];
    const float* Wv    = (const float*)d_in[5];
    const float* bv    = (const float*)d_in[6];
    const float* Wo    = (const float*)d_in[7];
    const float* bo    = (const float*)d_in[8];
    const float* alpha = (const float*)d_in[9];
    float* out = (float*)d_out;

    __nv_bfloat16 *pqh, *pql, *pWqh, *pWql, *pWkh, *pWkl, *pWvh, *pWvl, *pWoh, *pWol;
    __nv_bfloat16 *pQh, *pQl, *pKh, *pKl, *pVth, *pVtl, *pah, *pal, *pch, *pcl;
    float *pV, *pSc;
    __half2 *pFreq;
    float2 *pTw;
    cudaGetSymbolAddress((void**)&pqh, g_qh);   cudaGetSymbolAddress((void**)&pql, g_ql);
    cudaGetSymbolAddress((void**)&pWqh, g_Wqh); cudaGetSymbolAddress((void**)&pWql, g_Wql);
    cudaGetSymbolAddress((void**)&pWkh, g_Wkh); cudaGetSymbolAddress((void**)&pWkl, g_Wkl);
    cudaGetSymbolAddress((void**)&pWvh, g_Wvh); cudaGetSymbolAddress((void**)&pWvl, g_Wvl);
    cudaGetSymbolAddress((void**)&pWoh, g_Woh); cudaGetSymbolAddress((void**)&pWol, g_Wol);
    cudaGetSymbolAddress((void**)&pQh, g_Qh);   cudaGetSymbolAddress((void**)&pQl, g_Ql);
    cudaGetSymbolAddress((void**)&pKh, g_Kh);   cudaGetSymbolAddress((void**)&pKl, g_Kl);
    cudaGetSymbolAddress((void**)&pVth, g_Vth); cudaGetSymbolAddress((void**)&pVtl, g_Vtl);
    cudaGetSymbolAddress((void**)&pah, g_ah);   cudaGetSymbolAddress((void**)&pal, g_al);
    cudaGetSymbolAddress((void**)&pch, g_ch);   cudaGetSymbolAddress((void**)&pcl, g_cl);
    cudaGetSymbolAddress((void**)&pV, g_V);
    cudaGetSymbolAddress((void**)&pSc, g_scores);
    cudaGetSymbolAddress((void**)&pFreq, g_freq);
    cudaGetSymbolAddress((void**)&pTw, g_tw);

    const int SM_P = 3 * (2 * 8192 + 2 * 8192);   /* 98304 */
    const int SM_A = 3 * (2 * 8192 + 2 * 4096);   /* 73728 */
    cudaFuncSetAttribute((const void*)mma_gemm<0, 2, 128, 2, 4, 1024>,
                         cudaFuncAttributeMaxDynamicSharedMemorySize, SM_P);
    cudaFuncSetAttribute((const void*)mma_gemm<0, 0, 128, 2, 4, 1024>,
                         cudaFuncAttributeMaxDynamicSharedMemorySize, SM_P);
    cudaFuncSetAttribute((const void*)mma_gemm<1, 1, 128, 2, 4, 64>,
                         cudaFuncAttributeMaxDynamicSharedMemorySize, SM_P);
    cudaFuncSetAttribute((const void*)mma_gemm<2, 3, 64, 4, 2, 1024>,
                         cudaFuncAttributeMaxDynamicSharedMemorySize, SM_A);

    init_twiddles<<<4, 256>>>(pTw);

    split_convert<<<(int)(NELEM / 4 / 256), 256>>>(query, pqh, pql, (int)(NELEM / 4));
    split_convert<<<E_ * E_ / 4 / 256, 256>>>(Wq, pWqh, pWql, E_ * E_ / 4);
    split_convert<<<E_ * E_ / 4 / 256, 256>>>(Wk, pWkh, pWkl, E_ * E_ / 4);
    split_convert<<<E_ * E_ / 4 / 256, 256>>>(Wv, pWvh, pWvl, E_ * E_ / 4);
    split_convert<<<E_ * E_ / 4 / 256, 256>>>(Wo, pWoh, pWol, E_ * E_ / 4);

    dim3 gp(E_ / 128, (B_ * S_) / 128, 1);
    mma_gemm<0, 2, 128, 2, 4, 1024><<<gp, 256, SM_P>>>(pqh, pql, pWqh, pWql, bq, pQh, pQl, 1.0f);
    mma_gemm<0, 2, 128, 2, 4, 1024><<<gp, 256, SM_P>>>(pqh, pql, pWkh, pWkl, bk, pKh, pKl, 1.0f);
    mma_gemm<0, 0, 128, 2, 4, 1024><<<gp, 256, SM_P>>>(pqh, pql, pWvh, pWvl, bv, pV, 0, 1.0f);

    transpose_v<<<dim3(32, 2, NBH), dim3(32, 8)>>>(pV, pVth, pVtl);

    dim3 gs(S_ / 128, S_ / 128, NBH);
    mma_gemm<1, 1, 128, 2, 4, 64><<<gs, 256, SM_P>>>(pQh, pQl, pKh, pKl, 0, pSc, 0, 0.125f);

    fft_rows_fwd_w<<<NBH * S_ / 2 / 4, 128>>>(pSc, pFreq, pTw);

    fft_cols_w<<<dim3(129, NBH), 128>>>(pFreq, alpha, pTw);

    fft_rows_inv_softmax_w<<<NBH * S_ / 2 / 4, 128>>>(pFreq, pah, pal, pTw);

    dim3 ga(1, S_ / 128, NBH);
    mma_gemm<2, 3, 64, 4, 2, 1024><<<ga, 256, SM_A>>>(pah, pal, pVth, pVtl, 0, pch, pcl, 1.0f);

    mma_gemm<0, 0, 128, 2, 4, 1024><<<gp, 256, SM_P>>>(pch, pcl, pWoh, pWol, bo, out, 0, 1.0f);
}

// round 8
// speedup vs baseline: 4.9113x; 1.0840x over previous
#include <cuda_runtime.h>
#include <cuda_bf16.h>
#include <cuda_fp16.h>
#include <math.h>
#include <stdint.h>

#define B_   4
#define S_   1024
#define E_   1024
#define H_   16
#define HD_  64
#define NBH  64          /* B*H */
#define KP   528         /* padded half-spectrum width */
#define NELEM ((size_t)B_ * S_ * E_)   /* 4M */

/* ---------------- scratch (device globals: no allocations allowed) -------- */
__device__ __nv_bfloat16 g_qh[NELEM],  g_ql[NELEM];
__device__ __nv_bfloat16 g_Wqh[E_*E_], g_Wql[E_*E_];
__device__ __nv_bfloat16 g_Wkh[E_*E_], g_Wkl[E_*E_];
__device__ __nv_bfloat16 g_Wvh[E_*E_], g_Wvl[E_*E_];
__device__ __nv_bfloat16 g_Woh[E_*E_], g_Wol[E_*E_];
__device__ __nv_bfloat16 g_Qh[NELEM],  g_Ql[NELEM];
__device__ __nv_bfloat16 g_Kh[NELEM],  g_Kl[NELEM];
__device__ float         g_V[NELEM];
__device__ __half        g_Vth[NELEM], g_Vtl[NELEM];   /* V^T split fp16 */
__device__ __half2       g_sc16[(size_t)NBH * 512 * 1024]; /* row-pair scores */
__device__ __half        g_a16[(size_t)NBH * S_ * S_];     /* attn fp16 */
__device__ __nv_bfloat16 g_ch[NELEM],  g_cl[NELEM];
__device__ __half2 g_freq[(size_t)NBH * S_ * KP];
__device__ float2 g_tw[1024];

/* ======================= small helpers ==================================== */
__device__ __forceinline__ uint32_t smem_u32(const void* p) {
    uint32_t a;
    asm("{ .reg .u64 t; cvta.to.shared.u64 t, %1; cvt.u32.u64 %0, t; }"
        : "=r"(a) : "l"(p));
    return a;
}
#define CP16(dst, src) \
    asm volatile("cp.async.cg.shared.global [%0], [%1], 16;" \
                 :: "r"(dst), "l"(src))
#define CP_COMMIT() asm volatile("cp.async.commit_group;" ::: "memory")
#define CP_WAIT1()  asm volatile("cp.async.wait_group 1;" ::: "memory")
#define CP_WAIT0()  asm volatile("cp.async.wait_group 0;" ::: "memory")

__device__ __forceinline__ void mma_bf16(float* d, const uint32_t* a, const uint32_t* b)
{
    asm volatile(
        "mma.sync.aligned.m16n8k16.row.col.f32.bf16.bf16.f32 "
        "{%0,%1,%2,%3}, {%4,%5,%6,%7}, {%8,%9}, {%0,%1,%2,%3};"
        : "+f"(d[0]), "+f"(d[1]), "+f"(d[2]), "+f"(d[3])
        : "r"(a[0]), "r"(a[1]), "r"(a[2]), "r"(a[3]), "r"(b[0]), "r"(b[1]));
}
__device__ __forceinline__ void mma_f16(float* d, const uint32_t* a, const uint32_t* b)
{
    asm volatile(
        "mma.sync.aligned.m16n8k16.row.col.f32.f16.f16.f32 "
        "{%0,%1,%2,%3}, {%4,%5,%6,%7}, {%8,%9}, {%0,%1,%2,%3};"
        : "+f"(d[0]), "+f"(d[1]), "+f"(d[2]), "+f"(d[3])
        : "r"(a[0]), "r"(a[1]), "r"(a[2]), "r"(a[3]), "r"(b[0]), "r"(b[1]));
}

__device__ __forceinline__ int swzt(int row, int ch) {
    return (row << 6) + ((ch ^ ((row >> 1) & 3)) << 4);
}

__device__ __forceinline__ void splitw(float v, __nv_bfloat16& h, __nv_bfloat16& l) {
    h = __float2bfloat16(v);
    l = __float2bfloat16(v - __bfloat162float(h));
}
__device__ __forceinline__ void splitwh(float v, __half& h, __half& l) {
    h = __float2half(v);
    l = __float2half(v - __half2float(h));
}

__device__ __forceinline__ float2 cmul(float2 a, float2 b) {
    return make_float2(a.x * b.x - a.y * b.y, a.x * b.y + a.y * b.x);
}
__device__ __forceinline__ float2 cmulc(float2 a, float2 b) {
    return make_float2(a.x * b.x + a.y * b.y, a.y * b.x - a.x * b.y);
}

/* ============ split convert: fp32 -> bf16 hi + bf16 lo (vectorized) ======= */
__global__ void split_convert(const float* __restrict__ src,
                              __nv_bfloat16* __restrict__ h,
                              __nv_bfloat16* __restrict__ l, int n4)
{
    int i = blockIdx.x * blockDim.x + threadIdx.x;
    if (i >= n4) return;
    float4 v = ((const float4*)src)[i];
    __nv_bfloat16 h0, h1, h2, h3, l0, l1, l2, l3;
    splitw(v.x, h0, l0); splitw(v.y, h1, l1);
    splitw(v.z, h2, l2); splitw(v.w, h3, l3);
    uint2 hv, lv;
    hv.x = (uint32_t)__bfloat16_as_ushort(h0) | ((uint32_t)__bfloat16_as_ushort(h1) << 16);
    hv.y = (uint32_t)__bfloat16_as_ushort(h2) | ((uint32_t)__bfloat16_as_ushort(h3) << 16);
    lv.x = (uint32_t)__bfloat16_as_ushort(l0) | ((uint32_t)__bfloat16_as_ushort(l1) << 16);
    lv.y = (uint32_t)__bfloat16_as_ushort(l2) | ((uint32_t)__bfloat16_as_ushort(l3) << 16);
    ((uint2*)h)[i] = hv;
    ((uint2*)l)[i] = lv;
}

/* == tensor-core GEMM, 3-stage cp.async pipeline =========================== */
/* KIND 0: bf16 split x split (3 mma). KIND 1: fp16 single x split (2 mma).   */
/* EPI 0: fp32+bias; 2: split-bf16+bias; 3: split-bf16; 4: half2 pair scores. */
template<int MODE, int EPI, int KIND, int BN, int WROWS, int WCOLS, int KTOT>
__global__ void __launch_bounds__(256, 2) mma_gemm(
    const __nv_bfloat16* __restrict__ Ahg, const __nv_bfloat16* __restrict__ Alg,
    const __nv_bfloat16* __restrict__ Bhg, const __nv_bfloat16* __restrict__ Blg,
    const float* __restrict__ bias, void* __restrict__ Cp, void* __restrict__ C2p,
    float oscale)
{
    constexpr int BM = 128;
    constexpr int ATB = BM * 64;
    constexpr int BTB = BN * 64;
    constexpr int ABYTES = (KIND ? 1 : 2) * ATB;
    constexpr int BUFS = ABYTES + 2 * BTB;
    constexpr int WTM = BM / WROWS, WTN = BN / WCOLS;
    constexpr int FM = WTM / 16, FN = WTN / 8;
    constexpr int NIT = KTOT / 32;

    extern __shared__ char sm[];
    uint32_t smb = smem_u32(sm);

    int tid = threadIdx.x;
    int lane = tid & 31, wid = tid >> 5;
    int wrow = wid / WCOLS, wcol = wid % WCOLS;
    int m0 = wrow * WTM, n0 = wcol * WTN;
    int gid = lane >> 2, tig = lane & 3;

    size_t offA = 0, offB = 0, offC = 0, offP = 0;
    if (MODE == 1) {
        int z = blockIdx.z;
        size_t ho = (size_t)(z >> 4) * S_ * E_ + (size_t)(z & 15) * HD_;
        offA = ho; offB = ho;
        offP = (size_t)z * 512 * 1024;
    } else if (MODE == 2) {
        int z = blockIdx.z;
        offA = (size_t)z * S_ * S_;
        offB = (size_t)z * HD_ * S_;
        offC = (size_t)(z >> 4) * S_ * E_ + (size_t)(z & 15) * HD_;
    }
    /* all operand rows are 2048 bytes (1024 x 2B elements) */
    const char* A8h = (const char*)Ahg + (offA + (size_t)blockIdx.y * BM * 1024) * 2;
    const char* A8l = (const char*)Alg + (offA + (size_t)blockIdx.y * BM * 1024) * 2;
    const char* B8h = (const char*)Bhg + (offB + (size_t)blockIdx.x * BN * 1024) * 2;
    const char* B8l = (const char*)Blg + (offB + (size_t)blockIdx.x * BN * 1024) * 2;

    auto fill = [&](int bf, int k0) {
        size_t kb = (size_t)k0 * 2;
        uint32_t base = smb + bf * BUFS;
#pragma unroll
        for (int i = tid; i < BM * 4; i += 256) {
            int r = i >> 2, ch = i & 3;
            size_t so = (size_t)r * 2048 + kb + ch * 16;
            CP16(base + swzt(r, ch), A8h + so);
            if (KIND == 0) CP16(base + ATB + swzt(r, ch), A8l + so);
        }
#pragma unroll
        for (int i = tid; i < BN * 4; i += 256) {
            int r = i >> 2, ch = i & 3;
            size_t so = (size_t)r * 2048 + kb + ch * 16;
            CP16(base + ABYTES + swzt(r, ch), B8h + so);
            CP16(base + ABYTES + BTB + swzt(r, ch), B8l + so);
        }
    };

    float acc[FM][FN][4];
#pragma unroll
    for (int i = 0; i < FM; i++)
#pragma unroll
        for (int j = 0; j < FN; j++)
#pragma unroll
            for (int u = 0; u < 4; u++) acc[i][j][u] = 0.f;

    fill(0, 0);
    CP_COMMIT();
    if (NIT > 1) fill(1, 32);
    CP_COMMIT();

    for (int it = 0; it < NIT; ++it) {
        if (it + 1 < NIT) { CP_WAIT1(); } else { CP_WAIT0(); }
        __syncthreads();
        int buf = it % 3;
        const char* pAh = sm + buf * BUFS;
        const char* pAl = pAh + ATB;
        const char* pBh = pAh + ABYTES;
        const char* pBl = pBh + BTB;
#pragma unroll
        for (int ks = 0; ks < 2; ks++) {
            uint32_t bhf[FN][2], blf[FN][2];
#pragma unroll
            for (int fn = 0; fn < FN; fn++) {
                int br = n0 + fn * 8 + gid;
                int o0 = swzt(br, ks * 2) + tig * 4;
                int o1 = swzt(br, ks * 2 + 1) + tig * 4;
                bhf[fn][0] = *(const uint32_t*)(pBh + o0);
                bhf[fn][1] = *(const uint32_t*)(pBh + o1);
                blf[fn][0] = *(const uint32_t*)(pBl + o0);
                blf[fn][1] = *(const uint32_t*)(pBl + o1);
            }
#pragma unroll
            for (int fm = 0; fm < FM; fm++) {
                int ar0 = m0 + fm * 16 + gid, ar8 = ar0 + 8;
                int o00 = swzt(ar0, ks * 2) + tig * 4;
                int o80 = swzt(ar8, ks * 2) + tig * 4;
                int o01 = swzt(ar0, ks * 2 + 1) + tig * 4;
                int o81 = swzt(ar8, ks * 2 + 1) + tig * 4;
                uint32_t ahf[4];
                ahf[0] = *(const uint32_t*)(pAh + o00);
                ahf[1] = *(const uint32_t*)(pAh + o80);
                ahf[2] = *(const uint32_t*)(pAh + o01);
                ahf[3] = *(const uint32_t*)(pAh + o81);
                if (KIND == 0) {
                    uint32_t alf[4];
                    alf[0] = *(const uint32_t*)(pAl + o00);
                    alf[1] = *(const uint32_t*)(pAl + o80);
                    alf[2] = *(const uint32_t*)(pAl + o01);
                    alf[3] = *(const uint32_t*)(pAl + o81);
#pragma unroll
                    for (int fn = 0; fn < FN; fn++) {
                        mma_bf16(acc[fm][fn], ahf, bhf[fn]);
                        mma_bf16(acc[fm][fn], ahf, blf[fn]);
                        mma_bf16(acc[fm][fn], alf, bhf[fn]);
                    }
                } else {
#pragma unroll
                    for (int fn = 0; fn < FN; fn++) {
                        mma_f16(acc[fm][fn], ahf, bhf[fn]);
                        mma_f16(acc[fm][fn], ahf, blf[fn]);
                    }
                }
            }
        }
        if (it + 2 < NIT) {
            fill((it + 2) % 3, (it + 2) * 32);
            CP_COMMIT();
        }
    }

#pragma unroll
    for (int fm = 0; fm < FM; fm++) {
        size_t r0 = (size_t)blockIdx.y * BM + m0 + fm * 16 + gid;
#pragma unroll
        for (int fn = 0; fn < FN; fn++) {
            int cgl = blockIdx.x * BN + n0 + fn * 8 + tig * 2;
            float v00 = acc[fm][fn][0] * oscale;
            float v01 = acc[fm][fn][1] * oscale;
            float v10 = acc[fm][fn][2] * oscale;
            float v11 = acc[fm][fn][3] * oscale;
            if (EPI == 4) {
                /* row-pair packed fp16 scores: lane^4 holds the odd row */
                float q00 = __shfl_xor_sync(0xffffffffu, v00, 4);
                float q01 = __shfl_xor_sync(0xffffffffu, v01, 4);
                float q10 = __shfl_xor_sync(0xffffffffu, v10, 4);
                float q11 = __shfl_xor_sync(0xffffffffu, v11, 4);
                if (!(gid & 1)) {
                    __half2* SC = (__half2*)Cp;
                    __half2 a0 = __floats2half2_rn(v00, q00);
                    __half2 a1 = __floats2half2_rn(v01, q01);
                    __half2 b0 = __floats2half2_rn(v10, q10);
                    __half2 b1 = __floats2half2_rn(v11, q11);
                    uint2 pk0 = make_uint2(*(uint32_t*)&a0, *(uint32_t*)&a1);
                    uint2 pk1 = make_uint2(*(uint32_t*)&b0, *(uint32_t*)&b1);
                    *(uint2*)&SC[offP + (r0 >> 1) * 1024 + cgl] = pk0;
                    *(uint2*)&SC[offP + ((r0 + 8) >> 1) * 1024 + cgl] = pk1;
                }
            } else if (EPI == 0) {
                float b0 = bias[cgl], b1 = bias[cgl + 1];
                float* C = (float*)Cp;
                *(float2*)&C[offC + r0 * 1024 + cgl] = make_float2(v00 + b0, v01 + b1);
                *(float2*)&C[offC + (r0 + 8) * 1024 + cgl] = make_float2(v10 + b0, v11 + b1);
            } else {
                float b0 = 0.f, b1 = 0.f;
                if (EPI == 2) { b0 = bias[cgl]; b1 = bias[cgl + 1]; }
                v00 += b0; v01 += b1; v10 += b0; v11 += b1;
                __nv_bfloat16* Ch = (__nv_bfloat16*)Cp;
                __nv_bfloat16* Cl = (__nv_bfloat16*)C2p;
                __nv_bfloat16 h00, h01, h10, h11, l00, l01, l10, l11;
                splitw(v00, h00, l00); splitw(v01, h01, l01);
                splitw(v10, h10, l10); splitw(v11, h11, l11);
                uint32_t hv0 = (uint32_t)__bfloat16_as_ushort(h00) | ((uint32_t)__bfloat16_as_ushort(h01) << 16);
                uint32_t lv0 = (uint32_t)__bfloat16_as_ushort(l00) | ((uint32_t)__bfloat16_as_ushort(l01) << 16);
                uint32_t hv1 = (uint32_t)__bfloat16_as_ushort(h10) | ((uint32_t)__bfloat16_as_ushort(h11) << 16);
                uint32_t lv1 = (uint32_t)__bfloat16_as_ushort(l10) | ((uint32_t)__bfloat16_as_ushort(l11) << 16);
                *(uint32_t*)&Ch[offC + r0 * 1024 + cgl] = hv0;
                *(uint32_t*)&Cl[offC + r0 * 1024 + cgl] = lv0;
                *(uint32_t*)&Ch[offC + (r0 + 8) * 1024 + cgl] = hv1;
                *(uint32_t*)&Cl[offC + (r0 + 8) * 1024 + cgl] = lv1;
            }
        }
    }
}

/* ===== Vt[z][d][k] = V[b][k][h*64+d], written split-fp16 ================== */
__global__ void transpose_v(const float* __restrict__ V,
                            __half* __restrict__ Vth, __half* __restrict__ Vtl)
{
    __shared__ float tile[32][33];
    int z = blockIdx.z;
    int b = z >> 4, h = z & 15;
    int k0 = blockIdx.x * 32, d0 = blockIdx.y * 32;
    int tx = threadIdx.x, ty = threadIdx.y;
#pragma unroll
    for (int i = 0; i < 4; i++)
        tile[ty + i * 8][tx] =
            V[((size_t)b * S_ + k0 + ty + i * 8) * E_ + h * HD_ + d0 + tx];
    __syncthreads();
#pragma unroll
    for (int i = 0; i < 4; i++) {
        float v = tile[tx][ty + i * 8];
        __half hh, ll;
        splitwh(v, hh, ll);
        size_t o = ((size_t)z * HD_ + d0 + ty + i * 8) * S_ + k0 + tx;
        Vth[o] = hh;
        Vtl[o] = ll;
    }
}

/* ===================== twiddle init ======================================= */
__global__ void init_twiddles(float2* tw)
{
    int j = blockIdx.x * blockDim.x + threadIdx.x;
    if (j < 1024) {
        float ang = -6.28318530717958647692f * (float)j / 1024.0f;
        tw[j] = make_float2(cosf(ang), sinf(ang));
    }
}

/* ============== in-register 32-pt FFT (DIF, natural order out) ============ */
template<bool INV>
__device__ __forceinline__ void fft32r(float2* v)
{
    const float C[16] = {
        1.f, 0.980785280403230f, 0.923879532511287f, 0.831469612302545f,
        0.707106781186548f, 0.555570233019602f, 0.382683432365090f, 0.195090322016128f,
        0.f, -0.195090322016128f, -0.382683432365090f, -0.555570233019602f,
        -0.707106781186548f, -0.831469612302545f, -0.923879532511287f, -0.980785280403230f };
    const float Sn[16] = {
        0.f, 0.195090322016128f, 0.382683432365090f, 0.555570233019602f,
        0.707106781186548f, 0.831469612302545f, 0.923879532511287f, 0.980785280403230f,
        1.f, 0.980785280403230f, 0.923879532511287f, 0.831469612302545f,
        0.707106781186548f, 0.555570233019602f, 0.382683432365090f, 0.195090322016128f };
#pragma unroll
    for (int h = 16; h >= 1; h >>= 1) {
#pragma unroll
        for (int b = 0; b < 32; b += 2 * h) {
#pragma unroll
            for (int j = 0; j < h; j++) {
                int e = j * (16 / h);
                float tc = C[e];
                float ts = INV ? Sn[e] : -Sn[e];
                float2 a = v[b + j], bb = v[b + j + h];
                v[b + j] = make_float2(a.x + bb.x, a.y + bb.y);
                float dx = a.x - bb.x, dy = a.y - bb.y;
                v[b + j + h] = make_float2(dx * tc - dy * ts, dx * ts + dy * tc);
            }
        }
    }
#pragma unroll
    for (int i = 0; i < 32; i++) {
        int r = ((i & 1) << 4) | ((i & 2) << 2) | (i & 4) | ((i & 8) >> 2) | ((i & 16) >> 4);
        if (r > i) { float2 tmp = v[i]; v[i] = v[r]; v[r] = tmp; }
    }
}

/* ====== pass 1: warp fwd FFT of packed fp16 row pairs -> half spectra ===== */
__global__ void __launch_bounds__(128) fft_rows_fwd_w(
    const __half2* __restrict__ sc, __half2* __restrict__ Y,
    const float2* __restrict__ twg)
{
    __shared__ __align__(16) float pat[4 * 2112];
    int t = threadIdx.x & 31, w = threadIdx.x >> 5;
    float* pre = pat + w * 2112;
    float* pim = pre + 1056;
    size_t p = (size_t)blockIdx.x * 4 + w;
    const __half2* r01 = sc + p * 1024;

    float2 v[32];
#pragma unroll
    for (int i2 = 0; i2 < 32; i2++)
        v[i2] = __half22float2(r01[t + 32 * i2]);
    fft32r<false>(v);
#pragma unroll
    for (int k2 = 1; k2 < 32; k2++)
        v[k2] = cmul(v[k2], twg[(t * k2) & 1023]);
#pragma unroll
    for (int k2 = 0; k2 < 32; k2++) {
        pre[t * 33 + k2] = v[k2].x;
        pim[t * 33 + k2] = v[k2].y;
    }
    __syncwarp();
#pragma unroll
    for (int i1 = 0; i1 < 32; i1++)
        v[i1] = make_float2(pre[i1 * 33 + t], pim[i1 * 33 + t]);
    __syncwarp();
    fft32r<false>(v);
#pragma unroll
    for (int k1 = 0; k1 < 32; k1++) {
        pre[k1 * 33 + t] = v[k1].x;
        pim[k1 * 33 + t] = v[k1].y;
    }
    __syncwarp();

    __half2* y0 = Y + (size_t)(2 * p) * KP;
    __half2* y1 = y0 + KP;
#pragma unroll
    for (int u = 0; u <= 16; u++) {
        int k = t + 32 * u;
        if (u < 16 || t == 0) {
            int idx = u * 33 + t;
            float2 Xk = make_float2(pre[idx], pim[idx]);
            int m = (1024 - k) & 1023;
            int midx = (m >> 5) * 33 + (m & 31);
            float2 Xm = make_float2(pre[midx], pim[midx]);
            y0[k] = __floats2half2_rn(0.5f * (Xk.x + Xm.x), 0.5f * (Xk.y - Xm.y));
            y1[k] = __floats2half2_rn(0.5f * (Xk.y + Xm.y), 0.5f * (Xm.x - Xk.x));
        }
    }
}

/* ===== pass 2: warp-level col FFT + real cos-filter + col IFFT =========== */
__global__ void __launch_bounds__(128) fft_cols_w(
    __half2* __restrict__ Y, const float* __restrict__ alpha_p,
    const float2* __restrict__ twg)
{
    __shared__ __align__(16) float sm[10240];   /* slab 2x5120 / patches 4x2112 */
    float* slab_re = sm;
    float* slab_im = sm + 5120;
    int tid = threadIdx.x;
    int t = tid & 31, w = tid >> 5;
    int z = blockIdx.y;
    int kbase = blockIdx.x * 4;
    __half2* base = Y + (size_t)z * S_ * KP + kbase;

#pragma unroll 8
    for (int idx = tid; idx < 4096; idx += 128) {
        int q = idx >> 2, c = idx & 3;
        float2 val = __half22float2(base[(size_t)q * KP + c]);
        slab_re[q * 5 + c] = val.x;
        slab_im[q * 5 + c] = val.y;
    }
    __syncthreads();

    float2 v[32];
#pragma unroll
    for (int i2 = 0; i2 < 32; i2++) {
        int q = t + 32 * i2;
        v[i2] = make_float2(slab_re[q * 5 + w], slab_im[q * 5 + w]);
    }
    __syncthreads();
    float* pre = sm + w * 2112;
    float* pim = pre + 1056;

    fft32r<false>(v);
#pragma unroll
    for (int k2 = 1; k2 < 32; k2++)
        v[k2] = cmul(v[k2], twg[(t * k2) & 1023]);
#pragma unroll
    for (int k2 = 0; k2 < 32; k2++) {
        pre[t * 33 + k2] = v[k2].x;
        pim[t * 33 + k2] = v[k2].y;
    }
    __syncwarp();
#pragma unroll
    for (int i1 = 0; i1 < 32; i1++)
        v[i1] = make_float2(pre[i1 * 33 + t], pim[i1 * 33 + t]);
    __syncwarp();
    fft32r<false>(v);

    float alpha = *alpha_p;
#pragma unroll
    for (int k1 = 0; k1 < 32; k1++) {
        float mag = sqrtf(v[k1].x * v[k1].x + v[k1].y * v[k1].y);
        float g = __cosf(alpha * atanf(__logf(mag + 1e-10f)));
        v[k1].x *= g; v[k1].y *= g;
    }

    fft32r<true>(v);
#pragma unroll
    for (int i1 = 1; i1 < 32; i1++)
        v[i1] = cmulc(v[i1], twg[(t * i1) & 1023]);
#pragma unroll
    for (int i1 = 0; i1 < 32; i1++) {
        pre[t * 33 + i1] = v[i1].x;
        pim[t * 33 + i1] = v[i1].y;
    }
    __syncwarp();
#pragma unroll
    for (int k2 = 0; k2 < 32; k2++)
        v[k2] = make_float2(pre[k2 * 33 + t], pim[k2 * 33 + t]);
    __syncwarp();
    fft32r<true>(v);

    __syncthreads();
    const float scl = 1.0f / 1024.0f;
#pragma unroll
    for (int i2 = 0; i2 < 32; i2++) {
        int q = t + 32 * i2;
        slab_re[q * 5 + w] = v[i2].x * scl;
        slab_im[q * 5 + w] = v[i2].y * scl;
    }
    __syncthreads();
#pragma unroll 8
    for (int idx = tid; idx < 4096; idx += 128) {
        int q = idx >> 2, c = idx & 3;
        if (kbase + c < 513)
            base[(size_t)q * KP + c] =
                __floats2half2_rn(slab_re[q * 5 + c], slab_im[q * 5 + c]);
    }
}

/* == pass 3: warp c2r inverse + warp softmax, attn fp16 vectorized out ===== */
__global__ void __launch_bounds__(128) fft_rows_inv_softmax_w(
    const __half2* __restrict__ Y, __half* __restrict__ out16,
    const float2* __restrict__ twg)
{
    __shared__ __align__(16) float pat[4 * 2112];
    int t = threadIdx.x & 31, w = threadIdx.x >> 5;
    float* pre = pat + w * 2112;
    float* pim = pre + 1056;
    size_t p = (size_t)blockIdx.x * 4 + w;
    const __half2* y0 = Y + (size_t)(2 * p) * KP;
    const __half2* y1 = y0 + KP;

#pragma unroll
    for (int u = 0; u <= 16; u++) {
        int k = t + 32 * u;
        if (u < 16 || t == 0) {
            float2 h0 = __half22float2(y0[k]);
            float2 h1 = __half22float2(y1[k]);
            int idx = u * 33 + t;
            pre[idx] = h0.x - h1.y;
            pim[idx] = h0.y + h1.x;
            if (k >= 1 && k < 512) {
                int m = 1024 - k;
                int midx = (m >> 5) * 33 + (m & 31);
                pre[midx] = h0.x + h1.y;
                pim[midx] = h1.x - h0.y;
            }
        }
    }
    __syncwarp();
    float2 v[32];
#pragma unroll
    for (int k1 = 0; k1 < 32; k1++)
        v[k1] = make_float2(pre[k1 * 33 + t], pim[k1 * 33 + t]);
    __syncwarp();
    fft32r<true>(v);
#pragma unroll
    for (int i1 = 1; i1 < 32; i1++)
        v[i1] = cmulc(v[i1], twg[(t * i1) & 1023]);
#pragma unroll
    for (int i1 = 0; i1 < 32; i1++) {
        pre[t * 33 + i1] = v[i1].x;
        pim[t * 33 + i1] = v[i1].y;
    }
    __syncwarp();
#pragma unroll
    for (int k2 = 0; k2 < 32; k2++)
        v[k2] = make_float2(pre[k2 * 33 + t], pim[k2 * 33 + t]);
    __syncwarp();
    fft32r<true>(v);

    const float scl = 1.0f / 1024.0f;
    float m0 = -1e30f, m1 = -1e30f;
#pragma unroll
    for (int i2 = 0; i2 < 32; i2++) {
        v[i2].x *= scl; v[i2].y *= scl;
        m0 = fmaxf(m0, v[i2].x); m1 = fmaxf(m1, v[i2].y);
    }
#pragma unroll
    for (int o = 16; o; o >>= 1) {
        m0 = fmaxf(m0, __shfl_xor_sync(0xffffffffu, m0, o));
        m1 = fmaxf(m1, __shfl_xor_sync(0xffffffffu, m1, o));
    }
    float s0 = 0.f, s1 = 0.f;
    float p0[32], p1[32];
#pragma unroll
    for (int i2 = 0; i2 < 32; i2++) {
        p0[i2] = __expf(v[i2].x - m0);
        p1[i2] = __expf(v[i2].y - m1);
        s0 += p0[i2]; s1 += p1[i2];
    }
#pragma unroll
    for (int o = 16; o; o >>= 1) {
        s0 += __shfl_xor_sync(0xffffffffu, s0, o);
        s1 += __shfl_xor_sync(0xffffffffu, s1, o);
    }
    float inv0 = 1.0f / s0, inv1 = 1.0f / s1;
    __syncwarp();                        /* patch reads done; reuse as fp16 stage */
    __half* hb = (__half*)pre;           /* 2 rows x 1024 half = 4KB (fits 8448B) */
#pragma unroll
    for (int i2 = 0; i2 < 32; i2++) {
        int col = t + 32 * i2;
        hb[col] = __float2half(p0[i2] * inv0);
        hb[1024 + col] = __float2half(p1[i2] * inv1);
    }
    __syncwarp();
    uint4* dst = (uint4*)(out16 + (size_t)(2 * p) * 1024);
    const uint4* srcv = (const uint4*)hb;
#pragma unroll
    for (int j = t; j < 256; j += 32) dst[j] = srcv[j];
}

/* ============================== launcher =================================== */
extern "C" void kernel_launch(void* const* d_in, const int* in_sizes, int n_in,
                              void* d_out, int out_size)
{
    const float* query = (const float*)d_in[0];
    const float* Wq    = (const float*)d_in[1];
    const float* bq    = (const float*)d_in[2];
    const float* Wk    = (const float*)d_in[3];
    const float* bk    = (const float*)d_in[4];
    const float* Wv    = (const float*)d_in[5];
    const float* bv    = (const float*)d_in[6];
    const float* Wo    = (const float*)d_in[7];
    const float* bo    = (const float*)d_in[8];
    const float* alpha = (const float*)d_in[9];
    float* out = (float*)d_out;

    __nv_bfloat16 *pqh, *pql, *pWqh, *pWql, *pWkh, *pWkl, *pWvh, *pWvl, *pWoh, *pWol;
    __nv_bfloat16 *pQh, *pQl, *pKh, *pKl, *pch, *pcl;
    __half *pVth, *pVtl, *pA16;
    __half2 *pSc16, *pFreq;
    float *pV;
    float2 *pTw;
    cudaGetSymbolAddress((void**)&pqh, g_qh);   cudaGetSymbolAddress((void**)&pql, g_ql);
    cudaGetSymbolAddress((void**)&pWqh, g_Wqh); cudaGetSymbolAddress((void**)&pWql, g_Wql);
    cudaGetSymbolAddress((void**)&pWkh, g_Wkh); cudaGetSymbolAddress((void**)&pWkl, g_Wkl);
    cudaGetSymbolAddress((void**)&pWvh, g_Wvh); cudaGetSymbolAddress((void**)&pWvl, g_Wvl);
    cudaGetSymbolAddress((void**)&pWoh, g_Woh); cudaGetSymbolAddress((void**)&pWol, g_Wol);
    cudaGetSymbolAddress((void**)&pQh, g_Qh);   cudaGetSymbolAddress((void**)&pQl, g_Ql);
    cudaGetSymbolAddress((void**)&pKh, g_Kh);   cudaGetSymbolAddress((void**)&pKl, g_Kl);
    cudaGetSymbolAddress((void**)&pVth, g_Vth); cudaGetSymbolAddress((void**)&pVtl, g_Vtl);
    cudaGetSymbolAddress((void**)&pch, g_ch);   cudaGetSymbolAddress((void**)&pcl, g_cl);
    cudaGetSymbolAddress((void**)&pV, g_V);
    cudaGetSymbolAddress((void**)&pSc16, g_sc16);
    cudaGetSymbolAddress((void**)&pA16, g_a16);
    cudaGetSymbolAddress((void**)&pFreq, g_freq);
    cudaGetSymbolAddress((void**)&pTw, g_tw);

    const int SM_P = 3 * (2 * 8192 + 2 * 8192);   /* 98304 */
    const int SM_A = 3 * (1 * 8192 + 2 * 4096);   /* 49152 */
    cudaFuncSetAttribute((const void*)mma_gemm<0, 2, 0, 128, 2, 4, 1024>,
                         cudaFuncAttributeMaxDynamicSharedMemorySize, SM_P);
    cudaFuncSetAttribute((const void*)mma_gemm<0, 0, 0, 128, 2, 4, 1024>,
                         cudaFuncAttributeMaxDynamicSharedMemorySize, SM_P);
    cudaFuncSetAttribute((const void*)mma_gemm<1, 4, 0, 128, 2, 4, 64>,
                         cudaFuncAttributeMaxDynamicSharedMemorySize, SM_P);
    cudaFuncSetAttribute((const void*)mma_gemm<2, 3, 1, 64, 4, 2, 1024>,
                         cudaFuncAttributeMaxDynamicSharedMemorySize, SM_A);

    init_twiddles<<<4, 256>>>(pTw);

    split_convert<<<(int)(NELEM / 4 / 256), 256>>>(query, pqh, pql, (int)(NELEM / 4));
    split_convert<<<E_ * E_ / 4 / 256, 256>>>(Wq, pWqh, pWql, E_ * E_ / 4);
    split_convert<<<E_ * E_ / 4 / 256, 256>>>(Wk, pWkh, pWkl, E_ * E_ / 4);
    split_convert<<<E_ * E_ / 4 / 256, 256>>>(Wv, pWvh, pWvl, E_ * E_ / 4);
    split_convert<<<E_ * E_ / 4 / 256, 256>>>(Wo, pWoh, pWol, E_ * E_ / 4);

    dim3 gp(E_ / 128, (B_ * S_) / 128, 1);
    mma_gemm<0, 2, 0, 128, 2, 4, 1024><<<gp, 256, SM_P>>>(pqh, pql, pWqh, pWql, bq, pQh, pQl, 1.0f);
    mma_gemm<0, 2, 0, 128, 2, 4, 1024><<<gp, 256, SM_P>>>(pqh, pql, pWkh, pWkl, bk, pKh, pKl, 1.0f);
    mma_gemm<0, 0, 0, 128, 2, 4, 1024><<<gp, 256, SM_P>>>(pqh, pql, pWvh, pWvl, bv, pV, 0, 1.0f);

    transpose_v<<<dim3(32, 2, NBH), dim3(32, 8)>>>(pV, pVth, pVtl);

    dim3 gs(S_ / 128, S_ / 128, NBH);
    mma_gemm<1, 4, 0, 128, 2, 4, 64><<<gs, 256, SM_P>>>(pQh, pQl, pKh, pKl, 0, pSc16, 0, 0.125f);

    fft_rows_fwd_w<<<NBH * S_ / 2 / 4, 128>>>(pSc16, pFreq, pTw);

    fft_cols_w<<<dim3(129, NBH), 128>>>(pFreq, alpha, pTw);

    fft_rows_inv_softmax_w<<<NBH * S_ / 2 / 4, 128>>>(pFreq, pA16, pTw);

    dim3 ga(1, S_ / 128, NBH);
    mma_gemm<2, 3, 1, 64, 4, 2, 1024><<<ga, 256, SM_A>>>(
        (const __nv_bfloat16*)pA16, 0,
        (const __nv_bfloat16*)pVth, (const __nv_bfloat16*)pVtl, 0, pch, pcl, 1.0f);

    mma_gemm<0, 0, 0, 128, 2, 4, 1024><<<gp, 256, SM_P>>>(pch, pcl, pWoh, pWol, bo, out, 0, 1.0f);
}